// round 2
// baseline (speedup 1.0000x reference)
#include <cuda_runtime.h>
#include <math.h>

// Problem constants
#define BB      16
#define NNODE   64
#define FIN     128
#define FHID    256
#define ODIM    768
#define HT      1536   // translate hidden
#define DR      770
#define HR      1540
#define NEDGE   65536  // B*N*N
#define NROW    1024   // B*N

// ---------------- scratch (device globals; no runtime allocation) ----------
__device__ float g_agg[NROW * 256];          // GIN aggregated features [B*N, 2*FIN]
__device__ float g_U[NROW * HT];             // xo @ W1t[2:770]
__device__ float g_V[NROW * HT];             // xo @ W1t[770:1538]
__device__ float g_na[(size_t)NEDGE * ODIM]; // new_adjs pre-symmetrize [e, f]  (201 MB)
__device__ float g_part[NROW * 2 * HT];      // per-(b,i) BN partial sums [bi][sum(1536)|sq(1536)]
__device__ float g_c1[HT], g_c2[HT];         // folded BN scale/shift

__device__ __forceinline__ float elu_f(float x) {
    return x > 0.f ? x : (__expf(x) - 1.f);
}

// ---------------- kernel 1: agg[b,i,c,f] = sum_j A_c[b,i,j] * x[b,j,f] ------
__global__ void k_agg(const float* __restrict__ x, const float* __restrict__ adjs,
                      const float* __restrict__ flags) {
    int bi = blockIdx.x;            // b*64 + i
    int b = bi >> 6, i = bi & 63;
    int f = threadIdx.x;            // 0..127
    __shared__ float a0s[64], a1s[64];
    float fi = flags[b * 64 + i];
    if (threadIdx.x < 64) {
        int j = threadIdx.x;
        float fj = flags[b * 64 + j];
        float a = adjs[(size_t)bi * 64 + j];
        float m = fi * fj;
        a0s[j] = a * m;
        a1s[j] = (1.f - a) * m;
    }
    __syncthreads();
    float s0 = 0.f, s1 = 0.f;
    const float* xb = x + (size_t)b * NNODE * FIN;
    #pragma unroll 4
    for (int j = 0; j < 64; j++) {
        float xv = xb[j * FIN + f];
        s0 += a0s[j] * xv;
        s1 += a1s[j] * xv;
    }
    g_agg[bi * 256 + f] = s0;
    g_agg[bi * 256 + 128 + f] = s1;
}

// ---------------- kernel 2: GIN MLPs -> x_o (written directly to output) ---
__global__ void k_gin(const float* __restrict__ x, const float* __restrict__ flags,
                      const float* __restrict__ Wg, const float* __restrict__ bg,
                      const float* __restrict__ Wout, const float* __restrict__ bout,
                      float* __restrict__ out_xo) {
    __shared__ float aggs[8][256];
    __shared__ float xs[8][128];
    __shared__ float hs[8][256];
    __shared__ float fl[8];
    int r0 = blockIdx.x * 8;        // 128 blocks, 8 rows each
    int t = threadIdx.x;            // 256 threads
    for (int idx = t; idx < 8 * 256; idx += 256)
        aggs[idx >> 8][idx & 255] = g_agg[r0 * 256 + idx];
    for (int idx = t; idx < 8 * 128; idx += 256)
        xs[idx >> 7][idx & 127] = x[(size_t)r0 * 128 + idx];
    if (t < 8) fl[t] = flags[r0 + t];
    __syncthreads();

    // h = elu(agg @ Wg + bg) * flag   (Wg: [256,256])
    {
        float acc[8];
        float bgv = bg[t];
        #pragma unroll
        for (int r = 0; r < 8; r++) acc[r] = bgv;
        for (int k = 0; k < 256; k++) {
            float w = Wg[k * 256 + t];
            #pragma unroll
            for (int r = 0; r < 8; r++) acc[r] += aggs[r][k] * w;
        }
        #pragma unroll
        for (int r = 0; r < 8; r++) hs[r][t] = elu_f(acc[r]) * fl[r];
    }
    __syncthreads();

    // xo = tanh([x,h] @ Wout + bout) * flag   (Wout: [384,768])
    float acc[3][8];
    #pragma unroll
    for (int c = 0; c < 3; c++) {
        float bo = bout[t + c * 256];
        #pragma unroll
        for (int r = 0; r < 8; r++) acc[c][r] = bo;
    }
    for (int k = 0; k < 128; k++) {
        float o[8];
        #pragma unroll
        for (int r = 0; r < 8; r++) o[r] = xs[r][k];
        #pragma unroll
        for (int c = 0; c < 3; c++) {
            float w = Wout[k * 768 + t + c * 256];
            #pragma unroll
            for (int r = 0; r < 8; r++) acc[c][r] += o[r] * w;
        }
    }
    for (int k = 0; k < 256; k++) {
        float o[8];
        #pragma unroll
        for (int r = 0; r < 8; r++) o[r] = hs[r][k];
        #pragma unroll
        for (int c = 0; c < 3; c++) {
            float w = Wout[(128 + k) * 768 + t + c * 256];
            #pragma unroll
            for (int r = 0; r < 8; r++) acc[c][r] += o[r] * w;
        }
    }
    #pragma unroll
    for (int c = 0; c < 3; c++)
        #pragma unroll
        for (int r = 0; r < 8; r++)
            out_xo[(size_t)(r0 + r) * 768 + t + c * 256] = tanhf(acc[c][r]) * fl[r];
}

// ---------------- kernel 3: U,V = xo @ W1t[2:770], xo @ W1t[770:1538] -------
__global__ void k_uv(const float* __restrict__ xo, const float* __restrict__ W1t) {
    __shared__ float As[8][128];
    __shared__ float Bs[8][128];
    int t = threadIdx.x;
    int m0 = blockIdx.y * 128;                // rows of xo
    int ng0 = blockIdx.x * 128;               // 0..3071 combined U|V column
    const int isU = (ng0 < HT);
    const float* Bbase = W1t + (size_t)(isU ? 2 : 770) * HT + (isU ? ng0 : ng0 - HT);
    int m = t >> 1, h4 = (t & 1) * 4;
    const float* pA = xo + (size_t)(m0 + m) * 768 + h4;
    int kkB = t >> 5, c4 = (t & 31) * 4;
    int m_base = (t >> 4) * 8, n_base = (t & 15) * 8;

    float acc[8][8];
    #pragma unroll
    for (int a = 0; a < 8; a++)
        #pragma unroll
        for (int bq = 0; bq < 8; bq++) acc[a][bq] = 0.f;

    for (int k0 = 0; k0 < 768; k0 += 8) {
        float4 av = *(const float4*)(pA + k0);
        float4 bv = *(const float4*)(Bbase + (size_t)(k0 + kkB) * HT + c4);
        __syncthreads();
        As[h4 + 0][m] = av.x; As[h4 + 1][m] = av.y;
        As[h4 + 2][m] = av.z; As[h4 + 3][m] = av.w;
        *(float4*)&Bs[kkB][c4] = bv;
        __syncthreads();
        #pragma unroll
        for (int kk = 0; kk < 8; kk++) {
            float a[8], bb[8];
            *(float4*)(a)     = *(const float4*)&As[kk][m_base];
            *(float4*)(a + 4) = *(const float4*)&As[kk][m_base + 4];
            *(float4*)(bb)     = *(const float4*)&Bs[kk][n_base];
            *(float4*)(bb + 4) = *(const float4*)&Bs[kk][n_base + 4];
            #pragma unroll
            for (int mi = 0; mi < 8; mi++)
                #pragma unroll
                for (int ni = 0; ni < 8; ni++)
                    acc[mi][ni] += a[mi] * bb[ni];
        }
    }
    float* Obase = isU ? g_U : g_V;
    int c0 = isU ? ng0 : ng0 - HT;
    #pragma unroll
    for (int mi = 0; mi < 8; mi++) {
        float* prow = Obase + (size_t)(m0 + m_base + mi) * HT + c0 + n_base;
        *(float4*)(prow)     = make_float4(acc[mi][0], acc[mi][1], acc[mi][2], acc[mi][3]);
        *(float4*)(prow + 4) = make_float4(acc[mi][4], acc[mi][5], acc[mi][6], acc[mi][7]);
    }
}

// ---------------- kernel 4: BN stats partials over edges (per (b,i)) -------
__global__ void k_stats(const float* __restrict__ adjs, const float* __restrict__ flags,
                        const float* __restrict__ W1t) {
    int bi = blockIdx.x;
    int b = bi >> 6, i = bi & 63;
    int t = threadIdx.x;  // 256
    __shared__ float Ur[HT];
    __shared__ float a0s[64], a1s[64];
    for (int k = t; k < HT; k += 256) Ur[k] = g_U[(size_t)bi * HT + k];
    if (t < 64) {
        int j = t;
        float m = flags[b * 64 + i] * flags[b * 64 + j];
        float a = adjs[(size_t)bi * 64 + j];
        a0s[j] = a * m;
        a1s[j] = (1.f - a) * m;
    }
    __syncthreads();
    float w0[6], w1[6], u[6], sum[6], sq[6];
    #pragma unroll
    for (int s = 0; s < 6; s++) {
        int k = t + s * 256;
        w0[s] = W1t[k];           // row 0 (a0 channel)
        w1[s] = W1t[HT + k];      // row 1 (a1 channel)
        u[s] = Ur[k];
        sum[s] = 0.f; sq[s] = 0.f;
    }
    const float* Vb = g_V + (size_t)(b * 64) * HT;
    for (int j = 0; j < 64; j++) {
        float a0 = a0s[j], a1 = a1s[j];
        const float* Vr = Vb + (size_t)j * HT;
        #pragma unroll
        for (int s = 0; s < 6; s++) {
            float z = u[s] + Vr[t + s * 256] + a0 * w0[s] + a1 * w1[s];
            sum[s] += z;
            sq[s] += z * z;
        }
    }
    #pragma unroll
    for (int s = 0; s < 6; s++) {
        g_part[(size_t)bi * 3072 + t + s * 256] = sum[s];
        g_part[(size_t)bi * 3072 + HT + t + s * 256] = sq[s];
    }
}

// ---------------- kernel 5: finalize BN constants ---------------------------
__global__ void k_stats2(const float* __restrict__ b1t, const float* __restrict__ gamma,
                         const float* __restrict__ beta) {
    int k = blockIdx.x * 256 + threadIdx.x;  // 6 blocks -> 1536
    float s = 0.f, q = 0.f;
    for (int bi = 0; bi < NROW; bi++) {
        s += g_part[(size_t)bi * 3072 + k];
        q += g_part[(size_t)bi * 3072 + HT + k];
    }
    const float inv = 1.f / 65536.f;
    float mu_z = s * inv;
    float var = fmaxf(q * inv - mu_z * mu_z, 0.f);
    float mu = mu_z + b1t[k];                 // bias shifts mean, not variance
    float c1 = gamma[k] * rsqrtf(var + 1e-5f);
    g_c1[k] = c1;
    g_c2[k] = beta[k] - mu * c1;
}

// ---------------- kernel 6: fused translate_mlp GEMM2 ----------------------
// new_adjs[e, f] = elu(BN(h1[e,:])) @ W2t + b2t, h1 generated on the fly
__global__ void k_gemm2(const float* __restrict__ adjs, const float* __restrict__ flags,
                        const float* __restrict__ W1t, const float* __restrict__ W2t,
                        const float* __restrict__ b2t) {
    __shared__ float As[8][128];
    __shared__ float Bs[8][128];
    __shared__ float a0s[128], a1s[128];
    int t = threadIdx.x;
    int m0 = blockIdx.y * 128;   // edge tile
    int n0 = blockIdx.x * 128;   // output feature tile (768/128 = 6)
    int b = m0 >> 12;
    if (t < 128) {
        int e = m0 + t;
        int i = (e >> 6) & 63, j = e & 63;
        float mk = flags[b * 64 + i] * flags[b * 64 + j];
        float a = adjs[(size_t)b * 4096 + i * 64 + j];
        a0s[t] = a * mk;
        a1s[t] = (1.f - a) * mk;
    }
    __syncthreads();
    int m = t >> 1, h4 = (t & 1) * 4;
    int e = m0 + m;
    int im = (e >> 6) & 63, jm = e & 63;
    const float* pU = g_U + (size_t)(b * 64 + im) * HT + h4;
    const float* pV = g_V + (size_t)(b * 64 + jm) * HT + h4;
    float a0 = a0s[m], a1 = a1s[m];
    int kkB = t >> 5, c4 = (t & 31) * 4;
    int m_base = (t >> 4) * 8, n_base = (t & 15) * 8;

    float acc[8][8];
    #pragma unroll
    for (int a = 0; a < 8; a++)
        #pragma unroll
        for (int bq = 0; bq < 8; bq++) acc[a][bq] = 0.f;

    for (int k0 = 0; k0 < HT; k0 += 8) {
        float4 u = *(const float4*)(pU + k0);
        float4 v = *(const float4*)(pV + k0);
        float4 w0 = *(const float4*)(W1t + k0 + h4);
        float4 w1 = *(const float4*)(W1t + HT + k0 + h4);
        float4 c1 = *(const float4*)(g_c1 + k0 + h4);
        float4 c2 = *(const float4*)(g_c2 + k0 + h4);
        float4 bv = *(const float4*)(W2t + (size_t)(k0 + kkB) * 768 + n0 + c4);
        __syncthreads();
        As[h4 + 0][m] = elu_f((u.x + v.x + a0 * w0.x + a1 * w1.x) * c1.x + c2.x);
        As[h4 + 1][m] = elu_f((u.y + v.y + a0 * w0.y + a1 * w1.y) * c1.y + c2.y);
        As[h4 + 2][m] = elu_f((u.z + v.z + a0 * w0.z + a1 * w1.z) * c1.z + c2.z);
        As[h4 + 3][m] = elu_f((u.w + v.w + a0 * w0.w + a1 * w1.w) * c1.w + c2.w);
        *(float4*)&Bs[kkB][c4] = bv;
        __syncthreads();
        #pragma unroll
        for (int kk = 0; kk < 8; kk++) {
            float a[8], bb[8];
            *(float4*)(a)     = *(const float4*)&As[kk][m_base];
            *(float4*)(a + 4) = *(const float4*)&As[kk][m_base + 4];
            *(float4*)(bb)     = *(const float4*)&Bs[kk][n_base];
            *(float4*)(bb + 4) = *(const float4*)&Bs[kk][n_base + 4];
            #pragma unroll
            for (int mi = 0; mi < 8; mi++)
                #pragma unroll
                for (int ni = 0; ni < 8; ni++)
                    acc[mi][ni] += a[mi] * bb[ni];
        }
    }
    float4 bt0 = *(const float4*)(b2t + n0 + n_base);
    float4 bt1 = *(const float4*)(b2t + n0 + n_base + 4);
    #pragma unroll
    for (int mi = 0; mi < 8; mi++) {
        float* prow = g_na + (size_t)(m0 + m_base + mi) * ODIM + n0 + n_base;
        *(float4*)(prow) = make_float4(acc[mi][0] + bt0.x, acc[mi][1] + bt0.y,
                                       acc[mi][2] + bt0.z, acc[mi][3] + bt0.w);
        *(float4*)(prow + 4) = make_float4(acc[mi][4] + bt1.x, acc[mi][5] + bt1.y,
                                           acc[mi][6] + bt1.z, acc[mi][7] + bt1.w);
    }
}

// ---------------- kernel 7: fused final_read_score (GEMM3 + GEMM4) ---------
__global__ void k_score(const float* __restrict__ adjs, const float* __restrict__ flags,
                        const float* __restrict__ W1r, const float* __restrict__ b1r,
                        const float* __restrict__ W2r, const float* __restrict__ b2r,
                        float* __restrict__ out_score) {
    __shared__ float As[8][128];
    __shared__ float Bs[8][128];
    __shared__ float a0s[128], a1s[128], msks[128];
    int t = threadIdx.x;
    int m0 = blockIdx.x * 128;
    int b = m0 >> 12;
    if (t < 128) {
        int e = m0 + t;
        int i = (e >> 6) & 63, j = e & 63;
        float mk = flags[b * 64 + i] * flags[b * 64 + j];
        float a = adjs[(size_t)b * 4096 + i * 64 + j];
        a0s[t] = a * mk;
        a1s[t] = (1.f - a) * mk;
        msks[t] = mk;
    }
    __syncthreads();
    int m = t >> 1, h4 = (t & 1) * 4;
    int e_ij = m0 + m;
    int im = (e_ij >> 6) & 63, jm = e_ij & 63;
    int e_ji = b * 4096 + jm * 64 + im;
    const float* pIJ = g_na + (size_t)e_ij * ODIM + h4;
    const float* pJI = g_na + (size_t)e_ji * ODIM + h4;
    float mskm = msks[m];
    int kkB = t >> 5, c4 = (t & 31) * 4;
    int m_base = (t >> 4) * 8, n_base = (t & 15) * 8;
    float a0r[8], a1r[8];
    #pragma unroll
    for (int mi = 0; mi < 8; mi++) {
        a0r[mi] = a0s[m_base + mi];
        a1r[mi] = a1s[m_base + mi];
    }
    float score8[8];
    #pragma unroll
    for (int mi = 0; mi < 8; mi++) score8[mi] = 0.f;

    for (int nc = 0; nc < 13; nc++) {
        int n0 = nc * 128;
        float brv[8], w0v[8], w1v[8], w2v[8];
        #pragma unroll
        for (int ni = 0; ni < 8; ni++) {
            int n = n0 + n_base + ni;
            bool ok = (n < HR);
            brv[ni] = ok ? b1r[n] : 0.f;
            w0v[ni] = ok ? W1r[n] : 0.f;          // a0 channel row
            w1v[ni] = ok ? W1r[HR + n] : 0.f;     // a1 channel row
            w2v[ni] = ok ? W2r[n] : 0.f;
        }
        float acc[8][8];
        #pragma unroll
        for (int mi = 0; mi < 8; mi++)
            #pragma unroll
            for (int ni = 0; ni < 8; ni++)
                acc[mi][ni] = brv[ni] + a0r[mi] * w0v[ni] + a1r[mi] * w1v[ni];

        for (int k0 = 0; k0 < ODIM; k0 += 8) {
            float4 u = *(const float4*)(pIJ + k0);
            float4 v = *(const float4*)(pJI + k0);
            float4 bvec;
            const float* p = W1r + (size_t)(2 + k0 + kkB) * HR + n0 + c4;
            if (n0 + c4 + 3 < HR) {
                bvec = *(const float4*)p;
            } else {
                bvec.x = (n0 + c4 + 0 < HR) ? p[0] : 0.f;
                bvec.y = (n0 + c4 + 1 < HR) ? p[1] : 0.f;
                bvec.z = (n0 + c4 + 2 < HR) ? p[2] : 0.f;
                bvec.w = (n0 + c4 + 3 < HR) ? p[3] : 0.f;
            }
            __syncthreads();
            As[h4 + 0][m] = (u.x + v.x) * mskm;
            As[h4 + 1][m] = (u.y + v.y) * mskm;
            As[h4 + 2][m] = (u.z + v.z) * mskm;
            As[h4 + 3][m] = (u.w + v.w) * mskm;
            *(float4*)&Bs[kkB][c4] = bvec;
            __syncthreads();
            #pragma unroll
            for (int kk = 0; kk < 8; kk++) {
                float a[8], bb[8];
                *(float4*)(a)     = *(const float4*)&As[kk][m_base];
                *(float4*)(a + 4) = *(const float4*)&As[kk][m_base + 4];
                *(float4*)(bb)     = *(const float4*)&Bs[kk][n_base];
                *(float4*)(bb + 4) = *(const float4*)&Bs[kk][n_base + 4];
                #pragma unroll
                for (int mi = 0; mi < 8; mi++)
                    #pragma unroll
                    for (int ni = 0; ni < 8; ni++)
                        acc[mi][ni] += a[mi] * bb[ni];
            }
        }
        #pragma unroll
        for (int mi = 0; mi < 8; mi++)
            #pragma unroll
            for (int ni = 0; ni < 8; ni++)
                score8[mi] += elu_f(acc[mi][ni]) * w2v[ni];
    }
    // reduce over the 16 threads (tx) that share each row group
    #pragma unroll
    for (int off = 8; off > 0; off >>= 1)
        #pragma unroll
        for (int mi = 0; mi < 8; mi++)
            score8[mi] += __shfl_xor_sync(0xffffffffu, score8[mi], off);
    if ((t & 15) == 0) {
        float b2 = b2r[0];
        #pragma unroll
        for (int mi = 0; mi < 8; mi++) {
            int e = m0 + m_base + mi;
            int i = (e >> 6) & 63, j = e & 63;
            out_score[e] = (i == j) ? 0.f : (score8[mi] + b2);
        }
    }
}

// ---------------- launch -----------------------------------------------------
extern "C" void kernel_launch(void* const* d_in, const int* in_sizes, int n_in,
                              void* d_out, int out_size) {
    const float* x     = (const float*)d_in[0];
    const float* adjs  = (const float*)d_in[1];
    const float* flags = (const float*)d_in[2];
    const float* Wg    = (const float*)d_in[3];
    const float* bg    = (const float*)d_in[4];
    const float* Wout  = (const float*)d_in[5];
    const float* bout  = (const float*)d_in[6];
    const float* W1t   = (const float*)d_in[7];
    const float* b1t   = (const float*)d_in[8];
    const float* gamma = (const float*)d_in[9];
    const float* beta  = (const float*)d_in[10];
    const float* W2t   = (const float*)d_in[11];
    const float* b2t   = (const float*)d_in[12];
    const float* W1r   = (const float*)d_in[13];
    const float* b1r   = (const float*)d_in[14];
    const float* W2r   = (const float*)d_in[15];
    const float* b2r   = (const float*)d_in[16];

    float* out_score = (float*)d_out;             // [B,N,N] = 65536
    float* out_xo    = (float*)d_out + NEDGE;     // [B,N,768]

    k_agg<<<NROW, 128>>>(x, adjs, flags);
    k_gin<<<NROW / 8, 256>>>(x, flags, Wg, bg, Wout, bout, out_xo);
    k_uv<<<dim3(24, 8), 256>>>(out_xo, W1t);
    k_stats<<<NROW, 256>>>(adjs, flags, W1t);
    k_stats2<<<6, 256>>>(b1t, gamma, beta);
    k_gemm2<<<dim3(6, 512), 256>>>(adjs, flags, W1t, W2t, b2t);
    k_score<<<512, 256>>>(adjs, flags, W1r, b1r, W2r, b2r, out_score);
}

// round 7
// speedup vs baseline: 1.2919x; 1.2919x over previous
#include <cuda_runtime.h>
#include <cuda_bf16.h>
#include <stdint.h>
#include <cstdint>
#include <math.h>

// Problem constants
#define BB      16
#define NNODE   64
#define FIN     128
#define FHID    256
#define ODIM    768
#define HT      1536   // translate hidden
#define DR      770
#define HR      1540
#define NEDGE   65536  // B*N*N
#define NROW    1024   // B*N

// ---------------- scratch (device globals; no runtime allocation) ----------
__device__ float g_agg[NROW * 256];          // GIN aggregated features [B*N, 2*FIN]
__device__ float g_U[NROW * HT];             // xo @ W1t[2:770]
__device__ float g_V[NROW * HT];             // xo @ W1t[770:1538]
__device__ float g_na[(size_t)NEDGE * ODIM]; // new_adjs pre-symmetrize [e, f]  (201 MB)
__device__ float g_part[NROW * 2 * HT];      // per-(b,i) BN partial sums
__device__ __align__(16) float g_c1[HT];     // folded BN scale
__device__ __align__(16) float g_c2[HT];     // folded BN shift

__device__ __forceinline__ float elu_f(float x) {
    return x > 0.f ? x : (__expf(x) - 1.f);
}
static __device__ __forceinline__ uint32_t pack2(float a, float b) {
    __nv_bfloat162 h = __floats2bfloat162_rn(a, b);
    return *reinterpret_cast<uint32_t*>(&h);
}
// mma.sync m16n8k16 row.col f32.bf16.bf16.f32 (portable PTX, HMMA on sm_103)
static __device__ __forceinline__ void mma16816(float* c, const uint32_t* a,
                                                const uint32_t* b) {
    asm volatile(
        "mma.sync.aligned.m16n8k16.row.col.f32.bf16.bf16.f32 "
        "{%0,%1,%2,%3}, {%4,%5,%6,%7}, {%8,%9}, {%0,%1,%2,%3};"
        : "+f"(c[0]), "+f"(c[1]), "+f"(c[2]), "+f"(c[3])
        : "r"(a[0]), "r"(a[1]), "r"(a[2]), "r"(a[3]), "r"(b[0]), "r"(b[1]));
}

// ---------------- kernel 1: agg[b,i,c,f] = sum_j A_c[b,i,j] * x[b,j,f] ------
__global__ void k_agg(const float* __restrict__ x, const float* __restrict__ adjs,
                      const float* __restrict__ flags) {
    int bi = blockIdx.x;
    int b = bi >> 6, i = bi & 63;
    int f = threadIdx.x;
    __shared__ float a0s[64], a1s[64];
    float fi = flags[b * 64 + i];
    if (threadIdx.x < 64) {
        int j = threadIdx.x;
        float fj = flags[b * 64 + j];
        float a = adjs[(size_t)bi * 64 + j];
        float m = fi * fj;
        a0s[j] = a * m;
        a1s[j] = (1.f - a) * m;
    }
    __syncthreads();
    float s0 = 0.f, s1 = 0.f;
    const float* xb = x + (size_t)b * NNODE * FIN;
    #pragma unroll 4
    for (int j = 0; j < 64; j++) {
        float xv = xb[j * FIN + f];
        s0 += a0s[j] * xv;
        s1 += a1s[j] * xv;
    }
    g_agg[bi * 256 + f] = s0;
    g_agg[bi * 256 + 128 + f] = s1;
}

// ---------------- kernel 2: GIN MLPs -> x_o ---------------------------------
__global__ void k_gin(const float* __restrict__ x, const float* __restrict__ flags,
                      const float* __restrict__ Wg, const float* __restrict__ bg,
                      const float* __restrict__ Wout, const float* __restrict__ bout,
                      float* __restrict__ out_xo) {
    __shared__ float aggs[8][256];
    __shared__ float xs[8][128];
    __shared__ float hs[8][256];
    __shared__ float fl[8];
    int r0 = blockIdx.x * 8;
    int t = threadIdx.x;
    for (int idx = t; idx < 8 * 256; idx += 256)
        aggs[idx >> 8][idx & 255] = g_agg[r0 * 256 + idx];
    for (int idx = t; idx < 8 * 128; idx += 256)
        xs[idx >> 7][idx & 127] = x[(size_t)r0 * 128 + idx];
    if (t < 8) fl[t] = flags[r0 + t];
    __syncthreads();
    {
        float acc[8];
        float bgv = bg[t];
        #pragma unroll
        for (int r = 0; r < 8; r++) acc[r] = bgv;
        for (int k = 0; k < 256; k++) {
            float w = Wg[k * 256 + t];
            #pragma unroll
            for (int r = 0; r < 8; r++) acc[r] += aggs[r][k] * w;
        }
        #pragma unroll
        for (int r = 0; r < 8; r++) hs[r][t] = elu_f(acc[r]) * fl[r];
    }
    __syncthreads();
    float acc[3][8];
    #pragma unroll
    for (int c = 0; c < 3; c++) {
        float bo = bout[t + c * 256];
        #pragma unroll
        for (int r = 0; r < 8; r++) acc[c][r] = bo;
    }
    for (int k = 0; k < 128; k++) {
        float o[8];
        #pragma unroll
        for (int r = 0; r < 8; r++) o[r] = xs[r][k];
        #pragma unroll
        for (int c = 0; c < 3; c++) {
            float w = Wout[k * 768 + t + c * 256];
            #pragma unroll
            for (int r = 0; r < 8; r++) acc[c][r] += o[r] * w;
        }
    }
    for (int k = 0; k < 256; k++) {
        float o[8];
        #pragma unroll
        for (int r = 0; r < 8; r++) o[r] = hs[r][k];
        #pragma unroll
        for (int c = 0; c < 3; c++) {
            float w = Wout[(128 + k) * 768 + t + c * 256];
            #pragma unroll
            for (int r = 0; r < 8; r++) acc[c][r] += o[r] * w;
        }
    }
    #pragma unroll
    for (int c = 0; c < 3; c++)
        #pragma unroll
        for (int r = 0; r < 8; r++)
            out_xo[(size_t)(r0 + r) * 768 + t + c * 256] = tanhf(acc[c][r]) * fl[r];
}

// ---------------- kernel 3: U,V = xo @ W1t[2:770], xo @ W1t[770:1538] -------
__global__ void k_uv(const float* __restrict__ xo, const float* __restrict__ W1t) {
    __shared__ float As[8][128];
    __shared__ float Bs[8][128];
    int t = threadIdx.x;
    int m0 = blockIdx.y * 128;
    int ng0 = blockIdx.x * 128;
    const int isU = (ng0 < HT);
    const float* Bbase = W1t + (size_t)(isU ? 2 : 770) * HT + (isU ? ng0 : ng0 - HT);
    int m = t >> 1, h4 = (t & 1) * 4;
    const float* pA = xo + (size_t)(m0 + m) * 768 + h4;
    int kkB = t >> 5, c4 = (t & 31) * 4;
    int m_base = (t >> 4) * 8, n_base = (t & 15) * 8;

    float acc[8][8];
    #pragma unroll
    for (int a = 0; a < 8; a++)
        #pragma unroll
        for (int bq = 0; bq < 8; bq++) acc[a][bq] = 0.f;

    for (int k0 = 0; k0 < 768; k0 += 8) {
        float4 av = *(const float4*)(pA + k0);
        float4 bv = *(const float4*)(Bbase + (size_t)(k0 + kkB) * HT + c4);
        __syncthreads();
        As[h4 + 0][m] = av.x; As[h4 + 1][m] = av.y;
        As[h4 + 2][m] = av.z; As[h4 + 3][m] = av.w;
        *(float4*)&Bs[kkB][c4] = bv;
        __syncthreads();
        #pragma unroll
        for (int kk = 0; kk < 8; kk++) {
            float a[8], bb[8];
            *(float4*)(a)     = *(const float4*)&As[kk][m_base];
            *(float4*)(a + 4) = *(const float4*)&As[kk][m_base + 4];
            *(float4*)(bb)     = *(const float4*)&Bs[kk][n_base];
            *(float4*)(bb + 4) = *(const float4*)&Bs[kk][n_base + 4];
            #pragma unroll
            for (int mi = 0; mi < 8; mi++)
                #pragma unroll
                for (int ni = 0; ni < 8; ni++)
                    acc[mi][ni] += a[mi] * bb[ni];
        }
    }
    float* Obase = isU ? g_U : g_V;
    int c0 = isU ? ng0 : ng0 - HT;
    #pragma unroll
    for (int mi = 0; mi < 8; mi++) {
        float* prow = Obase + (size_t)(m0 + m_base + mi) * HT + c0 + n_base;
        *(float4*)(prow)     = make_float4(acc[mi][0], acc[mi][1], acc[mi][2], acc[mi][3]);
        *(float4*)(prow + 4) = make_float4(acc[mi][4], acc[mi][5], acc[mi][6], acc[mi][7]);
    }
}

// ---------------- kernel 4: BN stats partials -------------------------------
__global__ void k_stats(const float* __restrict__ adjs, const float* __restrict__ flags,
                        const float* __restrict__ W1t) {
    int bi = blockIdx.x;
    int b = bi >> 6, i = bi & 63;
    int t = threadIdx.x;
    __shared__ float Ur[HT];
    __shared__ float a0s[64], a1s[64];
    for (int k = t; k < HT; k += 256) Ur[k] = g_U[(size_t)bi * HT + k];
    if (t < 64) {
        int j = t;
        float m = flags[b * 64 + i] * flags[b * 64 + j];
        float a = adjs[(size_t)bi * 64 + j];
        a0s[j] = a * m;
        a1s[j] = (1.f - a) * m;
    }
    __syncthreads();
    float w0[6], w1[6], u[6], sum[6], sq[6];
    #pragma unroll
    for (int s = 0; s < 6; s++) {
        int k = t + s * 256;
        w0[s] = W1t[k];
        w1[s] = W1t[HT + k];
        u[s] = Ur[k];
        sum[s] = 0.f; sq[s] = 0.f;
    }
    const float* Vb = g_V + (size_t)(b * 64) * HT;
    for (int j = 0; j < 64; j++) {
        float a0 = a0s[j], a1 = a1s[j];
        const float* Vr = Vb + (size_t)j * HT;
        #pragma unroll
        for (int s = 0; s < 6; s++) {
            float z = u[s] + Vr[t + s * 256] + a0 * w0[s] + a1 * w1[s];
            sum[s] += z;
            sq[s] += z * z;
        }
    }
    #pragma unroll
    for (int s = 0; s < 6; s++) {
        g_part[(size_t)bi * 3072 + t + s * 256] = sum[s];
        g_part[(size_t)bi * 3072 + HT + t + s * 256] = sq[s];
    }
}

// ---------------- kernel 5: finalize BN constants ---------------------------
__global__ void k_stats2(const float* __restrict__ b1t, const float* __restrict__ gamma,
                         const float* __restrict__ beta) {
    int k = blockIdx.x * 256 + threadIdx.x;
    float s = 0.f, q = 0.f;
    for (int bi = 0; bi < NROW; bi++) {
        s += g_part[(size_t)bi * 3072 + k];
        q += g_part[(size_t)bi * 3072 + HT + k];
    }
    const float inv = 1.f / 65536.f;
    float mu_z = s * inv;
    float var = fmaxf(q * inv - mu_z * mu_z, 0.f);
    float mu = mu_z + b1t[k];
    float c1 = gamma[k] * rsqrtf(var + 1e-5f);
    g_c1[k] = c1;
    g_c2[k] = beta[k] - mu * c1;
}

// ---------------- kernel 6: mma.sync bf16-split translate GEMM --------------
// C[128 edges, 256 feats] per CTA, grid (3, 512). K=1536 in 48 chunks of 32.
// A = elu(BN(U_i+V_j+a0*w0+a1*w1)) generated per chunk -> bf16 hi/lo in SMEM;
// B = W2t chunk transposed to [n][k] (stride 40 bf16) hi/lo.
// 16 warps: 2 (M) x 8 (N); warp tile 64x32 = 4x4 m16n8k16 tiles.
// 3-product split: Ah*Bh + Ah*Bl + Al*Bh, fp32 accum.
#define GM_A0S  0
#define GM_A1S  512
#define GM_AH   1024
#define GM_AL   11264
#define GM_BH   21504
#define GM_BL   41984
#define GM_SMEM 62464
#define KPAD    80   // bytes per k-row (40 bf16)

__global__ void __launch_bounds__(512, 1)
k_gemm2_mma(const float* __restrict__ adjs, const float* __restrict__ flags,
            const float* __restrict__ W1t, const float* __restrict__ W2t,
            const float* __restrict__ b2t) {
    extern __shared__ char sm[];
    float* a0s = (float*)(sm + GM_A0S);
    float* a1s = (float*)(sm + GM_A1S);
    int t = threadIdx.x;
    int m0 = blockIdx.y * 128, n0g = blockIdx.x * 256;
    int b = m0 >> 12;

    if (t < 128) {
        int e = m0 + t, i = (e >> 6) & 63, j = e & 63;
        float mk = flags[b * 64 + i] * flags[b * 64 + j];
        float a = adjs[(size_t)b * 4096 + i * 64 + j];
        a0s[t] = a * mk;
        a1s[t] = (1.f - a) * mk;
    }
    __syncthreads();

    // A-gen mapping: each thread owns row mrow, k-quad window kq..kq+7
    int mrow = t >> 2, kq = (t & 3) * 8;
    int e = m0 + mrow, im = (e >> 6) & 63, jm = e & 63;
    const float* pU = g_U + (size_t)(b * 64 + im) * HT;
    const float* pV = g_V + (size_t)(b * 64 + jm) * HT;
    float a0 = a0s[mrow], a1 = a1s[mrow];

    // warp mapping
    int wid = t >> 5, lane = t & 31;
    int mw = (wid & 1) * 64, nw = (wid >> 1) * 32;
    int row4 = lane >> 2, quad = lane & 3;

    float acc[4][4][4];
    #pragma unroll
    for (int tm = 0; tm < 4; tm++)
        #pragma unroll
        for (int tn = 0; tn < 4; tn++)
            #pragma unroll
            for (int q = 0; q < 4; q++) acc[tm][tn][q] = 0.f;

    for (int c = 0; c < 48; c++) {
        int k0 = c * 32;
        if (c) __syncthreads();   // protect frag reads of previous chunk
        // ---- A-gen: 128 x 32, hi/lo bf16 ----
        #pragma unroll
        for (int h = 0; h < 2; h++) {
            int kl = kq + h * 4, k = k0 + kl;
            float4 u  = *(const float4*)(pU + k);
            float4 v  = *(const float4*)(pV + k);
            float4 w0 = __ldg((const float4*)(W1t + k));
            float4 w1 = __ldg((const float4*)(W1t + HT + k));
            float4 c1 = *(const float4*)(g_c1 + k);
            float4 c2 = *(const float4*)(g_c2 + k);
            float z0 = elu_f((u.x + v.x + a0 * w0.x + a1 * w1.x) * c1.x + c2.x);
            float z1 = elu_f((u.y + v.y + a0 * w0.y + a1 * w1.y) * c1.y + c2.y);
            float z2 = elu_f((u.z + v.z + a0 * w0.z + a1 * w1.z) * c1.z + c2.z);
            float z3 = elu_f((u.w + v.w + a0 * w0.w + a1 * w1.w) * c1.w + c2.w);
            float r0 = z0 - __bfloat162float(__float2bfloat16(z0));
            float r1 = z1 - __bfloat162float(__float2bfloat16(z1));
            float r2 = z2 - __bfloat162float(__float2bfloat16(z2));
            float r3 = z3 - __bfloat162float(__float2bfloat16(z3));
            int off = mrow * KPAD + kl * 2;
            *(uint2*)(sm + GM_AH + off) = make_uint2(pack2(z0, z1), pack2(z2, z3));
            *(uint2*)(sm + GM_AL + off) = make_uint2(pack2(r0, r1), pack2(r2, r3));
        }
        // ---- B-load: W2t[k0:k0+32, n0g:n0g+256] -> [n][k] hi/lo ----
        #pragma unroll
        for (int it = 0; it < 4; it++) {
            int idx = t + it * 512;
            int n = idx & 255, kk = (idx >> 8) * 4;
            const float* pw = W2t + (size_t)(k0 + kk) * 768 + n0g + n;
            float w0v = __ldg(pw), w1v = __ldg(pw + 768),
                  w2v = __ldg(pw + 1536), w3v = __ldg(pw + 2304);
            float r0 = w0v - __bfloat162float(__float2bfloat16(w0v));
            float r1 = w1v - __bfloat162float(__float2bfloat16(w1v));
            float r2 = w2v - __bfloat162float(__float2bfloat16(w2v));
            float r3 = w3v - __bfloat162float(__float2bfloat16(w3v));
            int off = n * KPAD + kk * 2;
            *(uint2*)(sm + GM_BH + off) = make_uint2(pack2(w0v, w1v), pack2(w2v, w3v));
            *(uint2*)(sm + GM_BL + off) = make_uint2(pack2(r0, r1), pack2(r2, r3));
        }
        __syncthreads();
        // ---- 2 k-steps of m16n8k16 ----
        #pragma unroll
        for (int ks = 0; ks < 2; ks++) {
            int kb = ks * 32 + quad * 4;       // byte offset along k for this lane
            uint32_t af[4][4], bf[4][2];
            // hi*hi
            #pragma unroll
            for (int tm = 0; tm < 4; tm++) {
                int base = GM_AH + (mw + tm * 16 + row4) * KPAD + kb;
                af[tm][0] = *(const uint32_t*)(sm + base);
                af[tm][1] = *(const uint32_t*)(sm + base + 8 * KPAD);
                af[tm][2] = *(const uint32_t*)(sm + base + 16);
                af[tm][3] = *(const uint32_t*)(sm + base + 8 * KPAD + 16);
            }
            #pragma unroll
            for (int tn = 0; tn < 4; tn++) {
                int base = GM_BH + (nw + tn * 8 + row4) * KPAD + kb;
                bf[tn][0] = *(const uint32_t*)(sm + base);
                bf[tn][1] = *(const uint32_t*)(sm + base + 16);
            }
            #pragma unroll
            for (int tm = 0; tm < 4; tm++)
                #pragma unroll
                for (int tn = 0; tn < 4; tn++)
                    mma16816(acc[tm][tn], af[tm], bf[tn]);
            // hi*lo
            #pragma unroll
            for (int tn = 0; tn < 4; tn++) {
                int base = GM_BL + (nw + tn * 8 + row4) * KPAD + kb;
                bf[tn][0] = *(const uint32_t*)(sm + base);
                bf[tn][1] = *(const uint32_t*)(sm + base + 16);
            }
            #pragma unroll
            for (int tm = 0; tm < 4; tm++)
                #pragma unroll
                for (int tn = 0; tn < 4; tn++)
                    mma16816(acc[tm][tn], af[tm], bf[tn]);
            // lo*hi
            #pragma unroll
            for (int tm = 0; tm < 4; tm++) {
                int base = GM_AL + (mw + tm * 16 + row4) * KPAD + kb;
                af[tm][0] = *(const uint32_t*)(sm + base);
                af[tm][1] = *(const uint32_t*)(sm + base + 8 * KPAD);
                af[tm][2] = *(const uint32_t*)(sm + base + 16);
                af[tm][3] = *(const uint32_t*)(sm + base + 8 * KPAD + 16);
            }
            #pragma unroll
            for (int tn = 0; tn < 4; tn++) {
                int base = GM_BH + (nw + tn * 8 + row4) * KPAD + kb;
                bf[tn][0] = *(const uint32_t*)(sm + base);
                bf[tn][1] = *(const uint32_t*)(sm + base + 16);
            }
            #pragma unroll
            for (int tm = 0; tm < 4; tm++)
                #pragma unroll
                for (int tn = 0; tn < 4; tn++)
                    mma16816(acc[tm][tn], af[tm], bf[tn]);
        }
    }

    // ---- epilogue: +b2t, write g_na ----
    #pragma unroll
    for (int tm = 0; tm < 4; tm++) {
        int gr = m0 + mw + tm * 16 + row4;
        #pragma unroll
        for (int tn = 0; tn < 4; tn++) {
            int gc = n0g + nw + tn * 8 + quad * 2;
            float bx = __ldg(b2t + gc), by = __ldg(b2t + gc + 1);
            float* p0 = g_na + (size_t)gr * 768 + gc;
            float* p1 = g_na + (size_t)(gr + 8) * 768 + gc;
            *(float2*)p0 = make_float2(acc[tm][tn][0] + bx, acc[tm][tn][1] + by);
            *(float2*)p1 = make_float2(acc[tm][tn][2] + bx, acc[tm][tn][3] + by);
        }
    }
}

// ---------------- kernel 7: fused final_read_score (GEMM3 + GEMM4) ---------
__global__ void k_score(const float* __restrict__ adjs, const float* __restrict__ flags,
                        const float* __restrict__ W1r, const float* __restrict__ b1r,
                        const float* __restrict__ W2r, const float* __restrict__ b2r,
                        float* __restrict__ out_score) {
    __shared__ float As[8][128];
    __shared__ float Bs[8][128];
    __shared__ float a0s[128], a1s[128], msks[128];
    int t = threadIdx.x;
    int m0 = blockIdx.x * 128;
    int b = m0 >> 12;
    if (t < 128) {
        int e = m0 + t;
        int i = (e >> 6) & 63, j = e & 63;
        float mk = flags[b * 64 + i] * flags[b * 64 + j];
        float a = adjs[(size_t)b * 4096 + i * 64 + j];
        a0s[t] = a * mk;
        a1s[t] = (1.f - a) * mk;
        msks[t] = mk;
    }
    __syncthreads();
    int m = t >> 1, h4 = (t & 1) * 4;
    int e_ij = m0 + m;
    int im = (e_ij >> 6) & 63, jm = e_ij & 63;
    int e_ji = b * 4096 + jm * 64 + im;
    const float* pIJ = g_na + (size_t)e_ij * ODIM + h4;
    const float* pJI = g_na + (size_t)e_ji * ODIM + h4;
    float mskm = msks[m];
    int kkB = t >> 5, c4 = (t & 31) * 4;
    int m_base = (t >> 4) * 8, n_base = (t & 15) * 8;
    float a0r[8], a1r[8];
    #pragma unroll
    for (int mi = 0; mi < 8; mi++) {
        a0r[mi] = a0s[m_base + mi];
        a1r[mi] = a1s[m_base + mi];
    }
    float score8[8];
    #pragma unroll
    for (int mi = 0; mi < 8; mi++) score8[mi] = 0.f;

    for (int nc = 0; nc < 13; nc++) {
        int n0 = nc * 128;
        float brv[8], w0v[8], w1v[8], w2v[8];
        #pragma unroll
        for (int ni = 0; ni < 8; ni++) {
            int n = n0 + n_base + ni;
            bool ok = (n < HR);
            brv[ni] = ok ? b1r[n] : 0.f;
            w0v[ni] = ok ? W1r[n] : 0.f;
            w1v[ni] = ok ? W1r[HR + n] : 0.f;
            w2v[ni] = ok ? W2r[n] : 0.f;
        }
        float acc[8][8];
        #pragma unroll
        for (int mi = 0; mi < 8; mi++)
            #pragma unroll
            for (int ni = 0; ni < 8; ni++)
                acc[mi][ni] = brv[ni] + a0r[mi] * w0v[ni] + a1r[mi] * w1v[ni];

        for (int k0 = 0; k0 < ODIM; k0 += 8) {
            float4 u = *(const float4*)(pIJ + k0);
            float4 v = *(const float4*)(pJI + k0);
            float4 bvec;
            const float* p = W1r + (size_t)(2 + k0 + kkB) * HR + n0 + c4;
            if (n0 + c4 + 3 < HR) {
                bvec = *(const float4*)p;
            } else {
                bvec.x = (n0 + c4 + 0 < HR) ? p[0] : 0.f;
                bvec.y = (n0 + c4 + 1 < HR) ? p[1] : 0.f;
                bvec.z = (n0 + c4 + 2 < HR) ? p[2] : 0.f;
                bvec.w = (n0 + c4 + 3 < HR) ? p[3] : 0.f;
            }
            __syncthreads();
            As[h4 + 0][m] = (u.x + v.x) * mskm;
            As[h4 + 1][m] = (u.y + v.y) * mskm;
            As[h4 + 2][m] = (u.z + v.z) * mskm;
            As[h4 + 3][m] = (u.w + v.w) * mskm;
            *(float4*)&Bs[kkB][c4] = bvec;
            __syncthreads();
            #pragma unroll
            for (int kk = 0; kk < 8; kk++) {
                float a[8], bb[8];
                *(float4*)(a)     = *(const float4*)&As[kk][m_base];
                *(float4*)(a + 4) = *(const float4*)&As[kk][m_base + 4];
                *(float4*)(bb)     = *(const float4*)&Bs[kk][n_base];
                *(float4*)(bb + 4) = *(const float4*)&Bs[kk][n_base + 4];
                #pragma unroll
                for (int mi = 0; mi < 8; mi++)
                    #pragma unroll
                    for (int ni = 0; ni < 8; ni++)
                        acc[mi][ni] += a[mi] * bb[ni];
            }
        }
        #pragma unroll
        for (int mi = 0; mi < 8; mi++)
            #pragma unroll
            for (int ni = 0; ni < 8; ni++)
                score8[mi] += elu_f(acc[mi][ni]) * w2v[ni];
    }
    #pragma unroll
    for (int off = 8; off > 0; off >>= 1)
        #pragma unroll
        for (int mi = 0; mi < 8; mi++)
            score8[mi] += __shfl_xor_sync(0xffffffffu, score8[mi], off);
    if ((t & 15) == 0) {
        float b2 = b2r[0];
        #pragma unroll
        for (int mi = 0; mi < 8; mi++) {
            int e = m0 + m_base + mi;
            int i = (e >> 6) & 63, j = e & 63;
            out_score[e] = (i == j) ? 0.f : (score8[mi] + b2);
        }
    }
}

// ---------------- launch -----------------------------------------------------
extern "C" void kernel_launch(void* const* d_in, const int* in_sizes, int n_in,
                              void* d_out, int out_size) {
    const float* x     = (const float*)d_in[0];
    const float* adjs  = (const float*)d_in[1];
    const float* flags = (const float*)d_in[2];
    const float* Wg    = (const float*)d_in[3];
    const float* bg    = (const float*)d_in[4];
    const float* Wout  = (const float*)d_in[5];
    const float* bout  = (const float*)d_in[6];
    const float* W1t   = (const float*)d_in[7];
    const float* b1t   = (const float*)d_in[8];
    const float* gamma = (const float*)d_in[9];
    const float* beta  = (const float*)d_in[10];
    const float* W2t   = (const float*)d_in[11];
    const float* b2t   = (const float*)d_in[12];
    const float* W1r   = (const float*)d_in[13];
    const float* b1r   = (const float*)d_in[14];
    const float* W2r   = (const float*)d_in[15];
    const float* b2r   = (const float*)d_in[16];

    float* out_score = (float*)d_out;             // [B,N,N] = 65536
    float* out_xo    = (float*)d_out + NEDGE;     // [B,N,768]

    cudaFuncSetAttribute(k_gemm2_mma, cudaFuncAttributeMaxDynamicSharedMemorySize, GM_SMEM);

    k_agg<<<NROW, 128>>>(x, adjs, flags);
    k_gin<<<NROW / 8, 256>>>(x, flags, Wg, bg, Wout, bout, out_xo);
    k_uv<<<dim3(24, 8), 256>>>(out_xo, W1t);
    k_stats<<<NROW, 256>>>(adjs, flags, W1t);
    k_stats2<<<6, 256>>>(b1t, gamma, beta);
    k_gemm2_mma<<<dim3(3, 512), 512, GM_SMEM>>>(adjs, flags, W1t, W2t, b2t);
    k_score<<<512, 256>>>(adjs, flags, W1r, b1r, W2r, b2r, out_score);
}

// round 8
// speedup vs baseline: 2.0475x; 1.5849x over previous
#include <cuda_runtime.h>
#include <cuda_bf16.h>
#include <stdint.h>
#include <cstdint>
#include <math.h>

// Problem constants
#define BB      16
#define NNODE   64
#define FIN     128
#define FHID    256
#define ODIM    768
#define HT      1536   // translate hidden
#define DR      770
#define HR      1540
#define NEDGE   65536  // B*N*N
#define NROW    1024   // B*N

// ---------------- scratch (device globals; no runtime allocation) ----------
__device__ float g_agg[NROW * 256];          // GIN aggregated features [B*N, 2*FIN]
__device__ float g_U[NROW * HT];             // xo @ W1t[2:770]
__device__ float g_V[NROW * HT];             // xo @ W1t[770:1538]
__device__ float g_na[(size_t)NEDGE * ODIM]; // new_adjs pre-symmetrize [e, f]  (201 MB)
__device__ __align__(16) __nv_bfloat16 g_sh[(size_t)NEDGE * ODIM]; // sym hi (100 MB)
__device__ __align__(16) __nv_bfloat16 g_sl[(size_t)NEDGE * ODIM]; // sym lo (100 MB)
__device__ float g_part[NROW * 2 * HT];      // per-(b,i) BN partial sums
__device__ __align__(16) float g_c1[HT];     // folded BN scale
__device__ __align__(16) float g_c2[HT];     // folded BN shift

__device__ __forceinline__ float elu_f(float x) {
    return x > 0.f ? x : (__expf(x) - 1.f);
}
static __device__ __forceinline__ uint32_t pack2(float a, float b) {
    __nv_bfloat162 h = __floats2bfloat162_rn(a, b);
    return *reinterpret_cast<uint32_t*>(&h);
}
// mma.sync m16n8k16 row.col f32.bf16.bf16.f32 (portable PTX, HMMA on sm_103)
static __device__ __forceinline__ void mma16816(float* c, const uint32_t* a,
                                                const uint32_t* b) {
    asm volatile(
        "mma.sync.aligned.m16n8k16.row.col.f32.bf16.bf16.f32 "
        "{%0,%1,%2,%3}, {%4,%5,%6,%7}, {%8,%9}, {%0,%1,%2,%3};"
        : "+f"(c[0]), "+f"(c[1]), "+f"(c[2]), "+f"(c[3])
        : "r"(a[0]), "r"(a[1]), "r"(a[2]), "r"(a[3]), "r"(b[0]), "r"(b[1]));
}

// ---------------- kernel 1: agg[b,i,c,f] = sum_j A_c[b,i,j] * x[b,j,f] ------
__global__ void k_agg(const float* __restrict__ x, const float* __restrict__ adjs,
                      const float* __restrict__ flags) {
    int bi = blockIdx.x;
    int b = bi >> 6, i = bi & 63;
    int f = threadIdx.x;
    __shared__ float a0s[64], a1s[64];
    float fi = flags[b * 64 + i];
    if (threadIdx.x < 64) {
        int j = threadIdx.x;
        float fj = flags[b * 64 + j];
        float a = adjs[(size_t)bi * 64 + j];
        float m = fi * fj;
        a0s[j] = a * m;
        a1s[j] = (1.f - a) * m;
    }
    __syncthreads();
    float s0 = 0.f, s1 = 0.f;
    const float* xb = x + (size_t)b * NNODE * FIN;
    #pragma unroll 4
    for (int j = 0; j < 64; j++) {
        float xv = xb[j * FIN + f];
        s0 += a0s[j] * xv;
        s1 += a1s[j] * xv;
    }
    g_agg[bi * 256 + f] = s0;
    g_agg[bi * 256 + 128 + f] = s1;
}

// ---------------- kernel 2: GIN MLPs -> x_o ---------------------------------
__global__ void k_gin(const float* __restrict__ x, const float* __restrict__ flags,
                      const float* __restrict__ Wg, const float* __restrict__ bg,
                      const float* __restrict__ Wout, const float* __restrict__ bout,
                      float* __restrict__ out_xo) {
    __shared__ float aggs[8][256];
    __shared__ float xs[8][128];
    __shared__ float hs[8][256];
    __shared__ float fl[8];
    int r0 = blockIdx.x * 8;
    int t = threadIdx.x;
    for (int idx = t; idx < 8 * 256; idx += 256)
        aggs[idx >> 8][idx & 255] = g_agg[r0 * 256 + idx];
    for (int idx = t; idx < 8 * 128; idx += 256)
        xs[idx >> 7][idx & 127] = x[(size_t)r0 * 128 + idx];
    if (t < 8) fl[t] = flags[r0 + t];
    __syncthreads();
    {
        float acc[8];
        float bgv = bg[t];
        #pragma unroll
        for (int r = 0; r < 8; r++) acc[r] = bgv;
        for (int k = 0; k < 256; k++) {
            float w = Wg[k * 256 + t];
            #pragma unroll
            for (int r = 0; r < 8; r++) acc[r] += aggs[r][k] * w;
        }
        #pragma unroll
        for (int r = 0; r < 8; r++) hs[r][t] = elu_f(acc[r]) * fl[r];
    }
    __syncthreads();
    float acc[3][8];
    #pragma unroll
    for (int c = 0; c < 3; c++) {
        float bo = bout[t + c * 256];
        #pragma unroll
        for (int r = 0; r < 8; r++) acc[c][r] = bo;
    }
    for (int k = 0; k < 128; k++) {
        float o[8];
        #pragma unroll
        for (int r = 0; r < 8; r++) o[r] = xs[r][k];
        #pragma unroll
        for (int c = 0; c < 3; c++) {
            float w = Wout[k * 768 + t + c * 256];
            #pragma unroll
            for (int r = 0; r < 8; r++) acc[c][r] += o[r] * w;
        }
    }
    for (int k = 0; k < 256; k++) {
        float o[8];
        #pragma unroll
        for (int r = 0; r < 8; r++) o[r] = hs[r][k];
        #pragma unroll
        for (int c = 0; c < 3; c++) {
            float w = Wout[(128 + k) * 768 + t + c * 256];
            #pragma unroll
            for (int r = 0; r < 8; r++) acc[c][r] += o[r] * w;
        }
    }
    #pragma unroll
    for (int c = 0; c < 3; c++)
        #pragma unroll
        for (int r = 0; r < 8; r++)
            out_xo[(size_t)(r0 + r) * 768 + t + c * 256] = tanhf(acc[c][r]) * fl[r];
}

// ---------------- kernel 3: U,V = xo @ W1t[2:770], xo @ W1t[770:1538] -------
__global__ void k_uv(const float* __restrict__ xo, const float* __restrict__ W1t) {
    __shared__ float As[8][128];
    __shared__ float Bs[8][128];
    int t = threadIdx.x;
    int m0 = blockIdx.y * 128;
    int ng0 = blockIdx.x * 128;
    const int isU = (ng0 < HT);
    const float* Bbase = W1t + (size_t)(isU ? 2 : 770) * HT + (isU ? ng0 : ng0 - HT);
    int m = t >> 1, h4 = (t & 1) * 4;
    const float* pA = xo + (size_t)(m0 + m) * 768 + h4;
    int kkB = t >> 5, c4 = (t & 31) * 4;
    int m_base = (t >> 4) * 8, n_base = (t & 15) * 8;

    float acc[8][8];
    #pragma unroll
    for (int a = 0; a < 8; a++)
        #pragma unroll
        for (int bq = 0; bq < 8; bq++) acc[a][bq] = 0.f;

    for (int k0 = 0; k0 < 768; k0 += 8) {
        float4 av = *(const float4*)(pA + k0);
        float4 bv = *(const float4*)(Bbase + (size_t)(k0 + kkB) * HT + c4);
        __syncthreads();
        As[h4 + 0][m] = av.x; As[h4 + 1][m] = av.y;
        As[h4 + 2][m] = av.z; As[h4 + 3][m] = av.w;
        *(float4*)&Bs[kkB][c4] = bv;
        __syncthreads();
        #pragma unroll
        for (int kk = 0; kk < 8; kk++) {
            float a[8], bb[8];
            *(float4*)(a)     = *(const float4*)&As[kk][m_base];
            *(float4*)(a + 4) = *(const float4*)&As[kk][m_base + 4];
            *(float4*)(bb)     = *(const float4*)&Bs[kk][n_base];
            *(float4*)(bb + 4) = *(const float4*)&Bs[kk][n_base + 4];
            #pragma unroll
            for (int mi = 0; mi < 8; mi++)
                #pragma unroll
                for (int ni = 0; ni < 8; ni++)
                    acc[mi][ni] += a[mi] * bb[ni];
        }
    }
    float* Obase = isU ? g_U : g_V;
    int c0 = isU ? ng0 : ng0 - HT;
    #pragma unroll
    for (int mi = 0; mi < 8; mi++) {
        float* prow = Obase + (size_t)(m0 + m_base + mi) * HT + c0 + n_base;
        *(float4*)(prow)     = make_float4(acc[mi][0], acc[mi][1], acc[mi][2], acc[mi][3]);
        *(float4*)(prow + 4) = make_float4(acc[mi][4], acc[mi][5], acc[mi][6], acc[mi][7]);
    }
}

// ---------------- kernel 4: BN stats partials -------------------------------
__global__ void k_stats(const float* __restrict__ adjs, const float* __restrict__ flags,
                        const float* __restrict__ W1t) {
    int bi = blockIdx.x;
    int b = bi >> 6, i = bi & 63;
    int t = threadIdx.x;
    __shared__ float Ur[HT];
    __shared__ float a0s[64], a1s[64];
    for (int k = t; k < HT; k += 256) Ur[k] = g_U[(size_t)bi * HT + k];
    if (t < 64) {
        int j = t;
        float m = flags[b * 64 + i] * flags[b * 64 + j];
        float a = adjs[(size_t)bi * 64 + j];
        a0s[j] = a * m;
        a1s[j] = (1.f - a) * m;
    }
    __syncthreads();
    float w0[6], w1[6], u[6], sum[6], sq[6];
    #pragma unroll
    for (int s = 0; s < 6; s++) {
        int k = t + s * 256;
        w0[s] = W1t[k];
        w1[s] = W1t[HT + k];
        u[s] = Ur[k];
        sum[s] = 0.f; sq[s] = 0.f;
    }
    const float* Vb = g_V + (size_t)(b * 64) * HT;
    for (int j = 0; j < 64; j++) {
        float a0 = a0s[j], a1 = a1s[j];
        const float* Vr = Vb + (size_t)j * HT;
        #pragma unroll
        for (int s = 0; s < 6; s++) {
            float z = u[s] + Vr[t + s * 256] + a0 * w0[s] + a1 * w1[s];
            sum[s] += z;
            sq[s] += z * z;
        }
    }
    #pragma unroll
    for (int s = 0; s < 6; s++) {
        g_part[(size_t)bi * 3072 + t + s * 256] = sum[s];
        g_part[(size_t)bi * 3072 + HT + t + s * 256] = sq[s];
    }
}

// ---------------- kernel 5: finalize BN constants ---------------------------
__global__ void k_stats2(const float* __restrict__ b1t, const float* __restrict__ gamma,
                         const float* __restrict__ beta) {
    int k = blockIdx.x * 256 + threadIdx.x;
    float s = 0.f, q = 0.f;
    for (int bi = 0; bi < NROW; bi++) {
        s += g_part[(size_t)bi * 3072 + k];
        q += g_part[(size_t)bi * 3072 + HT + k];
    }
    const float inv = 1.f / 65536.f;
    float mu_z = s * inv;
    float var = fmaxf(q * inv - mu_z * mu_z, 0.f);
    float mu = mu_z + b1t[k];
    float c1 = gamma[k] * rsqrtf(var + 1e-5f);
    g_c1[k] = c1;
    g_c2[k] = beta[k] - mu * c1;
}

// ---------------- kernel 6: mma.sync bf16-split translate GEMM --------------
#define GM_A0S  0
#define GM_A1S  512
#define GM_AH   1024
#define GM_AL   11264
#define GM_BH   21504
#define GM_BL   41984
#define GM_SMEM 62464
#define KPAD    80   // bytes per k-row (40 bf16)

__global__ void __launch_bounds__(512, 1)
k_gemm2_mma(const float* __restrict__ adjs, const float* __restrict__ flags,
            const float* __restrict__ W1t, const float* __restrict__ W2t,
            const float* __restrict__ b2t) {
    extern __shared__ char sm[];
    float* a0s = (float*)(sm + GM_A0S);
    float* a1s = (float*)(sm + GM_A1S);
    int t = threadIdx.x;
    int m0 = blockIdx.y * 128, n0g = blockIdx.x * 256;
    int b = m0 >> 12;

    if (t < 128) {
        int e = m0 + t, i = (e >> 6) & 63, j = e & 63;
        float mk = flags[b * 64 + i] * flags[b * 64 + j];
        float a = adjs[(size_t)b * 4096 + i * 64 + j];
        a0s[t] = a * mk;
        a1s[t] = (1.f - a) * mk;
    }
    __syncthreads();

    int mrow = t >> 2, kq = (t & 3) * 8;
    int e = m0 + mrow, im = (e >> 6) & 63, jm = e & 63;
    const float* pU = g_U + (size_t)(b * 64 + im) * HT;
    const float* pV = g_V + (size_t)(b * 64 + jm) * HT;
    float a0 = a0s[mrow], a1 = a1s[mrow];

    int wid = t >> 5, lane = t & 31;
    int mw = (wid & 1) * 64, nw = (wid >> 1) * 32;
    int row4 = lane >> 2, quad = lane & 3;

    float acc[4][4][4];
    #pragma unroll
    for (int tm = 0; tm < 4; tm++)
        #pragma unroll
        for (int tn = 0; tn < 4; tn++)
            #pragma unroll
            for (int q = 0; q < 4; q++) acc[tm][tn][q] = 0.f;

    for (int c = 0; c < 48; c++) {
        int k0 = c * 32;
        if (c) __syncthreads();
        #pragma unroll
        for (int h = 0; h < 2; h++) {
            int kl = kq + h * 4, k = k0 + kl;
            float4 u  = *(const float4*)(pU + k);
            float4 v  = *(const float4*)(pV + k);
            float4 w0 = __ldg((const float4*)(W1t + k));
            float4 w1 = __ldg((const float4*)(W1t + HT + k));
            float4 c1 = *(const float4*)(g_c1 + k);
            float4 c2 = *(const float4*)(g_c2 + k);
            float z0 = elu_f((u.x + v.x + a0 * w0.x + a1 * w1.x) * c1.x + c2.x);
            float z1 = elu_f((u.y + v.y + a0 * w0.y + a1 * w1.y) * c1.y + c2.y);
            float z2 = elu_f((u.z + v.z + a0 * w0.z + a1 * w1.z) * c1.z + c2.z);
            float z3 = elu_f((u.w + v.w + a0 * w0.w + a1 * w1.w) * c1.w + c2.w);
            float r0 = z0 - __bfloat162float(__float2bfloat16(z0));
            float r1 = z1 - __bfloat162float(__float2bfloat16(z1));
            float r2 = z2 - __bfloat162float(__float2bfloat16(z2));
            float r3 = z3 - __bfloat162float(__float2bfloat16(z3));
            int off = mrow * KPAD + kl * 2;
            *(uint2*)(sm + GM_AH + off) = make_uint2(pack2(z0, z1), pack2(z2, z3));
            *(uint2*)(sm + GM_AL + off) = make_uint2(pack2(r0, r1), pack2(r2, r3));
        }
        #pragma unroll
        for (int it = 0; it < 4; it++) {
            int idx = t + it * 512;
            int n = idx & 255, kk = (idx >> 8) * 4;
            const float* pw = W2t + (size_t)(k0 + kk) * 768 + n0g + n;
            float w0v = __ldg(pw), w1v = __ldg(pw + 768),
                  w2v = __ldg(pw + 1536), w3v = __ldg(pw + 2304);
            float r0 = w0v - __bfloat162float(__float2bfloat16(w0v));
            float r1 = w1v - __bfloat162float(__float2bfloat16(w1v));
            float r2 = w2v - __bfloat162float(__float2bfloat16(w2v));
            float r3 = w3v - __bfloat162float(__float2bfloat16(w3v));
            int off = n * KPAD + kk * 2;
            *(uint2*)(sm + GM_BH + off) = make_uint2(pack2(w0v, w1v), pack2(w2v, w3v));
            *(uint2*)(sm + GM_BL + off) = make_uint2(pack2(r0, r1), pack2(r2, r3));
        }
        __syncthreads();
        #pragma unroll
        for (int ks = 0; ks < 2; ks++) {
            int kb = ks * 32 + quad * 4;
            uint32_t af[4][4], bf[4][2];
            #pragma unroll
            for (int tm = 0; tm < 4; tm++) {
                int base = GM_AH + (mw + tm * 16 + row4) * KPAD + kb;
                af[tm][0] = *(const uint32_t*)(sm + base);
                af[tm][1] = *(const uint32_t*)(sm + base + 8 * KPAD);
                af[tm][2] = *(const uint32_t*)(sm + base + 16);
                af[tm][3] = *(const uint32_t*)(sm + base + 8 * KPAD + 16);
            }
            #pragma unroll
            for (int tn = 0; tn < 4; tn++) {
                int base = GM_BH + (nw + tn * 8 + row4) * KPAD + kb;
                bf[tn][0] = *(const uint32_t*)(sm + base);
                bf[tn][1] = *(const uint32_t*)(sm + base + 16);
            }
            #pragma unroll
            for (int tm = 0; tm < 4; tm++)
                #pragma unroll
                for (int tn = 0; tn < 4; tn++)
                    mma16816(acc[tm][tn], af[tm], bf[tn]);
            #pragma unroll
            for (int tn = 0; tn < 4; tn++) {
                int base = GM_BL + (nw + tn * 8 + row4) * KPAD + kb;
                bf[tn][0] = *(const uint32_t*)(sm + base);
                bf[tn][1] = *(const uint32_t*)(sm + base + 16);
            }
            #pragma unroll
            for (int tm = 0; tm < 4; tm++)
                #pragma unroll
                for (int tn = 0; tn < 4; tn++)
                    mma16816(acc[tm][tn], af[tm], bf[tn]);
            #pragma unroll
            for (int tm = 0; tm < 4; tm++) {
                int base = GM_AL + (mw + tm * 16 + row4) * KPAD + kb;
                af[tm][0] = *(const uint32_t*)(sm + base);
                af[tm][1] = *(const uint32_t*)(sm + base + 8 * KPAD);
                af[tm][2] = *(const uint32_t*)(sm + base + 16);
                af[tm][3] = *(const uint32_t*)(sm + base + 8 * KPAD + 16);
            }
            #pragma unroll
            for (int tn = 0; tn < 4; tn++) {
                int base = GM_BH + (nw + tn * 8 + row4) * KPAD + kb;
                bf[tn][0] = *(const uint32_t*)(sm + base);
                bf[tn][1] = *(const uint32_t*)(sm + base + 16);
            }
            #pragma unroll
            for (int tm = 0; tm < 4; tm++)
                #pragma unroll
                for (int tn = 0; tn < 4; tn++)
                    mma16816(acc[tm][tn], af[tm], bf[tn]);
        }
    }

    #pragma unroll
    for (int tm = 0; tm < 4; tm++) {
        int gr = m0 + mw + tm * 16 + row4;
        #pragma unroll
        for (int tn = 0; tn < 4; tn++) {
            int gc = n0g + nw + tn * 8 + quad * 2;
            float bx = __ldg(b2t + gc), by = __ldg(b2t + gc + 1);
            float* p0 = g_na + (size_t)gr * 768 + gc;
            float* p1 = g_na + (size_t)(gr + 8) * 768 + gc;
            *(float2*)p0 = make_float2(acc[tm][tn][0] + bx, acc[tm][tn][1] + by);
            *(float2*)p1 = make_float2(acc[tm][tn][2] + bx, acc[tm][tn][3] + by);
        }
    }
}

// ---------------- kernel 6b: symmetrize new_adjs -> bf16 hi/lo --------------
__global__ void k_sym(const float* __restrict__ flags) {
    int e = blockIdx.x;
    int b = e >> 12, i = (e >> 6) & 63, j = e & 63;
    float mk = flags[b * 64 + i] * flags[b * 64 + j];
    int eji = (b << 12) | (j << 6) | i;
    int t = threadIdx.x;  // 192 threads * 4 floats = 768
    float4 u = *(const float4*)(g_na + (size_t)e * 768 + t * 4);
    float4 v = *(const float4*)(g_na + (size_t)eji * 768 + t * 4);
    float s0 = (u.x + v.x) * mk, s1 = (u.y + v.y) * mk;
    float s2 = (u.z + v.z) * mk, s3 = (u.w + v.w) * mk;
    float r0 = s0 - __bfloat162float(__float2bfloat16(s0));
    float r1 = s1 - __bfloat162float(__float2bfloat16(s1));
    float r2 = s2 - __bfloat162float(__float2bfloat16(s2));
    float r3 = s3 - __bfloat162float(__float2bfloat16(s3));
    *(uint2*)(g_sh + (size_t)e * 768 + t * 4) = make_uint2(pack2(s0, s1), pack2(s2, s3));
    *(uint2*)(g_sl + (size_t)e * 768 + t * 4) = make_uint2(pack2(r0, r1), pack2(r2, r3));
}

// ---------------- kernel 7: mma.sync final_read_score -----------------------
// score[e] = sum_n elu( b1r[n] + a0*W1r[0,n] + a1*W1r[1,n] + S[e,:]@W1r[2:,n] ) * W2r[n]
// S = (na_ij + na_ji)*mask, precomputed bf16 hi/lo in g_sh/g_sl.
// CTA: 128 edges, 512 threads, 16 warps (2M x 8N); 7 passes of 256 n-cols.
#define KS_A0S  0
#define KS_A1S  512
#define KS_AH   1024
#define KS_AL   11264
#define KS_BH   21504
#define KS_BL   41984
#define KS_RED  62464
#define KS_SMEM 66560

__global__ void __launch_bounds__(512, 1)
k_score_mma(const float* __restrict__ adjs, const float* __restrict__ flags,
            const float* __restrict__ W1r, const float* __restrict__ b1r,
            const float* __restrict__ W2r, const float* __restrict__ b2r,
            float* __restrict__ out_score) {
    extern __shared__ char sm[];
    float* a0s = (float*)(sm + KS_A0S);
    float* a1s = (float*)(sm + KS_A1S);
    float* red = (float*)(sm + KS_RED);
    int t = threadIdx.x;
    int m0 = blockIdx.x * 128;
    int b = m0 >> 12;

    if (t < 128) {
        int e = m0 + t, i = (e >> 6) & 63, j = e & 63;
        float mk = flags[b * 64 + i] * flags[b * 64 + j];
        float a = adjs[(size_t)b * 4096 + i * 64 + j];
        a0s[t] = a * mk;
        a1s[t] = (1.f - a) * mk;
    }
    __syncthreads();

    int wid = t >> 5, lane = t & 31;
    int mw = (wid & 1) * 64, nw = (wid >> 1) * 32;
    int row4 = lane >> 2, quad = lane & 3;

    int mrow = t >> 2, kq8 = (t & 3) * 8;
    const __nv_bfloat16* pSH = g_sh + (size_t)(m0 + mrow) * 768 + kq8;
    const __nv_bfloat16* pSL = g_sl + (size_t)(m0 + mrow) * 768 + kq8;

    float score[4][2];
    #pragma unroll
    for (int tm = 0; tm < 4; tm++) { score[tm][0] = 0.f; score[tm][1] = 0.f; }

    for (int nc = 0; nc < 7; nc++) {
        int n0 = nc * 256;
        float acc[4][4][4];
        #pragma unroll
        for (int tm = 0; tm < 4; tm++) {
            int r0 = mw + tm * 16 + row4;
            float a0A = a0s[r0], a1A = a1s[r0];
            float a0B = a0s[r0 + 8], a1B = a1s[r0 + 8];
            #pragma unroll
            for (int tn = 0; tn < 4; tn++) {
                #pragma unroll
                for (int cq = 0; cq < 2; cq++) {
                    int n = n0 + nw + tn * 8 + quad * 2 + cq;
                    bool ok = n < HR;
                    float br = ok ? __ldg(b1r + n) : 0.f;
                    float w0 = ok ? __ldg(W1r + n) : 0.f;
                    float w1 = ok ? __ldg(W1r + HR + n) : 0.f;
                    acc[tm][tn][cq]     = br + a0A * w0 + a1A * w1;
                    acc[tm][tn][2 + cq] = br + a0B * w0 + a1B * w1;
                }
            }
        }
        for (int c = 0; c < 24; c++) {
            int k0 = c * 32;
            __syncthreads();
            *(uint4*)(sm + KS_AH + mrow * KPAD + kq8 * 2) = *(const uint4*)(pSH + k0);
            *(uint4*)(sm + KS_AL + mrow * KPAD + kq8 * 2) = *(const uint4*)(pSL + k0);
            #pragma unroll
            for (int it = 0; it < 4; it++) {
                int idx = t + it * 512;
                int n = idx & 255, kk = (idx >> 8) * 4;
                int ncol = n0 + n;
                bool ok = ncol < HR;
                const float* pw = W1r + (size_t)(2 + k0 + kk) * HR + ncol;
                float w0v = ok ? __ldg(pw) : 0.f;
                float w1v = ok ? __ldg(pw + HR) : 0.f;
                float w2v = ok ? __ldg(pw + 2 * HR) : 0.f;
                float w3v = ok ? __ldg(pw + 3 * HR) : 0.f;
                float r0 = w0v - __bfloat162float(__float2bfloat16(w0v));
                float r1 = w1v - __bfloat162float(__float2bfloat16(w1v));
                float r2 = w2v - __bfloat162float(__float2bfloat16(w2v));
                float r3 = w3v - __bfloat162float(__float2bfloat16(w3v));
                int off = n * KPAD + kk * 2;
                *(uint2*)(sm + KS_BH + off) = make_uint2(pack2(w0v, w1v), pack2(w2v, w3v));
                *(uint2*)(sm + KS_BL + off) = make_uint2(pack2(r0, r1), pack2(r2, r3));
            }
            __syncthreads();
            #pragma unroll
            for (int ks = 0; ks < 2; ks++) {
                int kb = ks * 32 + quad * 4;
                uint32_t af[4][4], bf[4][2];
                #pragma unroll
                for (int tm = 0; tm < 4; tm++) {
                    int base = KS_AH + (mw + tm * 16 + row4) * KPAD + kb;
                    af[tm][0] = *(const uint32_t*)(sm + base);
                    af[tm][1] = *(const uint32_t*)(sm + base + 8 * KPAD);
                    af[tm][2] = *(const uint32_t*)(sm + base + 16);
                    af[tm][3] = *(const uint32_t*)(sm + base + 8 * KPAD + 16);
                }
                #pragma unroll
                for (int tn = 0; tn < 4; tn++) {
                    int base = KS_BH + (nw + tn * 8 + row4) * KPAD + kb;
                    bf[tn][0] = *(const uint32_t*)(sm + base);
                    bf[tn][1] = *(const uint32_t*)(sm + base + 16);
                }
                #pragma unroll
                for (int tm = 0; tm < 4; tm++)
                    #pragma unroll
                    for (int tn = 0; tn < 4; tn++)
                        mma16816(acc[tm][tn], af[tm], bf[tn]);
                #pragma unroll
                for (int tn = 0; tn < 4; tn++) {
                    int base = KS_BL + (nw + tn * 8 + row4) * KPAD + kb;
                    bf[tn][0] = *(const uint32_t*)(sm + base);
                    bf[tn][1] = *(const uint32_t*)(sm + base + 16);
                }
                #pragma unroll
                for (int tm = 0; tm < 4; tm++)
                    #pragma unroll
                    for (int tn = 0; tn < 4; tn++)
                        mma16816(acc[tm][tn], af[tm], bf[tn]);
                #pragma unroll
                for (int tm = 0; tm < 4; tm++) {
                    int base = KS_AL + (mw + tm * 16 + row4) * KPAD + kb;
                    af[tm][0] = *(const uint32_t*)(sm + base);
                    af[tm][1] = *(const uint32_t*)(sm + base + 8 * KPAD);
                    af[tm][2] = *(const uint32_t*)(sm + base + 16);
                    af[tm][3] = *(const uint32_t*)(sm + base + 8 * KPAD + 16);
                }
                #pragma unroll
                for (int tn = 0; tn < 4; tn++) {
                    int base = KS_BH + (nw + tn * 8 + row4) * KPAD + kb;
                    bf[tn][0] = *(const uint32_t*)(sm + base);
                    bf[tn][1] = *(const uint32_t*)(sm + base + 16);
                }
                #pragma unroll
                for (int tm = 0; tm < 4; tm++)
                    #pragma unroll
                    for (int tn = 0; tn < 4; tn++)
                        mma16816(acc[tm][tn], af[tm], bf[tn]);
            }
        }
        // accumulate score for this n-chunk
        #pragma unroll
        for (int tn = 0; tn < 4; tn++) {
            #pragma unroll
            for (int cq = 0; cq < 2; cq++) {
                int n = n0 + nw + tn * 8 + quad * 2 + cq;
                float w2 = (n < HR) ? __ldg(W2r + n) : 0.f;
                #pragma unroll
                for (int tm = 0; tm < 4; tm++) {
                    score[tm][0] += elu_f(acc[tm][tn][cq]) * w2;
                    score[tm][1] += elu_f(acc[tm][tn][2 + cq]) * w2;
                }
            }
        }
    }
    // reduce over quad lanes
    #pragma unroll
    for (int off = 1; off <= 2; off <<= 1)
        #pragma unroll
        for (int tm = 0; tm < 4; tm++) {
            score[tm][0] += __shfl_xor_sync(0xffffffffu, score[tm][0], off);
            score[tm][1] += __shfl_xor_sync(0xffffffffu, score[tm][1], off);
        }
    __syncthreads();
    if (quad == 0) {
        int wn = wid >> 1;
        #pragma unroll
        for (int tm = 0; tm < 4; tm++) {
            int r0 = mw + tm * 16 + row4;
            red[r0 * 8 + wn] = score[tm][0];
            red[(r0 + 8) * 8 + wn] = score[tm][1];
        }
    }
    __syncthreads();
    if (t < 128) {
        float s = 0.f;
        #pragma unroll
        for (int w8 = 0; w8 < 8; w8++) s += red[t * 8 + w8];
        int e = m0 + t, i = (e >> 6) & 63, j = e & 63;
        out_score[e] = (i == j) ? 0.f : (s + b2r[0]);
    }
}

// ---------------- launch -----------------------------------------------------
extern "C" void kernel_launch(void* const* d_in, const int* in_sizes, int n_in,
                              void* d_out, int out_size) {
    const float* x     = (const float*)d_in[0];
    const float* adjs  = (const float*)d_in[1];
    const float* flags = (const float*)d_in[2];
    const float* Wg    = (const float*)d_in[3];
    const float* bg    = (const float*)d_in[4];
    const float* Wout  = (const float*)d_in[5];
    const float* bout  = (const float*)d_in[6];
    const float* W1t   = (const float*)d_in[7];
    const float* b1t   = (const float*)d_in[8];
    const float* gamma = (const float*)d_in[9];
    const float* beta  = (const float*)d_in[10];
    const float* W2t   = (const float*)d_in[11];
    const float* b2t   = (const float*)d_in[12];
    const float* W1r   = (const float*)d_in[13];
    const float* b1r   = (const float*)d_in[14];
    const float* W2r   = (const float*)d_in[15];
    const float* b2r   = (const float*)d_in[16];

    float* out_score = (float*)d_out;             // [B,N,N] = 65536
    float* out_xo    = (float*)d_out + NEDGE;     // [B,N,768]

    cudaFuncSetAttribute(k_gemm2_mma, cudaFuncAttributeMaxDynamicSharedMemorySize, GM_SMEM);
    cudaFuncSetAttribute(k_score_mma, cudaFuncAttributeMaxDynamicSharedMemorySize, KS_SMEM);

    k_agg<<<NROW, 128>>>(x, adjs, flags);
    k_gin<<<NROW / 8, 256>>>(x, flags, Wg, bg, Wout, bout, out_xo);
    k_uv<<<dim3(24, 8), 256>>>(out_xo, W1t);
    k_stats<<<NROW, 256>>>(adjs, flags, W1t);
    k_stats2<<<6, 256>>>(b1t, gamma, beta);
    k_gemm2_mma<<<dim3(3, 512), 512, GM_SMEM>>>(adjs, flags, W1t, W2t, b2t);
    k_sym<<<NEDGE, 192>>>(flags);
    k_score_mma<<<512, 512, KS_SMEM>>>(adjs, flags, W1r, b1r, W2r, b2r, out_score);
}

// round 9
// speedup vs baseline: 2.0777x; 1.0147x over previous
#include <cuda_runtime.h>
#include <cuda_bf16.h>
#include <stdint.h>
#include <cstdint>
#include <math.h>

// Problem constants
#define BB      16
#define NNODE   64
#define FIN     128
#define FHID    256
#define ODIM    768
#define HT      1536   // translate hidden
#define DR      770
#define HR      1540
#define NEDGE   65536  // B*N*N
#define NROW    1024   // B*N

// ---------------- scratch (device globals; no runtime allocation) ----------
__device__ float g_agg[NROW * 256];          // GIN aggregated features [B*N, 2*FIN]
__device__ float g_U[NROW * HT];             // xo @ W1t[2:770]
__device__ float g_V[NROW * HT];             // xo @ W1t[770:1538]
__device__ float g_na[(size_t)NEDGE * ODIM]; // new_adjs pre-symmetrize [e, f]  (201 MB)
__device__ __align__(16) __nv_bfloat16 g_ah[(size_t)NEDGE * HT];   // A hi (201 MB)
__device__ __align__(16) __nv_bfloat16 g_al[(size_t)NEDGE * HT];   // A lo (201 MB)
__device__ __align__(16) __nv_bfloat16 g_sh[(size_t)NEDGE * ODIM]; // sym hi (100 MB)
__device__ __align__(16) __nv_bfloat16 g_sl[(size_t)NEDGE * ODIM]; // sym lo (100 MB)
__device__ float g_part[NROW * 2 * HT];      // per-(b,i) BN partial sums
__device__ __align__(16) float g_c1[HT];     // folded BN scale
__device__ __align__(16) float g_c2[HT];     // folded BN shift

__device__ __forceinline__ float elu_f(float x) {
    return x > 0.f ? x : (__expf(x) - 1.f);
}
static __device__ __forceinline__ uint32_t pack2(float a, float b) {
    __nv_bfloat162 h = __floats2bfloat162_rn(a, b);
    return *reinterpret_cast<uint32_t*>(&h);
}
// mma.sync m16n8k16 row.col f32.bf16.bf16.f32 (portable PTX, HMMA on sm_103)
static __device__ __forceinline__ void mma16816(float* c, const uint32_t* a,
                                                const uint32_t* b) {
    asm volatile(
        "mma.sync.aligned.m16n8k16.row.col.f32.bf16.bf16.f32 "
        "{%0,%1,%2,%3}, {%4,%5,%6,%7}, {%8,%9}, {%0,%1,%2,%3};"
        : "+f"(c[0]), "+f"(c[1]), "+f"(c[2]), "+f"(c[3])
        : "r"(a[0]), "r"(a[1]), "r"(a[2]), "r"(a[3]), "r"(b[0]), "r"(b[1]));
}

// ---------------- kernel 1: agg[b,i,c,f] = sum_j A_c[b,i,j] * x[b,j,f] ------
__global__ void k_agg(const float* __restrict__ x, const float* __restrict__ adjs,
                      const float* __restrict__ flags) {
    int bi = blockIdx.x;
    int b = bi >> 6, i = bi & 63;
    int f = threadIdx.x;
    __shared__ float a0s[64], a1s[64];
    float fi = flags[b * 64 + i];
    if (threadIdx.x < 64) {
        int j = threadIdx.x;
        float fj = flags[b * 64 + j];
        float a = adjs[(size_t)bi * 64 + j];
        float m = fi * fj;
        a0s[j] = a * m;
        a1s[j] = (1.f - a) * m;
    }
    __syncthreads();
    float s0 = 0.f, s1 = 0.f;
    const float* xb = x + (size_t)b * NNODE * FIN;
    #pragma unroll 4
    for (int j = 0; j < 64; j++) {
        float xv = xb[j * FIN + f];
        s0 += a0s[j] * xv;
        s1 += a1s[j] * xv;
    }
    g_agg[bi * 256 + f] = s0;
    g_agg[bi * 256 + 128 + f] = s1;
}

// ---------------- kernel 2: GIN MLPs -> x_o ---------------------------------
__global__ void k_gin(const float* __restrict__ x, const float* __restrict__ flags,
                      const float* __restrict__ Wg, const float* __restrict__ bg,
                      const float* __restrict__ Wout, const float* __restrict__ bout,
                      float* __restrict__ out_xo) {
    __shared__ float aggs[8][256];
    __shared__ float xs[8][128];
    __shared__ float hs[8][256];
    __shared__ float fl[8];
    int r0 = blockIdx.x * 8;
    int t = threadIdx.x;
    for (int idx = t; idx < 8 * 256; idx += 256)
        aggs[idx >> 8][idx & 255] = g_agg[r0 * 256 + idx];
    for (int idx = t; idx < 8 * 128; idx += 256)
        xs[idx >> 7][idx & 127] = x[(size_t)r0 * 128 + idx];
    if (t < 8) fl[t] = flags[r0 + t];
    __syncthreads();
    {
        float acc[8];
        float bgv = bg[t];
        #pragma unroll
        for (int r = 0; r < 8; r++) acc[r] = bgv;
        for (int k = 0; k < 256; k++) {
            float w = Wg[k * 256 + t];
            #pragma unroll
            for (int r = 0; r < 8; r++) acc[r] += aggs[r][k] * w;
        }
        #pragma unroll
        for (int r = 0; r < 8; r++) hs[r][t] = elu_f(acc[r]) * fl[r];
    }
    __syncthreads();
    float acc[3][8];
    #pragma unroll
    for (int c = 0; c < 3; c++) {
        float bo = bout[t + c * 256];
        #pragma unroll
        for (int r = 0; r < 8; r++) acc[c][r] = bo;
    }
    for (int k = 0; k < 128; k++) {
        float o[8];
        #pragma unroll
        for (int r = 0; r < 8; r++) o[r] = xs[r][k];
        #pragma unroll
        for (int c = 0; c < 3; c++) {
            float w = Wout[k * 768 + t + c * 256];
            #pragma unroll
            for (int r = 0; r < 8; r++) acc[c][r] += o[r] * w;
        }
    }
    for (int k = 0; k < 256; k++) {
        float o[8];
        #pragma unroll
        for (int r = 0; r < 8; r++) o[r] = hs[r][k];
        #pragma unroll
        for (int c = 0; c < 3; c++) {
            float w = Wout[(128 + k) * 768 + t + c * 256];
            #pragma unroll
            for (int r = 0; r < 8; r++) acc[c][r] += o[r] * w;
        }
    }
    #pragma unroll
    for (int c = 0; c < 3; c++)
        #pragma unroll
        for (int r = 0; r < 8; r++)
            out_xo[(size_t)(r0 + r) * 768 + t + c * 256] = tanhf(acc[c][r]) * fl[r];
}

// ---------------- kernel 3: U,V = xo @ W1t[2:770], xo @ W1t[770:1538] -------
__global__ void k_uv(const float* __restrict__ xo, const float* __restrict__ W1t) {
    __shared__ float As[8][128];
    __shared__ float Bs[8][128];
    int t = threadIdx.x;
    int m0 = blockIdx.y * 128;
    int ng0 = blockIdx.x * 128;
    const int isU = (ng0 < HT);
    const float* Bbase = W1t + (size_t)(isU ? 2 : 770) * HT + (isU ? ng0 : ng0 - HT);
    int m = t >> 1, h4 = (t & 1) * 4;
    const float* pA = xo + (size_t)(m0 + m) * 768 + h4;
    int kkB = t >> 5, c4 = (t & 31) * 4;
    int m_base = (t >> 4) * 8, n_base = (t & 15) * 8;

    float acc[8][8];
    #pragma unroll
    for (int a = 0; a < 8; a++)
        #pragma unroll
        for (int bq = 0; bq < 8; bq++) acc[a][bq] = 0.f;

    for (int k0 = 0; k0 < 768; k0 += 8) {
        float4 av = *(const float4*)(pA + k0);
        float4 bv = *(const float4*)(Bbase + (size_t)(k0 + kkB) * HT + c4);
        __syncthreads();
        As[h4 + 0][m] = av.x; As[h4 + 1][m] = av.y;
        As[h4 + 2][m] = av.z; As[h4 + 3][m] = av.w;
        *(float4*)&Bs[kkB][c4] = bv;
        __syncthreads();
        #pragma unroll
        for (int kk = 0; kk < 8; kk++) {
            float a[8], bb[8];
            *(float4*)(a)     = *(const float4*)&As[kk][m_base];
            *(float4*)(a + 4) = *(const float4*)&As[kk][m_base + 4];
            *(float4*)(bb)     = *(const float4*)&Bs[kk][n_base];
            *(float4*)(bb + 4) = *(const float4*)&Bs[kk][n_base + 4];
            #pragma unroll
            for (int mi = 0; mi < 8; mi++)
                #pragma unroll
                for (int ni = 0; ni < 8; ni++)
                    acc[mi][ni] += a[mi] * bb[ni];
        }
    }
    float* Obase = isU ? g_U : g_V;
    int c0 = isU ? ng0 : ng0 - HT;
    #pragma unroll
    for (int mi = 0; mi < 8; mi++) {
        float* prow = Obase + (size_t)(m0 + m_base + mi) * HT + c0 + n_base;
        *(float4*)(prow)     = make_float4(acc[mi][0], acc[mi][1], acc[mi][2], acc[mi][3]);
        *(float4*)(prow + 4) = make_float4(acc[mi][4], acc[mi][5], acc[mi][6], acc[mi][7]);
    }
}

// ---------------- kernel 4: BN stats partials -------------------------------
__global__ void k_stats(const float* __restrict__ adjs, const float* __restrict__ flags,
                        const float* __restrict__ W1t) {
    int bi = blockIdx.x;
    int b = bi >> 6, i = bi & 63;
    int t = threadIdx.x;
    __shared__ float Ur[HT];
    __shared__ float a0s[64], a1s[64];
    for (int k = t; k < HT; k += 256) Ur[k] = g_U[(size_t)bi * HT + k];
    if (t < 64) {
        int j = t;
        float m = flags[b * 64 + i] * flags[b * 64 + j];
        float a = adjs[(size_t)bi * 64 + j];
        a0s[j] = a * m;
        a1s[j] = (1.f - a) * m;
    }
    __syncthreads();
    float w0[6], w1[6], u[6], sum[6], sq[6];
    #pragma unroll
    for (int s = 0; s < 6; s++) {
        int k = t + s * 256;
        w0[s] = W1t[k];
        w1[s] = W1t[HT + k];
        u[s] = Ur[k];
        sum[s] = 0.f; sq[s] = 0.f;
    }
    const float* Vb = g_V + (size_t)(b * 64) * HT;
    for (int j = 0; j < 64; j++) {
        float a0 = a0s[j], a1 = a1s[j];
        const float* Vr = Vb + (size_t)j * HT;
        #pragma unroll
        for (int s = 0; s < 6; s++) {
            float z = u[s] + Vr[t + s * 256] + a0 * w0[s] + a1 * w1[s];
            sum[s] += z;
            sq[s] += z * z;
        }
    }
    #pragma unroll
    for (int s = 0; s < 6; s++) {
        g_part[(size_t)bi * 3072 + t + s * 256] = sum[s];
        g_part[(size_t)bi * 3072 + HT + t + s * 256] = sq[s];
    }
}

// ---------------- kernel 5: finalize BN constants ---------------------------
__global__ void k_stats2(const float* __restrict__ b1t, const float* __restrict__ gamma,
                         const float* __restrict__ beta) {
    int k = blockIdx.x * 256 + threadIdx.x;
    float s = 0.f, q = 0.f;
    for (int bi = 0; bi < NROW; bi++) {
        s += g_part[(size_t)bi * 3072 + k];
        q += g_part[(size_t)bi * 3072 + HT + k];
    }
    const float inv = 1.f / 65536.f;
    float mu_z = s * inv;
    float var = fmaxf(q * inv - mu_z * mu_z, 0.f);
    float mu = mu_z + b1t[k];
    float c1 = gamma[k] * rsqrtf(var + 1e-5f);
    g_c1[k] = c1;
    g_c2[k] = beta[k] - mu * c1;
}

// ---------------- kernel 5b: materialize A = elu(BN(h1)) as bf16 hi/lo -----
// One block per (b,i); 64 edges x 1536 cols. U row in SMEM; V rows via L2.
__global__ void k_agen(const float* __restrict__ adjs, const float* __restrict__ flags,
                       const float* __restrict__ W1t) {
    int bi = blockIdx.x;
    int b = bi >> 6, i = bi & 63;
    int t = threadIdx.x;  // 256
    __shared__ float Ur[HT];
    __shared__ float a0s[64], a1s[64];
    for (int k = t; k < HT; k += 256) Ur[k] = g_U[(size_t)bi * HT + k];
    if (t < 64) {
        float m = flags[b * 64 + i] * flags[b * 64 + t];
        float a = adjs[(size_t)bi * 64 + t];
        a0s[t] = a * m;
        a1s[t] = (1.f - a) * m;
    }
    __syncthreads();
    // 3 column-pairs per thread: k2 = 2t + s*512
    float2 w0[3], w1[3], u[3], c1v[3], c2v[3];
    #pragma unroll
    for (int s = 0; s < 3; s++) {
        int k2 = 2 * t + s * 512;
        w0[s]  = *(const float2*)(W1t + k2);
        w1[s]  = *(const float2*)(W1t + HT + k2);
        u[s]   = *(const float2*)(Ur + k2);
        c1v[s] = *(const float2*)(g_c1 + k2);
        c2v[s] = *(const float2*)(g_c2 + k2);
    }
    for (int j = 0; j < 64; j++) {
        float a0 = a0s[j], a1 = a1s[j];
        const float* Vr = g_V + (size_t)(b * 64 + j) * HT;
        size_t erow = (size_t)(bi * 64 + j) * HT;
        #pragma unroll
        for (int s = 0; s < 3; s++) {
            int k2 = 2 * t + s * 512;
            float2 v = *(const float2*)(Vr + k2);
            float z0 = elu_f((u[s].x + v.x + a0 * w0[s].x + a1 * w1[s].x) * c1v[s].x + c2v[s].x);
            float z1 = elu_f((u[s].y + v.y + a0 * w0[s].y + a1 * w1[s].y) * c1v[s].y + c2v[s].y);
            float r0 = z0 - __bfloat162float(__float2bfloat16(z0));
            float r1 = z1 - __bfloat162float(__float2bfloat16(z1));
            *(uint32_t*)(g_ah + erow + k2) = pack2(z0, z1);
            *(uint32_t*)(g_al + erow + k2) = pack2(r0, r1);
        }
    }
}

#define KPAD    80   // bytes per k-row (40 bf16)

// ---------------- kernel 6: pure mma.sync translate GEMM --------------------
// C[128 edges, 256 feats] per CTA, grid (3, 512). A from g_ah/g_al.
#define GP_AH   0
#define GP_AL   10240
#define GP_BH   20480
#define GP_BL   40960
#define GP_SMEM 61440

__global__ void __launch_bounds__(512, 1)
k_gemm2p(const float* __restrict__ W2t, const float* __restrict__ b2t) {
    extern __shared__ char sm[];
    int t = threadIdx.x;
    int m0 = blockIdx.y * 128, n0g = blockIdx.x * 256;

    int wid = t >> 5, lane = t & 31;
    int mw = (wid & 1) * 64, nw = (wid >> 1) * 32;
    int row4 = lane >> 2, quad = lane & 3;

    int mrow = t >> 2, kq8 = (t & 3) * 8;
    const __nv_bfloat16* pAH = g_ah + (size_t)(m0 + mrow) * HT + kq8;
    const __nv_bfloat16* pAL = g_al + (size_t)(m0 + mrow) * HT + kq8;

    float acc[4][4][4];
    #pragma unroll
    for (int tm = 0; tm < 4; tm++)
        #pragma unroll
        for (int tn = 0; tn < 4; tn++)
            #pragma unroll
            for (int q = 0; q < 4; q++) acc[tm][tn][q] = 0.f;

    for (int c = 0; c < 48; c++) {
        int k0 = c * 32;
        if (c) __syncthreads();
        *(uint4*)(sm + GP_AH + mrow * KPAD + kq8 * 2) = *(const uint4*)(pAH + k0);
        *(uint4*)(sm + GP_AL + mrow * KPAD + kq8 * 2) = *(const uint4*)(pAL + k0);
        #pragma unroll
        for (int it = 0; it < 4; it++) {
            int idx = t + it * 512;
            int n = idx & 255, kk = (idx >> 8) * 4;
            const float* pw = W2t + (size_t)(k0 + kk) * 768 + n0g + n;
            float w0v = __ldg(pw), w1v = __ldg(pw + 768),
                  w2v = __ldg(pw + 1536), w3v = __ldg(pw + 2304);
            float r0 = w0v - __bfloat162float(__float2bfloat16(w0v));
            float r1 = w1v - __bfloat162float(__float2bfloat16(w1v));
            float r2 = w2v - __bfloat162float(__float2bfloat16(w2v));
            float r3 = w3v - __bfloat162float(__float2bfloat16(w3v));
            int off = n * KPAD + kk * 2;
            *(uint2*)(sm + GP_BH + off) = make_uint2(pack2(w0v, w1v), pack2(w2v, w3v));
            *(uint2*)(sm + GP_BL + off) = make_uint2(pack2(r0, r1), pack2(r2, r3));
        }
        __syncthreads();
        #pragma unroll
        for (int ks = 0; ks < 2; ks++) {
            int kb = ks * 32 + quad * 4;
            uint32_t af[4][4], bf[4][2];
            #pragma unroll
            for (int tm = 0; tm < 4; tm++) {
                int base = GP_AH + (mw + tm * 16 + row4) * KPAD + kb;
                af[tm][0] = *(const uint32_t*)(sm + base);
                af[tm][1] = *(const uint32_t*)(sm + base + 8 * KPAD);
                af[tm][2] = *(const uint32_t*)(sm + base + 16);
                af[tm][3] = *(const uint32_t*)(sm + base + 8 * KPAD + 16);
            }
            #pragma unroll
            for (int tn = 0; tn < 4; tn++) {
                int base = GP_BH + (nw + tn * 8 + row4) * KPAD + kb;
                bf[tn][0] = *(const uint32_t*)(sm + base);
                bf[tn][1] = *(const uint32_t*)(sm + base + 16);
            }
            #pragma unroll
            for (int tm = 0; tm < 4; tm++)
                #pragma unroll
                for (int tn = 0; tn < 4; tn++)
                    mma16816(acc[tm][tn], af[tm], bf[tn]);
            #pragma unroll
            for (int tn = 0; tn < 4; tn++) {
                int base = GP_BL + (nw + tn * 8 + row4) * KPAD + kb;
                bf[tn][0] = *(const uint32_t*)(sm + base);
                bf[tn][1] = *(const uint32_t*)(sm + base + 16);
            }
            #pragma unroll
            for (int tm = 0; tm < 4; tm++)
                #pragma unroll
                for (int tn = 0; tn < 4; tn++)
                    mma16816(acc[tm][tn], af[tm], bf[tn]);
            #pragma unroll
            for (int tm = 0; tm < 4; tm++) {
                int base = GP_AL + (mw + tm * 16 + row4) * KPAD + kb;
                af[tm][0] = *(const uint32_t*)(sm + base);
                af[tm][1] = *(const uint32_t*)(sm + base + 8 * KPAD);
                af[tm][2] = *(const uint32_t*)(sm + base + 16);
                af[tm][3] = *(const uint32_t*)(sm + base + 8 * KPAD + 16);
            }
            #pragma unroll
            for (int tn = 0; tn < 4; tn++) {
                int base = GP_BH + (nw + tn * 8 + row4) * KPAD + kb;
                bf[tn][0] = *(const uint32_t*)(sm + base);
                bf[tn][1] = *(const uint32_t*)(sm + base + 16);
            }
            #pragma unroll
            for (int tm = 0; tm < 4; tm++)
                #pragma unroll
                for (int tn = 0; tn < 4; tn++)
                    mma16816(acc[tm][tn], af[tm], bf[tn]);
        }
    }

    #pragma unroll
    for (int tm = 0; tm < 4; tm++) {
        int gr = m0 + mw + tm * 16 + row4;
        #pragma unroll
        for (int tn = 0; tn < 4; tn++) {
            int gc = n0g + nw + tn * 8 + quad * 2;
            float bx = __ldg(b2t + gc), by = __ldg(b2t + gc + 1);
            float* p0 = g_na + (size_t)gr * 768 + gc;
            float* p1 = g_na + (size_t)(gr + 8) * 768 + gc;
            *(float2*)p0 = make_float2(acc[tm][tn][0] + bx, acc[tm][tn][1] + by);
            *(float2*)p1 = make_float2(acc[tm][tn][2] + bx, acc[tm][tn][3] + by);
        }
    }
}

// ---------------- kernel 6b: symmetrize new_adjs -> bf16 hi/lo --------------
__global__ void k_sym(const float* __restrict__ flags) {
    int e = blockIdx.x;
    int b = e >> 12, i = (e >> 6) & 63, j = e & 63;
    float mk = flags[b * 64 + i] * flags[b * 64 + j];
    int eji = (b << 12) | (j << 6) | i;
    int t = threadIdx.x;  // 192 threads * 4 floats = 768
    float4 u = *(const float4*)(g_na + (size_t)e * 768 + t * 4);
    float4 v = *(const float4*)(g_na + (size_t)eji * 768 + t * 4);
    float s0 = (u.x + v.x) * mk, s1 = (u.y + v.y) * mk;
    float s2 = (u.z + v.z) * mk, s3 = (u.w + v.w) * mk;
    float r0 = s0 - __bfloat162float(__float2bfloat16(s0));
    float r1 = s1 - __bfloat162float(__float2bfloat16(s1));
    float r2 = s2 - __bfloat162float(__float2bfloat16(s2));
    float r3 = s3 - __bfloat162float(__float2bfloat16(s3));
    *(uint2*)(g_sh + (size_t)e * 768 + t * 4) = make_uint2(pack2(s0, s1), pack2(s2, s3));
    *(uint2*)(g_sl + (size_t)e * 768 + t * 4) = make_uint2(pack2(r0, r1), pack2(r2, r3));
}

// ---------------- kernel 7: mma.sync final_read_score -----------------------
#define KS_A0S  0
#define KS_A1S  512
#define KS_AH   1024
#define KS_AL   11264
#define KS_BH   21504
#define KS_BL   41984
#define KS_RED  62464
#define KS_SMEM 66560

__global__ void __launch_bounds__(512, 1)
k_score_mma(const float* __restrict__ adjs, const float* __restrict__ flags,
            const float* __restrict__ W1r, const float* __restrict__ b1r,
            const float* __restrict__ W2r, const float* __restrict__ b2r,
            float* __restrict__ out_score) {
    extern __shared__ char sm[];
    float* a0s = (float*)(sm + KS_A0S);
    float* a1s = (float*)(sm + KS_A1S);
    float* red = (float*)(sm + KS_RED);
    int t = threadIdx.x;
    int m0 = blockIdx.x * 128;
    int b = m0 >> 12;

    if (t < 128) {
        int e = m0 + t, i = (e >> 6) & 63, j = e & 63;
        float mk = flags[b * 64 + i] * flags[b * 64 + j];
        float a = adjs[(size_t)b * 4096 + i * 64 + j];
        a0s[t] = a * mk;
        a1s[t] = (1.f - a) * mk;
    }
    __syncthreads();

    int wid = t >> 5, lane = t & 31;
    int mw = (wid & 1) * 64, nw = (wid >> 1) * 32;
    int row4 = lane >> 2, quad = lane & 3;

    int mrow = t >> 2, kq8 = (t & 3) * 8;
    const __nv_bfloat16* pSH = g_sh + (size_t)(m0 + mrow) * 768 + kq8;
    const __nv_bfloat16* pSL = g_sl + (size_t)(m0 + mrow) * 768 + kq8;

    float score[4][2];
    #pragma unroll
    for (int tm = 0; tm < 4; tm++) { score[tm][0] = 0.f; score[tm][1] = 0.f; }

    for (int nc = 0; nc < 7; nc++) {
        int n0 = nc * 256;
        float acc[4][4][4];
        #pragma unroll
        for (int tm = 0; tm < 4; tm++) {
            int r0 = mw + tm * 16 + row4;
            float a0A = a0s[r0], a1A = a1s[r0];
            float a0B = a0s[r0 + 8], a1B = a1s[r0 + 8];
            #pragma unroll
            for (int tn = 0; tn < 4; tn++) {
                #pragma unroll
                for (int cq = 0; cq < 2; cq++) {
                    int n = n0 + nw + tn * 8 + quad * 2 + cq;
                    bool ok = n < HR;
                    float br = ok ? __ldg(b1r + n) : 0.f;
                    float w0 = ok ? __ldg(W1r + n) : 0.f;
                    float w1 = ok ? __ldg(W1r + HR + n) : 0.f;
                    acc[tm][tn][cq]     = br + a0A * w0 + a1A * w1;
                    acc[tm][tn][2 + cq] = br + a0B * w0 + a1B * w1;
                }
            }
        }
        for (int c = 0; c < 24; c++) {
            int k0 = c * 32;
            __syncthreads();
            *(uint4*)(sm + KS_AH + mrow * KPAD + kq8 * 2) = *(const uint4*)(pSH + k0);
            *(uint4*)(sm + KS_AL + mrow * KPAD + kq8 * 2) = *(const uint4*)(pSL + k0);
            #pragma unroll
            for (int it = 0; it < 4; it++) {
                int idx = t + it * 512;
                int n = idx & 255, kk = (idx >> 8) * 4;
                int ncol = n0 + n;
                bool ok = ncol < HR;
                const float* pw = W1r + (size_t)(2 + k0 + kk) * HR + ncol;
                float w0v = ok ? __ldg(pw) : 0.f;
                float w1v = ok ? __ldg(pw + HR) : 0.f;
                float w2v = ok ? __ldg(pw + 2 * HR) : 0.f;
                float w3v = ok ? __ldg(pw + 3 * HR) : 0.f;
                float r0 = w0v - __bfloat162float(__float2bfloat16(w0v));
                float r1 = w1v - __bfloat162float(__float2bfloat16(w1v));
                float r2 = w2v - __bfloat162float(__float2bfloat16(w2v));
                float r3 = w3v - __bfloat162float(__float2bfloat16(w3v));
                int off = n * KPAD + kk * 2;
                *(uint2*)(sm + KS_BH + off) = make_uint2(pack2(w0v, w1v), pack2(w2v, w3v));
                *(uint2*)(sm + KS_BL + off) = make_uint2(pack2(r0, r1), pack2(r2, r3));
            }
            __syncthreads();
            #pragma unroll
            for (int ks = 0; ks < 2; ks++) {
                int kb = ks * 32 + quad * 4;
                uint32_t af[4][4], bf[4][2];
                #pragma unroll
                for (int tm = 0; tm < 4; tm++) {
                    int base = KS_AH + (mw + tm * 16 + row4) * KPAD + kb;
                    af[tm][0] = *(const uint32_t*)(sm + base);
                    af[tm][1] = *(const uint32_t*)(sm + base + 8 * KPAD);
                    af[tm][2] = *(const uint32_t*)(sm + base + 16);
                    af[tm][3] = *(const uint32_t*)(sm + base + 8 * KPAD + 16);
                }
                #pragma unroll
                for (int tn = 0; tn < 4; tn++) {
                    int base = KS_BH + (nw + tn * 8 + row4) * KPAD + kb;
                    bf[tn][0] = *(const uint32_t*)(sm + base);
                    bf[tn][1] = *(const uint32_t*)(sm + base + 16);
                }
                #pragma unroll
                for (int tm = 0; tm < 4; tm++)
                    #pragma unroll
                    for (int tn = 0; tn < 4; tn++)
                        mma16816(acc[tm][tn], af[tm], bf[tn]);
                #pragma unroll
                for (int tn = 0; tn < 4; tn++) {
                    int base = KS_BL + (nw + tn * 8 + row4) * KPAD + kb;
                    bf[tn][0] = *(const uint32_t*)(sm + base);
                    bf[tn][1] = *(const uint32_t*)(sm + base + 16);
                }
                #pragma unroll
                for (int tm = 0; tm < 4; tm++)
                    #pragma unroll
                    for (int tn = 0; tn < 4; tn++)
                        mma16816(acc[tm][tn], af[tm], bf[tn]);
                #pragma unroll
                for (int tm = 0; tm < 4; tm++) {
                    int base = KS_AL + (mw + tm * 16 + row4) * KPAD + kb;
                    af[tm][0] = *(const uint32_t*)(sm + base);
                    af[tm][1] = *(const uint32_t*)(sm + base + 8 * KPAD);
                    af[tm][2] = *(const uint32_t*)(sm + base + 16);
                    af[tm][3] = *(const uint32_t*)(sm + base + 8 * KPAD + 16);
                }
                #pragma unroll
                for (int tn = 0; tn < 4; tn++) {
                    int base = KS_BH + (nw + tn * 8 + row4) * KPAD + kb;
                    bf[tn][0] = *(const uint32_t*)(sm + base);
                    bf[tn][1] = *(const uint32_t*)(sm + base + 16);
                }
                #pragma unroll
                for (int tm = 0; tm < 4; tm++)
                    #pragma unroll
                    for (int tn = 0; tn < 4; tn++)
                        mma16816(acc[tm][tn], af[tm], bf[tn]);
            }
        }
        #pragma unroll
        for (int tn = 0; tn < 4; tn++) {
            #pragma unroll
            for (int cq = 0; cq < 2; cq++) {
                int n = n0 + nw + tn * 8 + quad * 2 + cq;
                float w2 = (n < HR) ? __ldg(W2r + n) : 0.f;
                #pragma unroll
                for (int tm = 0; tm < 4; tm++) {
                    score[tm][0] += elu_f(acc[tm][tn][cq]) * w2;
                    score[tm][1] += elu_f(acc[tm][tn][2 + cq]) * w2;
                }
            }
        }
    }
    #pragma unroll
    for (int off = 1; off <= 2; off <<= 1)
        #pragma unroll
        for (int tm = 0; tm < 4; tm++) {
            score[tm][0] += __shfl_xor_sync(0xffffffffu, score[tm][0], off);
            score[tm][1] += __shfl_xor_sync(0xffffffffu, score[tm][1], off);
        }
    __syncthreads();
    if (quad == 0) {
        int wn = wid >> 1;
        #pragma unroll
        for (int tm = 0; tm < 4; tm++) {
            int r0 = mw + tm * 16 + row4;
            red[r0 * 8 + wn] = score[tm][0];
            red[(r0 + 8) * 8 + wn] = score[tm][1];
        }
    }
    __syncthreads();
    if (t < 128) {
        float s = 0.f;
        #pragma unroll
        for (int w8 = 0; w8 < 8; w8++) s += red[t * 8 + w8];
        int e = m0 + t, i = (e >> 6) & 63, j = e & 63;
        out_score[e] = (i == j) ? 0.f : (s + b2r[0]);
    }
}

// ---------------- launch -----------------------------------------------------
extern "C" void kernel_launch(void* const* d_in, const int* in_sizes, int n_in,
                              void* d_out, int out_size) {
    const float* x     = (const float*)d_in[0];
    const float* adjs  = (const float*)d_in[1];
    const float* flags = (const float*)d_in[2];
    const float* Wg    = (const float*)d_in[3];
    const float* bg    = (const float*)d_in[4];
    const float* Wout  = (const float*)d_in[5];
    const float* bout  = (const float*)d_in[6];
    const float* W1t   = (const float*)d_in[7];
    const float* b1t   = (const float*)d_in[8];
    const float* gamma = (const float*)d_in[9];
    const float* beta  = (const float*)d_in[10];
    const float* W2t   = (const float*)d_in[11];
    const float* b2t   = (const float*)d_in[12];
    const float* W1r   = (const float*)d_in[13];
    const float* b1r   = (const float*)d_in[14];
    const float* W2r   = (const float*)d_in[15];
    const float* b2r   = (const float*)d_in[16];

    float* out_score = (float*)d_out;             // [B,N,N] = 65536
    float* out_xo    = (float*)d_out + NEDGE;     // [B,N,768]

    cudaFuncSetAttribute(k_gemm2p, cudaFuncAttributeMaxDynamicSharedMemorySize, GP_SMEM);
    cudaFuncSetAttribute(k_score_mma, cudaFuncAttributeMaxDynamicSharedMemorySize, KS_SMEM);

    k_agg<<<NROW, 128>>>(x, adjs, flags);
    k_gin<<<NROW / 8, 256>>>(x, flags, Wg, bg, Wout, bout, out_xo);
    k_uv<<<dim3(24, 8), 256>>>(out_xo, W1t);
    k_stats<<<NROW, 256>>>(adjs, flags, W1t);
    k_stats2<<<6, 256>>>(b1t, gamma, beta);
    k_agen<<<NROW, 256>>>(adjs, flags, W1t);
    k_gemm2p<<<dim3(3, 512), 512, GP_SMEM>>>(W2t, b2t);
    k_sym<<<NEDGE, 192>>>(flags);
    k_score_mma<<<512, 512, KS_SMEM>>>(adjs, flags, W1r, b1r, W2r, b2r, out_score);
}

// round 10
// speedup vs baseline: 3.6674x; 1.7652x over previous
#include <cuda_runtime.h>
#include <cuda_bf16.h>
#include <stdint.h>
#include <cstdint>
#include <math.h>

// Problem constants
#define BB      16
#define NNODE   64
#define FIN     128
#define FHID    256
#define ODIM    768
#define HT      1536   // translate hidden
#define DR      770
#define HR      1540
#define NEDGE   65536  // B*N*N
#define NROW    1024   // B*N
#define TRI_B   2080   // 64*65/2 per batch
#define TRI_TOT 33280  // 16 * TRI_B (= 260 * 128)

// ---------------- scratch (device globals; no runtime allocation) ----------
__device__ float g_agg[NROW * 256];
__device__ float g_U[NROW * HT];
__device__ float g_V[NROW * HT];
__device__ float g_part[NROW * 2 * HT];
__device__ __align__(16) float g_c1[HT];
__device__ __align__(16) float g_c2[HT];
__device__ int   g_tri[TRI_TOT];                                   // tri rank -> edge
__device__ __align__(16) __nv_bfloat16 g_hh[(size_t)TRI_TOT * HT];   // h2sum hi
__device__ __align__(16) __nv_bfloat16 g_hl[(size_t)TRI_TOT * HT];   // h2sum lo
__device__ __align__(16) __nv_bfloat16 g_ssh[(size_t)TRI_TOT * ODIM]; // S hi
__device__ __align__(16) __nv_bfloat16 g_ssl[(size_t)TRI_TOT * ODIM]; // S lo

__device__ __forceinline__ float elu_f(float x) {
    return x > 0.f ? x : (__expf(x) - 1.f);
}
static __device__ __forceinline__ uint32_t pack2(float a, float b) {
    __nv_bfloat162 h = __floats2bfloat162_rn(a, b);
    return *reinterpret_cast<uint32_t*>(&h);
}
static __device__ __forceinline__ void mma16816(float* c, const uint32_t* a,
                                                const uint32_t* b) {
    asm volatile(
        "mma.sync.aligned.m16n8k16.row.col.f32.bf16.bf16.f32 "
        "{%0,%1,%2,%3}, {%4,%5,%6,%7}, {%8,%9}, {%0,%1,%2,%3};"
        : "+f"(c[0]), "+f"(c[1]), "+f"(c[2]), "+f"(c[3])
        : "r"(a[0]), "r"(a[1]), "r"(a[2]), "r"(a[3]), "r"(b[0]), "r"(b[1]));
}

// ---------------- kernel 0: triangle rank -> edge table ---------------------
__global__ void k_trimap() {
    int e = blockIdx.x * 1024 + threadIdx.x;
    int b = e >> 12, i = (e >> 6) & 63, j = e & 63;
    if (i <= j) {
        int rank = b * TRI_B + i * (129 - i) / 2 + (j - i);
        g_tri[rank] = e;
    }
}

// ---------------- kernel 1: agg --------------------------------------------
__global__ void k_agg(const float* __restrict__ x, const float* __restrict__ adjs,
                      const float* __restrict__ flags) {
    int bi = blockIdx.x;
    int b = bi >> 6, i = bi & 63;
    int f = threadIdx.x;
    __shared__ float a0s[64], a1s[64];
    float fi = flags[b * 64 + i];
    if (threadIdx.x < 64) {
        int j = threadIdx.x;
        float fj = flags[b * 64 + j];
        float a = adjs[(size_t)bi * 64 + j];
        float m = fi * fj;
        a0s[j] = a * m;
        a1s[j] = (1.f - a) * m;
    }
    __syncthreads();
    float s0 = 0.f, s1 = 0.f;
    const float* xb = x + (size_t)b * NNODE * FIN;
    #pragma unroll 4
    for (int j = 0; j < 64; j++) {
        float xv = xb[j * FIN + f];
        s0 += a0s[j] * xv;
        s1 += a1s[j] * xv;
    }
    g_agg[bi * 256 + f] = s0;
    g_agg[bi * 256 + 128 + f] = s1;
}

// ---------------- kernel 2: GIN MLPs -> x_o ---------------------------------
__global__ void k_gin(const float* __restrict__ x, const float* __restrict__ flags,
                      const float* __restrict__ Wg, const float* __restrict__ bg,
                      const float* __restrict__ Wout, const float* __restrict__ bout,
                      float* __restrict__ out_xo) {
    __shared__ float aggs[8][256];
    __shared__ float xs[8][128];
    __shared__ float hs[8][256];
    __shared__ float fl[8];
    int r0 = blockIdx.x * 8;
    int t = threadIdx.x;
    for (int idx = t; idx < 8 * 256; idx += 256)
        aggs[idx >> 8][idx & 255] = g_agg[r0 * 256 + idx];
    for (int idx = t; idx < 8 * 128; idx += 256)
        xs[idx >> 7][idx & 127] = x[(size_t)r0 * 128 + idx];
    if (t < 8) fl[t] = flags[r0 + t];
    __syncthreads();
    {
        float acc[8];
        float bgv = bg[t];
        #pragma unroll
        for (int r = 0; r < 8; r++) acc[r] = bgv;
        for (int k = 0; k < 256; k++) {
            float w = Wg[k * 256 + t];
            #pragma unroll
            for (int r = 0; r < 8; r++) acc[r] += aggs[r][k] * w;
        }
        #pragma unroll
        for (int r = 0; r < 8; r++) hs[r][t] = elu_f(acc[r]) * fl[r];
    }
    __syncthreads();
    float acc[3][8];
    #pragma unroll
    for (int c = 0; c < 3; c++) {
        float bo = bout[t + c * 256];
        #pragma unroll
        for (int r = 0; r < 8; r++) acc[c][r] = bo;
    }
    for (int k = 0; k < 128; k++) {
        float o[8];
        #pragma unroll
        for (int r = 0; r < 8; r++) o[r] = xs[r][k];
        #pragma unroll
        for (int c = 0; c < 3; c++) {
            float w = Wout[k * 768 + t + c * 256];
            #pragma unroll
            for (int r = 0; r < 8; r++) acc[c][r] += o[r] * w;
        }
    }
    for (int k = 0; k < 256; k++) {
        float o[8];
        #pragma unroll
        for (int r = 0; r < 8; r++) o[r] = hs[r][k];
        #pragma unroll
        for (int c = 0; c < 3; c++) {
            float w = Wout[(128 + k) * 768 + t + c * 256];
            #pragma unroll
            for (int r = 0; r < 8; r++) acc[c][r] += o[r] * w;
        }
    }
    #pragma unroll
    for (int c = 0; c < 3; c++)
        #pragma unroll
        for (int r = 0; r < 8; r++)
            out_xo[(size_t)(r0 + r) * 768 + t + c * 256] = tanhf(acc[c][r]) * fl[r];
}

// ---------------- kernel 3: U,V --------------------------------------------
__global__ void k_uv(const float* __restrict__ xo, const float* __restrict__ W1t) {
    __shared__ float As[8][128];
    __shared__ float Bs[8][128];
    int t = threadIdx.x;
    int m0 = blockIdx.y * 128;
    int ng0 = blockIdx.x * 128;
    const int isU = (ng0 < HT);
    const float* Bbase = W1t + (size_t)(isU ? 2 : 770) * HT + (isU ? ng0 : ng0 - HT);
    int m = t >> 1, h4 = (t & 1) * 4;
    const float* pA = xo + (size_t)(m0 + m) * 768 + h4;
    int kkB = t >> 5, c4 = (t & 31) * 4;
    int m_base = (t >> 4) * 8, n_base = (t & 15) * 8;

    float acc[8][8];
    #pragma unroll
    for (int a = 0; a < 8; a++)
        #pragma unroll
        for (int bq = 0; bq < 8; bq++) acc[a][bq] = 0.f;

    for (int k0 = 0; k0 < 768; k0 += 8) {
        float4 av = *(const float4*)(pA + k0);
        float4 bv = *(const float4*)(Bbase + (size_t)(k0 + kkB) * HT + c4);
        __syncthreads();
        As[h4 + 0][m] = av.x; As[h4 + 1][m] = av.y;
        As[h4 + 2][m] = av.z; As[h4 + 3][m] = av.w;
        *(float4*)&Bs[kkB][c4] = bv;
        __syncthreads();
        #pragma unroll
        for (int kk = 0; kk < 8; kk++) {
            float a[8], bb[8];
            *(float4*)(a)     = *(const float4*)&As[kk][m_base];
            *(float4*)(a + 4) = *(const float4*)&As[kk][m_base + 4];
            *(float4*)(bb)     = *(const float4*)&Bs[kk][n_base];
            *(float4*)(bb + 4) = *(const float4*)&Bs[kk][n_base + 4];
            #pragma unroll
            for (int mi = 0; mi < 8; mi++)
                #pragma unroll
                for (int ni = 0; ni < 8; ni++)
                    acc[mi][ni] += a[mi] * bb[ni];
        }
    }
    float* Obase = isU ? g_U : g_V;
    int c0 = isU ? ng0 : ng0 - HT;
    #pragma unroll
    for (int mi = 0; mi < 8; mi++) {
        float* prow = Obase + (size_t)(m0 + m_base + mi) * HT + c0 + n_base;
        *(float4*)(prow)     = make_float4(acc[mi][0], acc[mi][1], acc[mi][2], acc[mi][3]);
        *(float4*)(prow + 4) = make_float4(acc[mi][4], acc[mi][5], acc[mi][6], acc[mi][7]);
    }
}

// ---------------- kernel 4: BN stats partials -------------------------------
__global__ void k_stats(const float* __restrict__ adjs, const float* __restrict__ flags,
                        const float* __restrict__ W1t) {
    int bi = blockIdx.x;
    int b = bi >> 6, i = bi & 63;
    int t = threadIdx.x;
    __shared__ float Ur[HT];
    __shared__ float a0s[64], a1s[64];
    for (int k = t; k < HT; k += 256) Ur[k] = g_U[(size_t)bi * HT + k];
    if (t < 64) {
        int j = t;
        float m = flags[b * 64 + i] * flags[b * 64 + j];
        float a = adjs[(size_t)bi * 64 + j];
        a0s[j] = a * m;
        a1s[j] = (1.f - a) * m;
    }
    __syncthreads();
    float w0[6], w1[6], u[6], sum[6], sq[6];
    #pragma unroll
    for (int s = 0; s < 6; s++) {
        int k = t + s * 256;
        w0[s] = W1t[k];
        w1[s] = W1t[HT + k];
        u[s] = Ur[k];
        sum[s] = 0.f; sq[s] = 0.f;
    }
    const float* Vb = g_V + (size_t)(b * 64) * HT;
    for (int j = 0; j < 64; j++) {
        float a0 = a0s[j], a1 = a1s[j];
        const float* Vr = Vb + (size_t)j * HT;
        #pragma unroll
        for (int s = 0; s < 6; s++) {
            float z = u[s] + Vr[t + s * 256] + a0 * w0[s] + a1 * w1[s];
            sum[s] += z;
            sq[s] += z * z;
        }
    }
    #pragma unroll
    for (int s = 0; s < 6; s++) {
        g_part[(size_t)bi * 3072 + t + s * 256] = sum[s];
        g_part[(size_t)bi * 3072 + HT + t + s * 256] = sq[s];
    }
}

// ---------------- kernel 5: finalize BN constants ---------------------------
__global__ void k_stats2(const float* __restrict__ b1t, const float* __restrict__ gamma,
                         const float* __restrict__ beta) {
    int k = blockIdx.x * 256 + threadIdx.x;
    float s = 0.f, q = 0.f;
    for (int bi = 0; bi < NROW; bi++) {
        s += g_part[(size_t)bi * 3072 + k];
        q += g_part[(size_t)bi * 3072 + HT + k];
    }
    const float inv = 1.f / 65536.f;
    float mu_z = s * inv;
    float var = fmaxf(q * inv - mu_z * mu_z, 0.f);
    float mu = mu_z + b1t[k];
    float c1 = gamma[k] * rsqrtf(var + 1e-5f);
    g_c1[k] = c1;
    g_c2[k] = beta[k] - mu * c1;
}

// ---------------- kernel 5b: h2sum on triangle -> bf16 hi/lo ----------------
// block per (b,i); 384 threads x 4 cols; j = i..63.
__global__ void __launch_bounds__(384)
k_agen_tri(const float* __restrict__ adjs, const float* __restrict__ flags,
           const float* __restrict__ W1t) {
    int bi = blockIdx.x;
    int b = bi >> 6, i = bi & 63;
    int c4 = threadIdx.x * 4;
    float4 w0 = __ldg((const float4*)(W1t + c4));
    float4 w1 = __ldg((const float4*)(W1t + HT + c4));
    float4 c1 = *(const float4*)(g_c1 + c4);
    float4 c2 = *(const float4*)(g_c2 + c4);
    float4 ui = *(const float4*)(g_U + (size_t)bi * HT + c4);
    float4 vi = *(const float4*)(g_V + (size_t)bi * HT + c4);
    float fi = __ldg(flags + b * 64 + i);
    size_t rank0 = (size_t)b * TRI_B + i * (129 - i) / 2;
    for (int j = i; j < 64; j++) {
        float fj = __ldg(flags + b * 64 + j);
        float mk = fi * fj;
        float aij = __ldg(adjs + (size_t)b * 4096 + i * 64 + j);
        float aji = __ldg(adjs + (size_t)b * 4096 + j * 64 + i);
        float a0ij = aij * mk, a1ij = (1.f - aij) * mk;
        float a0ji = aji * mk, a1ji = (1.f - aji) * mk;
        float4 uj = *(const float4*)(g_U + (size_t)(b * 64 + j) * HT + c4);
        float4 vj = *(const float4*)(g_V + (size_t)(b * 64 + j) * HT + c4);
        float s0 = elu_f((ui.x + vj.x + a0ij * w0.x + a1ij * w1.x) * c1.x + c2.x)
                 + elu_f((uj.x + vi.x + a0ji * w0.x + a1ji * w1.x) * c1.x + c2.x);
        float s1 = elu_f((ui.y + vj.y + a0ij * w0.y + a1ij * w1.y) * c1.y + c2.y)
                 + elu_f((uj.y + vi.y + a0ji * w0.y + a1ji * w1.y) * c1.y + c2.y);
        float s2 = elu_f((ui.z + vj.z + a0ij * w0.z + a1ij * w1.z) * c1.z + c2.z)
                 + elu_f((uj.z + vi.z + a0ji * w0.z + a1ji * w1.z) * c1.z + c2.z);
        float s3 = elu_f((ui.w + vj.w + a0ij * w0.w + a1ij * w1.w) * c1.w + c2.w)
                 + elu_f((uj.w + vi.w + a0ji * w0.w + a1ji * w1.w) * c1.w + c2.w);
        float r0 = s0 - __bfloat162float(__float2bfloat16(s0));
        float r1 = s1 - __bfloat162float(__float2bfloat16(s1));
        float r2 = s2 - __bfloat162float(__float2bfloat16(s2));
        float r3 = s3 - __bfloat162float(__float2bfloat16(s3));
        size_t row = (rank0 + (j - i)) * HT + c4;
        *(uint2*)(g_hh + row) = make_uint2(pack2(s0, s1), pack2(s2, s3));
        *(uint2*)(g_hl + row) = make_uint2(pack2(r0, r1), pack2(r2, r3));
    }
}

#define KPAD    80   // bytes per k-row (40 bf16)

// ---------------- kernel 6: triangle translate GEMM -> S (bf16 hi/lo) -------
// C[128 tri-edges, 256 feats] per CTA, grid (3, 260). K=1536 in 48 chunks.
#define GP_AH   0
#define GP_AL   10240
#define GP_BH   20480
#define GP_BL   40960
#define GP_MKS  61440
#define GP_SMEM 61952

__global__ void __launch_bounds__(512, 1)
k_gemm2_tri(const float* __restrict__ flags,
            const float* __restrict__ W2t, const float* __restrict__ b2t) {
    extern __shared__ char sm[];
    float* mks = (float*)(sm + GP_MKS);
    int t = threadIdx.x;
    int m0 = blockIdx.y * 128, n0g = blockIdx.x * 256;

    if (t < 128) {
        int e = __ldg(g_tri + m0 + t);
        int b = e >> 12, i = (e >> 6) & 63, j = e & 63;
        mks[t] = __ldg(flags + b * 64 + i) * __ldg(flags + b * 64 + j);
    }
    __syncthreads();

    int wid = t >> 5, lane = t & 31;
    int mw = (wid & 1) * 64, nw = (wid >> 1) * 32;
    int row4 = lane >> 2, quad = lane & 3;

    int mrow = t >> 2, kq8 = (t & 3) * 8;
    const __nv_bfloat16* pAH = g_hh + (size_t)(m0 + mrow) * HT + kq8;
    const __nv_bfloat16* pAL = g_hl + (size_t)(m0 + mrow) * HT + kq8;

    float acc[4][4][4];
    #pragma unroll
    for (int tm = 0; tm < 4; tm++)
        #pragma unroll
        for (int tn = 0; tn < 4; tn++)
            #pragma unroll
            for (int q = 0; q < 4; q++) acc[tm][tn][q] = 0.f;

    for (int c = 0; c < 48; c++) {
        int k0 = c * 32;
        if (c) __syncthreads();
        *(uint4*)(sm + GP_AH + mrow * KPAD + kq8 * 2) = *(const uint4*)(pAH + k0);
        *(uint4*)(sm + GP_AL + mrow * KPAD + kq8 * 2) = *(const uint4*)(pAL + k0);
        #pragma unroll
        for (int it = 0; it < 4; it++) {
            int idx = t + it * 512;
            int n = idx & 255, kk = (idx >> 8) * 4;
            const float* pw = W2t + (size_t)(k0 + kk) * 768 + n0g + n;
            float w0v = __ldg(pw), w1v = __ldg(pw + 768),
                  w2v = __ldg(pw + 1536), w3v = __ldg(pw + 2304);
            float r0 = w0v - __bfloat162float(__float2bfloat16(w0v));
            float r1 = w1v - __bfloat162float(__float2bfloat16(w1v));
            float r2 = w2v - __bfloat162float(__float2bfloat16(w2v));
            float r3 = w3v - __bfloat162float(__float2bfloat16(w3v));
            int off = n * KPAD + kk * 2;
            *(uint2*)(sm + GP_BH + off) = make_uint2(pack2(w0v, w1v), pack2(w2v, w3v));
            *(uint2*)(sm + GP_BL + off) = make_uint2(pack2(r0, r1), pack2(r2, r3));
        }
        __syncthreads();
        #pragma unroll
        for (int ks = 0; ks < 2; ks++) {
            int kb = ks * 32 + quad * 4;
            uint32_t af[4][4], bf[4][2];
            #pragma unroll
            for (int tm = 0; tm < 4; tm++) {
                int base = GP_AH + (mw + tm * 16 + row4) * KPAD + kb;
                af[tm][0] = *(const uint32_t*)(sm + base);
                af[tm][1] = *(const uint32_t*)(sm + base + 8 * KPAD);
                af[tm][2] = *(const uint32_t*)(sm + base + 16);
                af[tm][3] = *(const uint32_t*)(sm + base + 8 * KPAD + 16);
            }
            #pragma unroll
            for (int tn = 0; tn < 4; tn++) {
                int base = GP_BH + (nw + tn * 8 + row4) * KPAD + kb;
                bf[tn][0] = *(const uint32_t*)(sm + base);
                bf[tn][1] = *(const uint32_t*)(sm + base + 16);
            }
            #pragma unroll
            for (int tm = 0; tm < 4; tm++)
                #pragma unroll
                for (int tn = 0; tn < 4; tn++)
                    mma16816(acc[tm][tn], af[tm], bf[tn]);
            #pragma unroll
            for (int tn = 0; tn < 4; tn++) {
                int base = GP_BL + (nw + tn * 8 + row4) * KPAD + kb;
                bf[tn][0] = *(const uint32_t*)(sm + base);
                bf[tn][1] = *(const uint32_t*)(sm + base + 16);
            }
            #pragma unroll
            for (int tm = 0; tm < 4; tm++)
                #pragma unroll
                for (int tn = 0; tn < 4; tn++)
                    mma16816(acc[tm][tn], af[tm], bf[tn]);
            #pragma unroll
            for (int tm = 0; tm < 4; tm++) {
                int base = GP_AL + (mw + tm * 16 + row4) * KPAD + kb;
                af[tm][0] = *(const uint32_t*)(sm + base);
                af[tm][1] = *(const uint32_t*)(sm + base + 8 * KPAD);
                af[tm][2] = *(const uint32_t*)(sm + base + 16);
                af[tm][3] = *(const uint32_t*)(sm + base + 8 * KPAD + 16);
            }
            #pragma unroll
            for (int tn = 0; tn < 4; tn++) {
                int base = GP_BH + (nw + tn * 8 + row4) * KPAD + kb;
                bf[tn][0] = *(const uint32_t*)(sm + base);
                bf[tn][1] = *(const uint32_t*)(sm + base + 16);
            }
            #pragma unroll
            for (int tm = 0; tm < 4; tm++)
                #pragma unroll
                for (int tn = 0; tn < 4; tn++)
                    mma16816(acc[tm][tn], af[tm], bf[tn]);
        }
    }

    // epilogue: S = (acc + 2*b2t) * mk -> bf16 hi/lo in triangle order
    #pragma unroll
    for (int tm = 0; tm < 4; tm++) {
        int r0 = mw + tm * 16 + row4;
        float mk0 = mks[r0], mk1 = mks[r0 + 8];
        size_t gr0 = (size_t)(m0 + r0) * 768;
        size_t gr1 = (size_t)(m0 + r0 + 8) * 768;
        #pragma unroll
        for (int tn = 0; tn < 4; tn++) {
            int gc = n0g + nw + tn * 8 + quad * 2;
            float bx = 2.f * __ldg(b2t + gc), by = 2.f * __ldg(b2t + gc + 1);
            float s00 = (acc[tm][tn][0] + bx) * mk0, s01 = (acc[tm][tn][1] + by) * mk0;
            float s10 = (acc[tm][tn][2] + bx) * mk1, s11 = (acc[tm][tn][3] + by) * mk1;
            float r00 = s00 - __bfloat162float(__float2bfloat16(s00));
            float r01 = s01 - __bfloat162float(__float2bfloat16(s01));
            float r10 = s10 - __bfloat162float(__float2bfloat16(s10));
            float r11 = s11 - __bfloat162float(__float2bfloat16(s11));
            *(uint32_t*)(g_ssh + gr0 + gc) = pack2(s00, s01);
            *(uint32_t*)(g_ssl + gr0 + gc) = pack2(r00, r01);
            *(uint32_t*)(g_ssh + gr1 + gc) = pack2(s10, s11);
            *(uint32_t*)(g_ssl + gr1 + gc) = pack2(r10, r11);
        }
    }
}

// ---------------- kernel 7: triangle final_read_score -----------------------
// G = S @ W1r[2:] on triangle rows; epilogue applies rank-1 + elu twice
// (ij and ji orientations) and emits both scores.
#define ST_AH   0
#define ST_AL   10240
#define ST_BH   20480
#define ST_BL   40960
#define ST_A0IJ 61440
#define ST_A1IJ 61952
#define ST_A0JI 62464
#define ST_A1JI 62976
#define ST_ESM  63488
#define ST_RED  64000
#define ST_SMEM 72192

__global__ void __launch_bounds__(512, 1)
k_score_tri(const float* __restrict__ adjs, const float* __restrict__ flags,
            const float* __restrict__ W1r, const float* __restrict__ b1r,
            const float* __restrict__ W2r, const float* __restrict__ b2r,
            float* __restrict__ out_score) {
    extern __shared__ char sm[];
    float* a0ijs = (float*)(sm + ST_A0IJ);
    float* a1ijs = (float*)(sm + ST_A1IJ);
    float* a0jis = (float*)(sm + ST_A0JI);
    float* a1jis = (float*)(sm + ST_A1JI);
    int*   esm   = (int*)(sm + ST_ESM);
    float* red   = (float*)(sm + ST_RED);   // [128][8] ij then [128][8] ji
    int t = threadIdx.x;
    int m0 = blockIdx.x * 128;

    if (t < 128) {
        int e = __ldg(g_tri + m0 + t);
        esm[t] = e;
        int b = e >> 12, i = (e >> 6) & 63, j = e & 63;
        float mk = __ldg(flags + b * 64 + i) * __ldg(flags + b * 64 + j);
        float aij = __ldg(adjs + e);
        float aji = __ldg(adjs + (b << 12) + (j << 6) + i);
        a0ijs[t] = aij * mk; a1ijs[t] = (1.f - aij) * mk;
        a0jis[t] = aji * mk; a1jis[t] = (1.f - aji) * mk;
    }
    __syncthreads();

    int wid = t >> 5, lane = t & 31;
    int mw = (wid & 1) * 64, nw = (wid >> 1) * 32;
    int row4 = lane >> 2, quad = lane & 3;

    int mrow = t >> 2, kq8 = (t & 3) * 8;
    const __nv_bfloat16* pSH = g_ssh + (size_t)(m0 + mrow) * 768 + kq8;
    const __nv_bfloat16* pSL = g_ssl + (size_t)(m0 + mrow) * 768 + kq8;

    float sij[4][2], sji[4][2];
    #pragma unroll
    for (int tm = 0; tm < 4; tm++) {
        sij[tm][0] = 0.f; sij[tm][1] = 0.f;
        sji[tm][0] = 0.f; sji[tm][1] = 0.f;
    }

    for (int nc = 0; nc < 7; nc++) {
        int n0 = nc * 256;
        float acc[4][4][4];
        #pragma unroll
        for (int tn = 0; tn < 4; tn++)
            #pragma unroll
            for (int cq = 0; cq < 2; cq++) {
                int n = n0 + nw + tn * 8 + quad * 2 + cq;
                float br = (n < HR) ? __ldg(b1r + n) : 0.f;
                #pragma unroll
                for (int tm = 0; tm < 4; tm++) {
                    acc[tm][tn][cq] = br;
                    acc[tm][tn][2 + cq] = br;
                }
            }
        for (int c = 0; c < 24; c++) {
            int k0 = c * 32;
            __syncthreads();
            *(uint4*)(sm + ST_AH + mrow * KPAD + kq8 * 2) = *(const uint4*)(pSH + k0);
            *(uint4*)(sm + ST_AL + mrow * KPAD + kq8 * 2) = *(const uint4*)(pSL + k0);
            #pragma unroll
            for (int it = 0; it < 4; it++) {
                int idx = t + it * 512;
                int n = idx & 255, kk = (idx >> 8) * 4;
                int ncol = n0 + n;
                bool ok = ncol < HR;
                const float* pw = W1r + (size_t)(2 + k0 + kk) * HR + ncol;
                float w0v = ok ? __ldg(pw) : 0.f;
                float w1v = ok ? __ldg(pw + HR) : 0.f;
                float w2v = ok ? __ldg(pw + 2 * HR) : 0.f;
                float w3v = ok ? __ldg(pw + 3 * HR) : 0.f;
                float r0 = w0v - __bfloat162float(__float2bfloat16(w0v));
                float r1 = w1v - __bfloat162float(__float2bfloat16(w1v));
                float r2 = w2v - __bfloat162float(__float2bfloat16(w2v));
                float r3 = w3v - __bfloat162float(__float2bfloat16(w3v));
                int off = n * KPAD + kk * 2;
                *(uint2*)(sm + ST_BH + off) = make_uint2(pack2(w0v, w1v), pack2(w2v, w3v));
                *(uint2*)(sm + ST_BL + off) = make_uint2(pack2(r0, r1), pack2(r2, r3));
            }
            __syncthreads();
            #pragma unroll
            for (int ks = 0; ks < 2; ks++) {
                int kb = ks * 32 + quad * 4;
                uint32_t af[4][4], bf[4][2];
                #pragma unroll
                for (int tm = 0; tm < 4; tm++) {
                    int base = ST_AH + (mw + tm * 16 + row4) * KPAD + kb;
                    af[tm][0] = *(const uint32_t*)(sm + base);
                    af[tm][1] = *(const uint32_t*)(sm + base + 8 * KPAD);
                    af[tm][2] = *(const uint32_t*)(sm + base + 16);
                    af[tm][3] = *(const uint32_t*)(sm + base + 8 * KPAD + 16);
                }
                #pragma unroll
                for (int tn = 0; tn < 4; tn++) {
                    int base = ST_BH + (nw + tn * 8 + row4) * KPAD + kb;
                    bf[tn][0] = *(const uint32_t*)(sm + base);
                    bf[tn][1] = *(const uint32_t*)(sm + base + 16);
                }
                #pragma unroll
                for (int tm = 0; tm < 4; tm++)
                    #pragma unroll
                    for (int tn = 0; tn < 4; tn++)
                        mma16816(acc[tm][tn], af[tm], bf[tn]);
                #pragma unroll
                for (int tn = 0; tn < 4; tn++) {
                    int base = ST_BL + (nw + tn * 8 + row4) * KPAD + kb;
                    bf[tn][0] = *(const uint32_t*)(sm + base);
                    bf[tn][1] = *(const uint32_t*)(sm + base + 16);
                }
                #pragma unroll
                for (int tm = 0; tm < 4; tm++)
                    #pragma unroll
                    for (int tn = 0; tn < 4; tn++)
                        mma16816(acc[tm][tn], af[tm], bf[tn]);
                #pragma unroll
                for (int tm = 0; tm < 4; tm++) {
                    int base = ST_AL + (mw + tm * 16 + row4) * KPAD + kb;
                    af[tm][0] = *(const uint32_t*)(sm + base);
                    af[tm][1] = *(const uint32_t*)(sm + base + 8 * KPAD);
                    af[tm][2] = *(const uint32_t*)(sm + base + 16);
                    af[tm][3] = *(const uint32_t*)(sm + base + 8 * KPAD + 16);
                }
                #pragma unroll
                for (int tn = 0; tn < 4; tn++) {
                    int base = ST_BH + (nw + tn * 8 + row4) * KPAD + kb;
                    bf[tn][0] = *(const uint32_t*)(sm + base);
                    bf[tn][1] = *(const uint32_t*)(sm + base + 16);
                }
                #pragma unroll
                for (int tm = 0; tm < 4; tm++)
                    #pragma unroll
                    for (int tn = 0; tn < 4; tn++)
                        mma16816(acc[tm][tn], af[tm], bf[tn]);
            }
        }
        // epilogue: elu for both orientations, dot with W2r
        #pragma unroll
        for (int tn = 0; tn < 4; tn++)
            #pragma unroll
            for (int cq = 0; cq < 2; cq++) {
                int n = n0 + nw + tn * 8 + quad * 2 + cq;
                bool ok = n < HR;
                float w0 = ok ? __ldg(W1r + n) : 0.f;
                float w1 = ok ? __ldg(W1r + HR + n) : 0.f;
                float w2 = ok ? __ldg(W2r + n) : 0.f;
                #pragma unroll
                for (int tm = 0; tm < 4; tm++) {
                    int r0 = mw + tm * 16 + row4;
                    float g0 = acc[tm][tn][cq], g1 = acc[tm][tn][2 + cq];
                    sij[tm][0] += elu_f(g0 + a0ijs[r0] * w0 + a1ijs[r0] * w1) * w2;
                    sji[tm][0] += elu_f(g0 + a0jis[r0] * w0 + a1jis[r0] * w1) * w2;
                    sij[tm][1] += elu_f(g1 + a0ijs[r0 + 8] * w0 + a1ijs[r0 + 8] * w1) * w2;
                    sji[tm][1] += elu_f(g1 + a0jis[r0 + 8] * w0 + a1jis[r0 + 8] * w1) * w2;
                }
            }
    }
    #pragma unroll
    for (int off = 1; off <= 2; off <<= 1)
        #pragma unroll
        for (int tm = 0; tm < 4; tm++) {
            sij[tm][0] += __shfl_xor_sync(0xffffffffu, sij[tm][0], off);
            sij[tm][1] += __shfl_xor_sync(0xffffffffu, sij[tm][1], off);
            sji[tm][0] += __shfl_xor_sync(0xffffffffu, sji[tm][0], off);
            sji[tm][1] += __shfl_xor_sync(0xffffffffu, sji[tm][1], off);
        }
    __syncthreads();
    if (quad == 0) {
        int wn = wid >> 1;
        #pragma unroll
        for (int tm = 0; tm < 4; tm++) {
            int r0 = mw + tm * 16 + row4;
            red[r0 * 8 + wn] = sij[tm][0];
            red[(r0 + 8) * 8 + wn] = sij[tm][1];
            red[1024 + r0 * 8 + wn] = sji[tm][0];
            red[1024 + (r0 + 8) * 8 + wn] = sji[tm][1];
        }
    }
    __syncthreads();
    if (t < 128) {
        float s1 = 0.f, s2 = 0.f;
        #pragma unroll
        for (int w8 = 0; w8 < 8; w8++) {
            s1 += red[t * 8 + w8];
            s2 += red[1024 + t * 8 + w8];
        }
        int e = esm[t];
        int b = e >> 12, i = (e >> 6) & 63, j = e & 63;
        float b2 = b2r[0];
        out_score[e] = (i == j) ? 0.f : (s1 + b2);
        if (i != j)
            out_score[(b << 12) + (j << 6) + i] = s2 + b2;
    }
}

// ---------------- launch -----------------------------------------------------
extern "C" void kernel_launch(void* const* d_in, const int* in_sizes, int n_in,
                              void* d_out, int out_size) {
    const float* x     = (const float*)d_in[0];
    const float* adjs  = (const float*)d_in[1];
    const float* flags = (const float*)d_in[2];
    const float* Wg    = (const float*)d_in[3];
    const float* bg    = (const float*)d_in[4];
    const float* Wout  = (const float*)d_in[5];
    const float* bout  = (const float*)d_in[6];
    const float* W1t   = (const float*)d_in[7];
    const float* b1t   = (const float*)d_in[8];
    const float* gamma = (const float*)d_in[9];
    const float* beta  = (const float*)d_in[10];
    const float* W2t   = (const float*)d_in[11];
    const float* b2t   = (const float*)d_in[12];
    const float* W1r   = (const float*)d_in[13];
    const float* b1r   = (const float*)d_in[14];
    const float* W2r   = (const float*)d_in[15];
    const float* b2r   = (const float*)d_in[16];

    float* out_score = (float*)d_out;             // [B,N,N] = 65536
    float* out_xo    = (float*)d_out + NEDGE;     // [B,N,768]

    cudaFuncSetAttribute(k_gemm2_tri, cudaFuncAttributeMaxDynamicSharedMemorySize, GP_SMEM);
    cudaFuncSetAttribute(k_score_tri, cudaFuncAttributeMaxDynamicSharedMemorySize, ST_SMEM);

    k_trimap<<<64, 1024>>>();
    k_agg<<<NROW, 128>>>(x, adjs, flags);
    k_gin<<<NROW / 8, 256>>>(x, flags, Wg, bg, Wout, bout, out_xo);
    k_uv<<<dim3(24, 8), 256>>>(out_xo, W1t);
    k_stats<<<NROW, 256>>>(adjs, flags, W1t);
    k_stats2<<<6, 256>>>(b1t, gamma, beta);
    k_agen_tri<<<NROW, 384>>>(adjs, flags, W1t);
    k_gemm2_tri<<<dim3(3, 260), 512, GP_SMEM>>>(flags, W2t, b2t);
    k_score_tri<<<260, 512, ST_SMEM>>>(adjs, flags, W1r, b1r, W2r, b2r, out_score);
}

// round 11
// speedup vs baseline: 3.8002x; 1.0362x over previous
#include <cuda_runtime.h>
#include <cuda_bf16.h>
#include <stdint.h>
#include <cstdint>
#include <math.h>

// Problem constants
#define BB      16
#define NNODE   64
#define FIN     128
#define FHID    256
#define ODIM    768
#define HT      1536   // translate hidden
#define DR      770
#define HR      1540
#define NEDGE   65536  // B*N*N
#define NROW    1024   // B*N
#define TRI_B   2080   // 64*65/2 per batch
#define TRI_TOT 33280  // 16 * TRI_B (= 260 * 128)

// ---------------- scratch (device globals; no runtime allocation) ----------
__device__ float g_agg[NROW * 256];
__device__ float g_U[NROW * HT];
__device__ float g_V[NROW * HT];
__device__ float g_part[NROW * 2 * HT];
__device__ __align__(16) float g_c1[HT];
__device__ __align__(16) float g_c2[HT];
__device__ int   g_tri[TRI_TOT];                                     // tri rank -> edge
__device__ __align__(16) __nv_bfloat16 g_xh[NROW * ODIM];            // xo hi
__device__ __align__(16) __nv_bfloat16 g_xl[NROW * ODIM];            // xo lo
__device__ __align__(16) __nv_bfloat16 g_hh[(size_t)TRI_TOT * HT];   // h2sum hi
__device__ __align__(16) __nv_bfloat16 g_hl[(size_t)TRI_TOT * HT];   // h2sum lo
__device__ __align__(16) __nv_bfloat16 g_ssh[(size_t)TRI_TOT * ODIM]; // S hi
__device__ __align__(16) __nv_bfloat16 g_ssl[(size_t)TRI_TOT * ODIM]; // S lo

__device__ __forceinline__ float elu_f(float x) {
    return x > 0.f ? x : (__expf(x) - 1.f);
}
static __device__ __forceinline__ uint32_t pack2(float a, float b) {
    __nv_bfloat162 h = __floats2bfloat162_rn(a, b);
    return *reinterpret_cast<uint32_t*>(&h);
}
static __device__ __forceinline__ void mma16816(float* c, const uint32_t* a,
                                                const uint32_t* b) {
    asm volatile(
        "mma.sync.aligned.m16n8k16.row.col.f32.bf16.bf16.f32 "
        "{%0,%1,%2,%3}, {%4,%5,%6,%7}, {%8,%9}, {%0,%1,%2,%3};"
        : "+f"(c[0]), "+f"(c[1]), "+f"(c[2]), "+f"(c[3])
        : "r"(a[0]), "r"(a[1]), "r"(a[2]), "r"(a[3]), "r"(b[0]), "r"(b[1]));
}

// ---------------- kernel 0: triangle rank -> edge table ---------------------
__global__ void k_trimap() {
    int e = blockIdx.x * 1024 + threadIdx.x;
    int b = e >> 12, i = (e >> 6) & 63, j = e & 63;
    if (i <= j) {
        int rank = b * TRI_B + i * (129 - i) / 2 + (j - i);
        g_tri[rank] = e;
    }
}

// ---------------- kernel 1: agg --------------------------------------------
__global__ void k_agg(const float* __restrict__ x, const float* __restrict__ adjs,
                      const float* __restrict__ flags) {
    int bi = blockIdx.x;
    int b = bi >> 6, i = bi & 63;
    int f = threadIdx.x;
    __shared__ float a0s[64], a1s[64];
    float fi = flags[b * 64 + i];
    if (threadIdx.x < 64) {
        int j = threadIdx.x;
        float fj = flags[b * 64 + j];
        float a = adjs[(size_t)bi * 64 + j];
        float m = fi * fj;
        a0s[j] = a * m;
        a1s[j] = (1.f - a) * m;
    }
    __syncthreads();
    float s0 = 0.f, s1 = 0.f;
    const float* xb = x + (size_t)b * NNODE * FIN;
    #pragma unroll 4
    for (int j = 0; j < 64; j++) {
        float xv = xb[j * FIN + f];
        s0 += a0s[j] * xv;
        s1 += a1s[j] * xv;
    }
    g_agg[bi * 256 + f] = s0;
    g_agg[bi * 256 + 128 + f] = s1;
}

// ---------------- kernel 2: GIN MLPs -> x_o (+ bf16 hi/lo split) ------------
__global__ void k_gin(const float* __restrict__ x, const float* __restrict__ flags,
                      const float* __restrict__ Wg, const float* __restrict__ bg,
                      const float* __restrict__ Wout, const float* __restrict__ bout,
                      float* __restrict__ out_xo) {
    __shared__ float aggs[8][256];
    __shared__ float xs[8][128];
    __shared__ float hs[8][256];
    __shared__ float fl[8];
    int r0 = blockIdx.x * 8;
    int t = threadIdx.x;
    for (int idx = t; idx < 8 * 256; idx += 256)
        aggs[idx >> 8][idx & 255] = g_agg[r0 * 256 + idx];
    for (int idx = t; idx < 8 * 128; idx += 256)
        xs[idx >> 7][idx & 127] = x[(size_t)r0 * 128 + idx];
    if (t < 8) fl[t] = flags[r0 + t];
    __syncthreads();
    {
        float acc[8];
        float bgv = bg[t];
        #pragma unroll
        for (int r = 0; r < 8; r++) acc[r] = bgv;
        for (int k = 0; k < 256; k++) {
            float w = Wg[k * 256 + t];
            #pragma unroll
            for (int r = 0; r < 8; r++) acc[r] += aggs[r][k] * w;
        }
        #pragma unroll
        for (int r = 0; r < 8; r++) hs[r][t] = elu_f(acc[r]) * fl[r];
    }
    __syncthreads();
    float acc[3][8];
    #pragma unroll
    for (int c = 0; c < 3; c++) {
        float bo = bout[t + c * 256];
        #pragma unroll
        for (int r = 0; r < 8; r++) acc[c][r] = bo;
    }
    for (int k = 0; k < 128; k++) {
        float o[8];
        #pragma unroll
        for (int r = 0; r < 8; r++) o[r] = xs[r][k];
        #pragma unroll
        for (int c = 0; c < 3; c++) {
            float w = Wout[k * 768 + t + c * 256];
            #pragma unroll
            for (int r = 0; r < 8; r++) acc[c][r] += o[r] * w;
        }
    }
    for (int k = 0; k < 256; k++) {
        float o[8];
        #pragma unroll
        for (int r = 0; r < 8; r++) o[r] = hs[r][k];
        #pragma unroll
        for (int c = 0; c < 3; c++) {
            float w = Wout[(128 + k) * 768 + t + c * 256];
            #pragma unroll
            for (int r = 0; r < 8; r++) acc[c][r] += o[r] * w;
        }
    }
    #pragma unroll
    for (int c = 0; c < 3; c++)
        #pragma unroll
        for (int r = 0; r < 8; r++) {
            size_t idx = (size_t)(r0 + r) * 768 + t + c * 256;
            float val = tanhf(acc[c][r]) * fl[r];
            out_xo[idx] = val;
            __nv_bfloat16 h = __float2bfloat16(val);
            g_xh[idx] = h;
            g_xl[idx] = __float2bfloat16(val - __bfloat162float(h));
        }
}

#define KPAD    80   // bytes per k-row (40 bf16)

// ---------------- kernel 3: U,V via mma (xo @ W1t slices) -------------------
// grid (12, 8): blockIdx.x<6 -> U cols, >=6 -> V cols. 24 chunks of K=32.
#define UV_AH   0
#define UV_AL   10240
#define UV_BH   20480
#define UV_BL   40960
#define UV_SMEM 61440

__global__ void __launch_bounds__(512, 1)
k_uv_mma(const float* __restrict__ W1t) {
    extern __shared__ char sm[];
    int t = threadIdx.x;
    int m0 = blockIdx.y * 128;
    int ng0 = blockIdx.x * 256;
    const int isU = (ng0 < HT);
    const float* Wbase = W1t + (size_t)(isU ? 2 : 770) * HT + (isU ? ng0 : ng0 - HT);

    int wid = t >> 5, lane = t & 31;
    int mw = (wid & 1) * 64, nw = (wid >> 1) * 32;
    int row4 = lane >> 2, quad = lane & 3;

    int mrow = t >> 2, kq8 = (t & 3) * 8;
    const __nv_bfloat16* pAH = g_xh + (size_t)(m0 + mrow) * 768 + kq8;
    const __nv_bfloat16* pAL = g_xl + (size_t)(m0 + mrow) * 768 + kq8;

    float acc[4][4][4];
    #pragma unroll
    for (int tm = 0; tm < 4; tm++)
        #pragma unroll
        for (int tn = 0; tn < 4; tn++)
            #pragma unroll
            for (int q = 0; q < 4; q++) acc[tm][tn][q] = 0.f;

    for (int c = 0; c < 24; c++) {
        int k0 = c * 32;
        if (c) __syncthreads();
        *(uint4*)(sm + UV_AH + mrow * KPAD + kq8 * 2) = *(const uint4*)(pAH + k0);
        *(uint4*)(sm + UV_AL + mrow * KPAD + kq8 * 2) = *(const uint4*)(pAL + k0);
        #pragma unroll
        for (int it = 0; it < 4; it++) {
            int idx = t + it * 512;
            int n = idx & 255, kk = (idx >> 8) * 4;
            const float* pw = Wbase + (size_t)(k0 + kk) * HT + n;
            float w0v = __ldg(pw), w1v = __ldg(pw + HT),
                  w2v = __ldg(pw + 2 * HT), w3v = __ldg(pw + 3 * HT);
            float r0 = w0v - __bfloat162float(__float2bfloat16(w0v));
            float r1 = w1v - __bfloat162float(__float2bfloat16(w1v));
            float r2 = w2v - __bfloat162float(__float2bfloat16(w2v));
            float r3 = w3v - __bfloat162float(__float2bfloat16(w3v));
            int off = n * KPAD + kk * 2;
            *(uint2*)(sm + UV_BH + off) = make_uint2(pack2(w0v, w1v), pack2(w2v, w3v));
            *(uint2*)(sm + UV_BL + off) = make_uint2(pack2(r0, r1), pack2(r2, r3));
        }
        __syncthreads();
        #pragma unroll
        for (int ks = 0; ks < 2; ks++) {
            int kb = ks * 32 + quad * 4;
            uint32_t af[4][4], bf[4][2];
            #pragma unroll
            for (int tm = 0; tm < 4; tm++) {
                int base = UV_AH + (mw + tm * 16 + row4) * KPAD + kb;
                af[tm][0] = *(const uint32_t*)(sm + base);
                af[tm][1] = *(const uint32_t*)(sm + base + 8 * KPAD);
                af[tm][2] = *(const uint32_t*)(sm + base + 16);
                af[tm][3] = *(const uint32_t*)(sm + base + 8 * KPAD + 16);
            }
            #pragma unroll
            for (int tn = 0; tn < 4; tn++) {
                int base = UV_BH + (nw + tn * 8 + row4) * KPAD + kb;
                bf[tn][0] = *(const uint32_t*)(sm + base);
                bf[tn][1] = *(const uint32_t*)(sm + base + 16);
            }
            #pragma unroll
            for (int tm = 0; tm < 4; tm++)
                #pragma unroll
                for (int tn = 0; tn < 4; tn++)
                    mma16816(acc[tm][tn], af[tm], bf[tn]);
            #pragma unroll
            for (int tn = 0; tn < 4; tn++) {
                int base = UV_BL + (nw + tn * 8 + row4) * KPAD + kb;
                bf[tn][0] = *(const uint32_t*)(sm + base);
                bf[tn][1] = *(const uint32_t*)(sm + base + 16);
            }
            #pragma unroll
            for (int tm = 0; tm < 4; tm++)
                #pragma unroll
                for (int tn = 0; tn < 4; tn++)
                    mma16816(acc[tm][tn], af[tm], bf[tn]);
            #pragma unroll
            for (int tm = 0; tm < 4; tm++) {
                int base = UV_AL + (mw + tm * 16 + row4) * KPAD + kb;
                af[tm][0] = *(const uint32_t*)(sm + base);
                af[tm][1] = *(const uint32_t*)(sm + base + 8 * KPAD);
                af[tm][2] = *(const uint32_t*)(sm + base + 16);
                af[tm][3] = *(const uint32_t*)(sm + base + 8 * KPAD + 16);
            }
            #pragma unroll
            for (int tn = 0; tn < 4; tn++) {
                int base = UV_BH + (nw + tn * 8 + row4) * KPAD + kb;
                bf[tn][0] = *(const uint32_t*)(sm + base);
                bf[tn][1] = *(const uint32_t*)(sm + base + 16);
            }
            #pragma unroll
            for (int tm = 0; tm < 4; tm++)
                #pragma unroll
                for (int tn = 0; tn < 4; tn++)
                    mma16816(acc[tm][tn], af[tm], bf[tn]);
        }
    }

    float* Obase = (isU ? g_U : g_V);
    int c0 = isU ? ng0 : ng0 - HT;
    #pragma unroll
    for (int tm = 0; tm < 4; tm++) {
        int gr = m0 + mw + tm * 16 + row4;
        #pragma unroll
        for (int tn = 0; tn < 4; tn++) {
            int gc = c0 + nw + tn * 8 + quad * 2;
            float* p0 = Obase + (size_t)gr * HT + gc;
            float* p1 = Obase + (size_t)(gr + 8) * HT + gc;
            *(float2*)p0 = make_float2(acc[tm][tn][0], acc[tm][tn][1]);
            *(float2*)p1 = make_float2(acc[tm][tn][2], acc[tm][tn][3]);
        }
    }
}

// ---------------- kernel 4: BN stats partials -------------------------------
__global__ void k_stats(const float* __restrict__ adjs, const float* __restrict__ flags,
                        const float* __restrict__ W1t) {
    int bi = blockIdx.x;
    int b = bi >> 6, i = bi & 63;
    int t = threadIdx.x;
    __shared__ float Ur[HT];
    __shared__ float a0s[64], a1s[64];
    for (int k = t; k < HT; k += 256) Ur[k] = g_U[(size_t)bi * HT + k];
    if (t < 64) {
        int j = t;
        float m = flags[b * 64 + i] * flags[b * 64 + j];
        float a = adjs[(size_t)bi * 64 + j];
        a0s[j] = a * m;
        a1s[j] = (1.f - a) * m;
    }
    __syncthreads();
    float w0[6], w1[6], u[6], sum[6], sq[6];
    #pragma unroll
    for (int s = 0; s < 6; s++) {
        int k = t + s * 256;
        w0[s] = W1t[k];
        w1[s] = W1t[HT + k];
        u[s] = Ur[k];
        sum[s] = 0.f; sq[s] = 0.f;
    }
    const float* Vb = g_V + (size_t)(b * 64) * HT;
    for (int j = 0; j < 64; j++) {
        float a0 = a0s[j], a1 = a1s[j];
        const float* Vr = Vb + (size_t)j * HT;
        #pragma unroll
        for (int s = 0; s < 6; s++) {
            float z = u[s] + Vr[t + s * 256] + a0 * w0[s] + a1 * w1[s];
            sum[s] += z;
            sq[s] += z * z;
        }
    }
    #pragma unroll
    for (int s = 0; s < 6; s++) {
        g_part[(size_t)bi * 3072 + t + s * 256] = sum[s];
        g_part[(size_t)bi * 3072 + HT + t + s * 256] = sq[s];
    }
}

// ---------------- kernel 5: finalize BN constants ---------------------------
__global__ void k_stats2(const float* __restrict__ b1t, const float* __restrict__ gamma,
                         const float* __restrict__ beta) {
    int k = blockIdx.x * 256 + threadIdx.x;
    float s = 0.f, q = 0.f;
    for (int bi = 0; bi < NROW; bi++) {
        s += g_part[(size_t)bi * 3072 + k];
        q += g_part[(size_t)bi * 3072 + HT + k];
    }
    const float inv = 1.f / 65536.f;
    float mu_z = s * inv;
    float var = fmaxf(q * inv - mu_z * mu_z, 0.f);
    float mu = mu_z + b1t[k];
    float c1 = gamma[k] * rsqrtf(var + 1e-5f);
    g_c1[k] = c1;
    g_c2[k] = beta[k] - mu * c1;
}

// ---------------- kernel 5b: h2sum on triangle (balanced pairs) -------------
// block p handles i=p and i=63-p of batch b: exactly 65 j-iterations total.
__global__ void __launch_bounds__(384)
k_agen_tri(const float* __restrict__ adjs, const float* __restrict__ flags,
           const float* __restrict__ W1t) {
    int blk = blockIdx.x;
    int b = blk >> 5, p = blk & 31;
    int c4 = threadIdx.x * 4;
    float4 w0 = __ldg((const float4*)(W1t + c4));
    float4 w1 = __ldg((const float4*)(W1t + HT + c4));
    float4 c1 = *(const float4*)(g_c1 + c4);
    float4 c2 = *(const float4*)(g_c2 + c4);
    #pragma unroll
    for (int half = 0; half < 2; half++) {
        int i = half ? (63 - p) : p;
        int bi = b * 64 + i;
        float4 ui = *(const float4*)(g_U + (size_t)bi * HT + c4);
        float4 vi = *(const float4*)(g_V + (size_t)bi * HT + c4);
        float fi = __ldg(flags + b * 64 + i);
        size_t rank0 = (size_t)b * TRI_B + i * (129 - i) / 2;
        for (int j = i; j < 64; j++) {
            float fj = __ldg(flags + b * 64 + j);
            float mk = fi * fj;
            float aij = __ldg(adjs + (size_t)b * 4096 + i * 64 + j);
            float aji = __ldg(adjs + (size_t)b * 4096 + j * 64 + i);
            float a0ij = aij * mk, a1ij = (1.f - aij) * mk;
            float a0ji = aji * mk, a1ji = (1.f - aji) * mk;
            float4 uj = *(const float4*)(g_U + (size_t)(b * 64 + j) * HT + c4);
            float4 vj = *(const float4*)(g_V + (size_t)(b * 64 + j) * HT + c4);
            float s0 = elu_f((ui.x + vj.x + a0ij * w0.x + a1ij * w1.x) * c1.x + c2.x)
                     + elu_f((uj.x + vi.x + a0ji * w0.x + a1ji * w1.x) * c1.x + c2.x);
            float s1 = elu_f((ui.y + vj.y + a0ij * w0.y + a1ij * w1.y) * c1.y + c2.y)
                     + elu_f((uj.y + vi.y + a0ji * w0.y + a1ji * w1.y) * c1.y + c2.y);
            float s2 = elu_f((ui.z + vj.z + a0ij * w0.z + a1ij * w1.z) * c1.z + c2.z)
                     + elu_f((uj.z + vi.z + a0ji * w0.z + a1ji * w1.z) * c1.z + c2.z);
            float s3 = elu_f((ui.w + vj.w + a0ij * w0.w + a1ij * w1.w) * c1.w + c2.w)
                     + elu_f((uj.w + vi.w + a0ji * w0.w + a1ji * w1.w) * c1.w + c2.w);
            float r0 = s0 - __bfloat162float(__float2bfloat16(s0));
            float r1 = s1 - __bfloat162float(__float2bfloat16(s1));
            float r2 = s2 - __bfloat162float(__float2bfloat16(s2));
            float r3 = s3 - __bfloat162float(__float2bfloat16(s3));
            size_t row = (rank0 + (j - i)) * HT + c4;
            *(uint2*)(g_hh + row) = make_uint2(pack2(s0, s1), pack2(s2, s3));
            *(uint2*)(g_hl + row) = make_uint2(pack2(r0, r1), pack2(r2, r3));
        }
    }
}

// ---------------- kernel 6: triangle translate GEMM -> S (bf16 hi/lo) -------
#define GP_AH   0
#define GP_AL   10240
#define GP_BH   20480
#define GP_BL   40960
#define GP_MKS  61440
#define GP_SMEM 61952

__global__ void __launch_bounds__(512, 1)
k_gemm2_tri(const float* __restrict__ flags,
            const float* __restrict__ W2t, const float* __restrict__ b2t) {
    extern __shared__ char sm[];
    float* mks = (float*)(sm + GP_MKS);
    int t = threadIdx.x;
    int m0 = blockIdx.y * 128, n0g = blockIdx.x * 256;

    if (t < 128) {
        int e = __ldg(g_tri + m0 + t);
        int b = e >> 12, i = (e >> 6) & 63, j = e & 63;
        mks[t] = __ldg(flags + b * 64 + i) * __ldg(flags + b * 64 + j);
    }
    __syncthreads();

    int wid = t >> 5, lane = t & 31;
    int mw = (wid & 1) * 64, nw = (wid >> 1) * 32;
    int row4 = lane >> 2, quad = lane & 3;

    int mrow = t >> 2, kq8 = (t & 3) * 8;
    const __nv_bfloat16* pAH = g_hh + (size_t)(m0 + mrow) * HT + kq8;
    const __nv_bfloat16* pAL = g_hl + (size_t)(m0 + mrow) * HT + kq8;

    float acc[4][4][4];
    #pragma unroll
    for (int tm = 0; tm < 4; tm++)
        #pragma unroll
        for (int tn = 0; tn < 4; tn++)
            #pragma unroll
            for (int q = 0; q < 4; q++) acc[tm][tn][q] = 0.f;

    for (int c = 0; c < 48; c++) {
        int k0 = c * 32;
        if (c) __syncthreads();
        *(uint4*)(sm + GP_AH + mrow * KPAD + kq8 * 2) = *(const uint4*)(pAH + k0);
        *(uint4*)(sm + GP_AL + mrow * KPAD + kq8 * 2) = *(const uint4*)(pAL + k0);
        #pragma unroll
        for (int it = 0; it < 4; it++) {
            int idx = t + it * 512;
            int n = idx & 255, kk = (idx >> 8) * 4;
            const float* pw = W2t + (size_t)(k0 + kk) * 768 + n0g + n;
            float w0v = __ldg(pw), w1v = __ldg(pw + 768),
                  w2v = __ldg(pw + 1536), w3v = __ldg(pw + 2304);
            float r0 = w0v - __bfloat162float(__float2bfloat16(w0v));
            float r1 = w1v - __bfloat162float(__float2bfloat16(w1v));
            float r2 = w2v - __bfloat162float(__float2bfloat16(w2v));
            float r3 = w3v - __bfloat162float(__float2bfloat16(w3v));
            int off = n * KPAD + kk * 2;
            *(uint2*)(sm + GP_BH + off) = make_uint2(pack2(w0v, w1v), pack2(w2v, w3v));
            *(uint2*)(sm + GP_BL + off) = make_uint2(pack2(r0, r1), pack2(r2, r3));
        }
        __syncthreads();
        #pragma unroll
        for (int ks = 0; ks < 2; ks++) {
            int kb = ks * 32 + quad * 4;
            uint32_t af[4][4], bf[4][2];
            #pragma unroll
            for (int tm = 0; tm < 4; tm++) {
                int base = GP_AH + (mw + tm * 16 + row4) * KPAD + kb;
                af[tm][0] = *(const uint32_t*)(sm + base);
                af[tm][1] = *(const uint32_t*)(sm + base + 8 * KPAD);
                af[tm][2] = *(const uint32_t*)(sm + base + 16);
                af[tm][3] = *(const uint32_t*)(sm + base + 8 * KPAD + 16);
            }
            #pragma unroll
            for (int tn = 0; tn < 4; tn++) {
                int base = GP_BH + (nw + tn * 8 + row4) * KPAD + kb;
                bf[tn][0] = *(const uint32_t*)(sm + base);
                bf[tn][1] = *(const uint32_t*)(sm + base + 16);
            }
            #pragma unroll
            for (int tm = 0; tm < 4; tm++)
                #pragma unroll
                for (int tn = 0; tn < 4; tn++)
                    mma16816(acc[tm][tn], af[tm], bf[tn]);
            #pragma unroll
            for (int tn = 0; tn < 4; tn++) {
                int base = GP_BL + (nw + tn * 8 + row4) * KPAD + kb;
                bf[tn][0] = *(const uint32_t*)(sm + base);
                bf[tn][1] = *(const uint32_t*)(sm + base + 16);
            }
            #pragma unroll
            for (int tm = 0; tm < 4; tm++)
                #pragma unroll
                for (int tn = 0; tn < 4; tn++)
                    mma16816(acc[tm][tn], af[tm], bf[tn]);
            #pragma unroll
            for (int tm = 0; tm < 4; tm++) {
                int base = GP_AL + (mw + tm * 16 + row4) * KPAD + kb;
                af[tm][0] = *(const uint32_t*)(sm + base);
                af[tm][1] = *(const uint32_t*)(sm + base + 8 * KPAD);
                af[tm][2] = *(const uint32_t*)(sm + base + 16);
                af[tm][3] = *(const uint32_t*)(sm + base + 8 * KPAD + 16);
            }
            #pragma unroll
            for (int tn = 0; tn < 4; tn++) {
                int base = GP_BH + (nw + tn * 8 + row4) * KPAD + kb;
                bf[tn][0] = *(const uint32_t*)(sm + base);
                bf[tn][1] = *(const uint32_t*)(sm + base + 16);
            }
            #pragma unroll
            for (int tm = 0; tm < 4; tm++)
                #pragma unroll
                for (int tn = 0; tn < 4; tn++)
                    mma16816(acc[tm][tn], af[tm], bf[tn]);
        }
    }

    #pragma unroll
    for (int tm = 0; tm < 4; tm++) {
        int r0 = mw + tm * 16 + row4;
        float mk0 = mks[r0], mk1 = mks[r0 + 8];
        size_t gr0 = (size_t)(m0 + r0) * 768;
        size_t gr1 = (size_t)(m0 + r0 + 8) * 768;
        #pragma unroll
        for (int tn = 0; tn < 4; tn++) {
            int gc = n0g + nw + tn * 8 + quad * 2;
            float bx = 2.f * __ldg(b2t + gc), by = 2.f * __ldg(b2t + gc + 1);
            float s00 = (acc[tm][tn][0] + bx) * mk0, s01 = (acc[tm][tn][1] + by) * mk0;
            float s10 = (acc[tm][tn][2] + bx) * mk1, s11 = (acc[tm][tn][3] + by) * mk1;
            float r00 = s00 - __bfloat162float(__float2bfloat16(s00));
            float r01 = s01 - __bfloat162float(__float2bfloat16(s01));
            float r10 = s10 - __bfloat162float(__float2bfloat16(s10));
            float r11 = s11 - __bfloat162float(__float2bfloat16(s11));
            *(uint32_t*)(g_ssh + gr0 + gc) = pack2(s00, s01);
            *(uint32_t*)(g_ssl + gr0 + gc) = pack2(r00, r01);
            *(uint32_t*)(g_ssh + gr1 + gc) = pack2(s10, s11);
            *(uint32_t*)(g_ssl + gr1 + gc) = pack2(r10, r11);
        }
    }
}

// ---------------- kernel 7: triangle final_read_score -----------------------
#define ST_AH   0
#define ST_AL   10240
#define ST_BH   20480
#define ST_BL   40960
#define ST_A0IJ 61440
#define ST_A1IJ 61952
#define ST_A0JI 62464
#define ST_A1JI 62976
#define ST_ESM  63488
#define ST_RED  64000
#define ST_SMEM 72192

__global__ void __launch_bounds__(512, 1)
k_score_tri(const float* __restrict__ adjs, const float* __restrict__ flags,
            const float* __restrict__ W1r, const float* __restrict__ b1r,
            const float* __restrict__ W2r, const float* __restrict__ b2r,
            float* __restrict__ out_score) {
    extern __shared__ char sm[];
    float* a0ijs = (float*)(sm + ST_A0IJ);
    float* a1ijs = (float*)(sm + ST_A1IJ);
    float* a0jis = (float*)(sm + ST_A0JI);
    float* a1jis = (float*)(sm + ST_A1JI);
    int*   esm   = (int*)(sm + ST_ESM);
    float* red   = (float*)(sm + ST_RED);
    int t = threadIdx.x;
    int m0 = blockIdx.x * 128;

    if (t < 128) {
        int e = __ldg(g_tri + m0 + t);
        esm[t] = e;
        int b = e >> 12, i = (e >> 6) & 63, j = e & 63;
        float mk = __ldg(flags + b * 64 + i) * __ldg(flags + b * 64 + j);
        float aij = __ldg(adjs + e);
        float aji = __ldg(adjs + (b << 12) + (j << 6) + i);
        a0ijs[t] = aij * mk; a1ijs[t] = (1.f - aij) * mk;
        a0jis[t] = aji * mk; a1jis[t] = (1.f - aji) * mk;
    }
    __syncthreads();

    int wid = t >> 5, lane = t & 31;
    int mw = (wid & 1) * 64, nw = (wid >> 1) * 32;
    int row4 = lane >> 2, quad = lane & 3;

    int mrow = t >> 2, kq8 = (t & 3) * 8;
    const __nv_bfloat16* pSH = g_ssh + (size_t)(m0 + mrow) * 768 + kq8;
    const __nv_bfloat16* pSL = g_ssl + (size_t)(m0 + mrow) * 768 + kq8;

    float sij[4][2], sji[4][2];
    #pragma unroll
    for (int tm = 0; tm < 4; tm++) {
        sij[tm][0] = 0.f; sij[tm][1] = 0.f;
        sji[tm][0] = 0.f; sji[tm][1] = 0.f;
    }

    for (int nc = 0; nc < 7; nc++) {
        int n0 = nc * 256;
        float acc[4][4][4];
        #pragma unroll
        for (int tn = 0; tn < 4; tn++)
            #pragma unroll
            for (int cq = 0; cq < 2; cq++) {
                int n = n0 + nw + tn * 8 + quad * 2 + cq;
                float br = (n < HR) ? __ldg(b1r + n) : 0.f;
                #pragma unroll
                for (int tm = 0; tm < 4; tm++) {
                    acc[tm][tn][cq] = br;
                    acc[tm][tn][2 + cq] = br;
                }
            }
        for (int c = 0; c < 24; c++) {
            int k0 = c * 32;
            __syncthreads();
            *(uint4*)(sm + ST_AH + mrow * KPAD + kq8 * 2) = *(const uint4*)(pSH + k0);
            *(uint4*)(sm + ST_AL + mrow * KPAD + kq8 * 2) = *(const uint4*)(pSL + k0);
            #pragma unroll
            for (int it = 0; it < 4; it++) {
                int idx = t + it * 512;
                int n = idx & 255, kk = (idx >> 8) * 4;
                int ncol = n0 + n;
                bool ok = ncol < HR;
                const float* pw = W1r + (size_t)(2 + k0 + kk) * HR + ncol;
                float w0v = ok ? __ldg(pw) : 0.f;
                float w1v = ok ? __ldg(pw + HR) : 0.f;
                float w2v = ok ? __ldg(pw + 2 * HR) : 0.f;
                float w3v = ok ? __ldg(pw + 3 * HR) : 0.f;
                float r0 = w0v - __bfloat162float(__float2bfloat16(w0v));
                float r1 = w1v - __bfloat162float(__float2bfloat16(w1v));
                float r2 = w2v - __bfloat162float(__float2bfloat16(w2v));
                float r3 = w3v - __bfloat162float(__float2bfloat16(w3v));
                int off = n * KPAD + kk * 2;
                *(uint2*)(sm + ST_BH + off) = make_uint2(pack2(w0v, w1v), pack2(w2v, w3v));
                *(uint2*)(sm + ST_BL + off) = make_uint2(pack2(r0, r1), pack2(r2, r3));
            }
            __syncthreads();
            #pragma unroll
            for (int ks = 0; ks < 2; ks++) {
                int kb = ks * 32 + quad * 4;
                uint32_t af[4][4], bf[4][2];
                #pragma unroll
                for (int tm = 0; tm < 4; tm++) {
                    int base = ST_AH + (mw + tm * 16 + row4) * KPAD + kb;
                    af[tm][0] = *(const uint32_t*)(sm + base);
                    af[tm][1] = *(const uint32_t*)(sm + base + 8 * KPAD);
                    af[tm][2] = *(const uint32_t*)(sm + base + 16);
                    af[tm][3] = *(const uint32_t*)(sm + base + 8 * KPAD + 16);
                }
                #pragma unroll
                for (int tn = 0; tn < 4; tn++) {
                    int base = ST_BH + (nw + tn * 8 + row4) * KPAD + kb;
                    bf[tn][0] = *(const uint32_t*)(sm + base);
                    bf[tn][1] = *(const uint32_t*)(sm + base + 16);
                }
                #pragma unroll
                for (int tm = 0; tm < 4; tm++)
                    #pragma unroll
                    for (int tn = 0; tn < 4; tn++)
                        mma16816(acc[tm][tn], af[tm], bf[tn]);
                #pragma unroll
                for (int tn = 0; tn < 4; tn++) {
                    int base = ST_BL + (nw + tn * 8 + row4) * KPAD + kb;
                    bf[tn][0] = *(const uint32_t*)(sm + base);
                    bf[tn][1] = *(const uint32_t*)(sm + base + 16);
                }
                #pragma unroll
                for (int tm = 0; tm < 4; tm++)
                    #pragma unroll
                    for (int tn = 0; tn < 4; tn++)
                        mma16816(acc[tm][tn], af[tm], bf[tn]);
                #pragma unroll
                for (int tm = 0; tm < 4; tm++) {
                    int base = ST_AL + (mw + tm * 16 + row4) * KPAD + kb;
                    af[tm][0] = *(const uint32_t*)(sm + base);
                    af[tm][1] = *(const uint32_t*)(sm + base + 8 * KPAD);
                    af[tm][2] = *(const uint32_t*)(sm + base + 16);
                    af[tm][3] = *(const uint32_t*)(sm + base + 8 * KPAD + 16);
                }
                #pragma unroll
                for (int tn = 0; tn < 4; tn++) {
                    int base = ST_BH + (nw + tn * 8 + row4) * KPAD + kb;
                    bf[tn][0] = *(const uint32_t*)(sm + base);
                    bf[tn][1] = *(const uint32_t*)(sm + base + 16);
                }
                #pragma unroll
                for (int tm = 0; tm < 4; tm++)
                    #pragma unroll
                    for (int tn = 0; tn < 4; tn++)
                        mma16816(acc[tm][tn], af[tm], bf[tn]);
            }
        }
        #pragma unroll
        for (int tn = 0; tn < 4; tn++)
            #pragma unroll
            for (int cq = 0; cq < 2; cq++) {
                int n = n0 + nw + tn * 8 + quad * 2 + cq;
                bool ok = n < HR;
                float w0 = ok ? __ldg(W1r + n) : 0.f;
                float w1 = ok ? __ldg(W1r + HR + n) : 0.f;
                float w2 = ok ? __ldg(W2r + n) : 0.f;
                #pragma unroll
                for (int tm = 0; tm < 4; tm++) {
                    int r0 = mw + tm * 16 + row4;
                    float g0 = acc[tm][tn][cq], g1 = acc[tm][tn][2 + cq];
                    sij[tm][0] += elu_f(g0 + a0ijs[r0] * w0 + a1ijs[r0] * w1) * w2;
                    sji[tm][0] += elu_f(g0 + a0jis[r0] * w0 + a1jis[r0] * w1) * w2;
                    sij[tm][1] += elu_f(g1 + a0ijs[r0 + 8] * w0 + a1ijs[r0 + 8] * w1) * w2;
                    sji[tm][1] += elu_f(g1 + a0jis[r0 + 8] * w0 + a1jis[r0 + 8] * w1) * w2;
                }
            }
    }
    #pragma unroll
    for (int off = 1; off <= 2; off <<= 1)
        #pragma unroll
        for (int tm = 0; tm < 4; tm++) {
            sij[tm][0] += __shfl_xor_sync(0xffffffffu, sij[tm][0], off);
            sij[tm][1] += __shfl_xor_sync(0xffffffffu, sij[tm][1], off);
            sji[tm][0] += __shfl_xor_sync(0xffffffffu, sji[tm][0], off);
            sji[tm][1] += __shfl_xor_sync(0xffffffffu, sji[tm][1], off);
        }
    __syncthreads();
    if (quad == 0) {
        int wn = wid >> 1;
        #pragma unroll
        for (int tm = 0; tm < 4; tm++) {
            int r0 = mw + tm * 16 + row4;
            red[r0 * 8 + wn] = sij[tm][0];
            red[(r0 + 8) * 8 + wn] = sij[tm][1];
            red[1024 + r0 * 8 + wn] = sji[tm][0];
            red[1024 + (r0 + 8) * 8 + wn] = sji[tm][1];
        }
    }
    __syncthreads();
    if (t < 128) {
        float s1 = 0.f, s2 = 0.f;
        #pragma unroll
        for (int w8 = 0; w8 < 8; w8++) {
            s1 += red[t * 8 + w8];
            s2 += red[1024 + t * 8 + w8];
        }
        int e = esm[t];
        int b = e >> 12, i = (e >> 6) & 63, j = e & 63;
        float b2 = b2r[0];
        out_score[e] = (i == j) ? 0.f : (s1 + b2);
        if (i != j)
            out_score[(b << 12) + (j << 6) + i] = s2 + b2;
    }
}

// ---------------- launch -----------------------------------------------------
extern "C" void kernel_launch(void* const* d_in, const int* in_sizes, int n_in,
                              void* d_out, int out_size) {
    const float* x     = (const float*)d_in[0];
    const float* adjs  = (const float*)d_in[1];
    const float* flags = (const float*)d_in[2];
    const float* Wg    = (const float*)d_in[3];
    const float* bg    = (const float*)d_in[4];
    const float* Wout  = (const float*)d_in[5];
    const float* bout  = (const float*)d_in[6];
    const float* W1t   = (const float*)d_in[7];
    const float* b1t   = (const float*)d_in[8];
    const float* gamma = (const float*)d_in[9];
    const float* beta  = (const float*)d_in[10];
    const float* W2t   = (const float*)d_in[11];
    const float* b2t   = (const float*)d_in[12];
    const float* W1r   = (const float*)d_in[13];
    const float* b1r   = (const float*)d_in[14];
    const float* W2r   = (const float*)d_in[15];
    const float* b2r   = (const float*)d_in[16];

    float* out_score = (float*)d_out;             // [B,N,N] = 65536
    float* out_xo    = (float*)d_out + NEDGE;     // [B,N,768]

    cudaFuncSetAttribute(k_uv_mma, cudaFuncAttributeMaxDynamicSharedMemorySize, UV_SMEM);
    cudaFuncSetAttribute(k_gemm2_tri, cudaFuncAttributeMaxDynamicSharedMemorySize, GP_SMEM);
    cudaFuncSetAttribute(k_score_tri, cudaFuncAttributeMaxDynamicSharedMemorySize, ST_SMEM);

    k_trimap<<<64, 1024>>>();
    k_agg<<<NROW, 128>>>(x, adjs, flags);
    k_gin<<<NROW / 8, 256>>>(x, flags, Wg, bg, Wout, bout, out_xo);
    k_uv_mma<<<dim3(12, 8), 512, UV_SMEM>>>(W1t);
    k_stats<<<NROW, 256>>>(adjs, flags, W1t);
    k_stats2<<<6, 256>>>(b1t, gamma, beta);
    k_agen_tri<<<512, 384>>>(adjs, flags, W1t);
    k_gemm2_tri<<<dim3(3, 260), 512, GP_SMEM>>>(flags, W2t, b2t);
    k_score_tri<<<260, 512, ST_SMEM>>>(adjs, flags, W1r, b1r, W2r, b2r, out_score);
}

// round 12
// speedup vs baseline: 3.9819x; 1.0478x over previous
#include <cuda_runtime.h>
#include <cuda_bf16.h>
#include <stdint.h>
#include <cstdint>
#include <math.h>

// Problem constants
#define BB      16
#define NNODE   64
#define FIN     128
#define FHID    256
#define ODIM    768
#define HT      1536   // translate hidden
#define DR      770
#define HR      1540
#define NEDGE   65536  // B*N*N
#define NROW    1024   // B*N
#define TRI_B   2080   // 64*65/2 per batch
#define TRI_TOT 33280  // 16 * TRI_B (= 260 * 128)

// ---------------- scratch (device globals; no runtime allocation) ----------
__device__ float g_agg[NROW * 256];
__device__ float g_U[NROW * HT];
__device__ float g_V[NROW * HT];
__device__ float g_part[NROW * 2 * HT];
__device__ __align__(16) float g_c1[HT];
__device__ __align__(16) float g_c2[HT];
__device__ int   g_tri[TRI_TOT];                                     // tri rank -> edge
__device__ __align__(16) __nv_bfloat16 g_xh[NROW * ODIM];            // xo hi
__device__ __align__(16) __nv_bfloat16 g_xl[NROW * ODIM];            // xo lo
__device__ __align__(16) __nv_bfloat16 g_hh[(size_t)TRI_TOT * HT];   // h2sum hi
__device__ __align__(16) __nv_bfloat16 g_hl[(size_t)TRI_TOT * HT];   // h2sum lo
__device__ __align__(16) __nv_bfloat16 g_ssh[(size_t)TRI_TOT * ODIM]; // S hi
__device__ __align__(16) __nv_bfloat16 g_ssl[(size_t)TRI_TOT * ODIM]; // S lo

__device__ __forceinline__ float elu_f(float x) {
    return x > 0.f ? x : (__expf(x) - 1.f);
}
static __device__ __forceinline__ uint32_t pack2(float a, float b) {
    __nv_bfloat162 h = __floats2bfloat162_rn(a, b);
    return *reinterpret_cast<uint32_t*>(&h);
}
static __device__ __forceinline__ uint32_t smem_addr(const void* p) {
    uint32_t a;
    asm("{ .reg .u64 t; cvta.to.shared.u64 t, %1; cvt.u32.u64 %0, t; }" : "=r"(a) : "l"(p));
    return a;
}
static __device__ __forceinline__ void mma16816(float* c, const uint32_t* a,
                                                const uint32_t* b) {
    asm volatile(
        "mma.sync.aligned.m16n8k16.row.col.f32.bf16.bf16.f32 "
        "{%0,%1,%2,%3}, {%4,%5,%6,%7}, {%8,%9}, {%0,%1,%2,%3};"
        : "+f"(c[0]), "+f"(c[1]), "+f"(c[2]), "+f"(c[3])
        : "r"(a[0]), "r"(a[1]), "r"(a[2]), "r"(a[3]), "r"(b[0]), "r"(b[1]));
}
static __device__ __forceinline__ void ldsm4(uint32_t* r, uint32_t addr) {
    asm volatile("ldmatrix.sync.aligned.m8n8.x4.shared.b16 {%0,%1,%2,%3}, [%4];"
        : "=r"(r[0]), "=r"(r[1]), "=r"(r[2]), "=r"(r[3]) : "r"(addr));
}
static __device__ __forceinline__ void ldsm2(uint32_t* r, uint32_t addr) {
    asm volatile("ldmatrix.sync.aligned.m8n8.x2.shared.b16 {%0,%1}, [%2];"
        : "=r"(r[0]), "=r"(r[1]) : "r"(addr));
}

#define KPAD    80   // bytes per k-row (40 bf16)

// ldmatrix lane-address components (row stride KPAD, 16B k-halves)
#define LDSM_A_ROW(lane)  (((lane) & 7) + ((((lane) >> 3) & 1) << 3))
#define LDSM_A_KOFF(lane) ((((lane) >> 4) & 1) * 16)
#define LDSM_B_ROW(lane)  ((lane) & 7)
#define LDSM_B_KOFF(lane) ((((lane) >> 3) & 1) * 16)

// One k-step of the 3-product split GEMM (shared by all mma kernels).
// aBH/aBL/bBH/bBL: per-lane ldmatrix base addresses (chunk-invariant),
// ksb = ks*32 byte offset within the chunk.
#define SPLIT_MMA_KSTEP(aBH, aBL, bBH, bBL, ksb, acc)                          \
    do {                                                                       \
        uint32_t af[4][4], bh[4][2], bl[4][2];                                 \
        _Pragma("unroll")                                                      \
        for (int tm = 0; tm < 4; tm++) ldsm4(af[tm], (aBH) + tm * 16 * KPAD + (ksb)); \
        _Pragma("unroll")                                                      \
        for (int tn = 0; tn < 4; tn++) ldsm2(bh[tn], (bBH) + tn * 8 * KPAD + (ksb)); \
        _Pragma("unroll")                                                      \
        for (int tn = 0; tn < 4; tn++) ldsm2(bl[tn], (bBL) + tn * 8 * KPAD + (ksb)); \
        _Pragma("unroll")                                                      \
        for (int tm = 0; tm < 4; tm++)                                         \
            _Pragma("unroll")                                                  \
            for (int tn = 0; tn < 4; tn++)                                     \
                mma16816(acc[tm][tn], af[tm], bh[tn]);                         \
        _Pragma("unroll")                                                      \
        for (int tm = 0; tm < 4; tm++)                                         \
            _Pragma("unroll")                                                  \
            for (int tn = 0; tn < 4; tn++)                                     \
                mma16816(acc[tm][tn], af[tm], bl[tn]);                         \
        _Pragma("unroll")                                                      \
        for (int tm = 0; tm < 4; tm++) ldsm4(af[tm], (aBL) + tm * 16 * KPAD + (ksb)); \
        _Pragma("unroll")                                                      \
        for (int tm = 0; tm < 4; tm++)                                         \
            _Pragma("unroll")                                                  \
            for (int tn = 0; tn < 4; tn++)                                     \
                mma16816(acc[tm][tn], af[tm], bh[tn]);                         \
    } while (0)

// ---------------- kernel 0: triangle rank -> edge table ---------------------
__global__ void k_trimap() {
    int e = blockIdx.x * 1024 + threadIdx.x;
    int b = e >> 12, i = (e >> 6) & 63, j = e & 63;
    if (i <= j) {
        int rank = b * TRI_B + i * (129 - i) / 2 + (j - i);
        g_tri[rank] = e;
    }
}

// ---------------- kernel 1: agg --------------------------------------------
__global__ void k_agg(const float* __restrict__ x, const float* __restrict__ adjs,
                      const float* __restrict__ flags) {
    int bi = blockIdx.x;
    int b = bi >> 6, i = bi & 63;
    int f = threadIdx.x;
    __shared__ float a0s[64], a1s[64];
    float fi = flags[b * 64 + i];
    if (threadIdx.x < 64) {
        int j = threadIdx.x;
        float fj = flags[b * 64 + j];
        float a = adjs[(size_t)bi * 64 + j];
        float m = fi * fj;
        a0s[j] = a * m;
        a1s[j] = (1.f - a) * m;
    }
    __syncthreads();
    float s0 = 0.f, s1 = 0.f;
    const float* xb = x + (size_t)b * NNODE * FIN;
    #pragma unroll 4
    for (int j = 0; j < 64; j++) {
        float xv = xb[j * FIN + f];
        s0 += a0s[j] * xv;
        s1 += a1s[j] * xv;
    }
    g_agg[bi * 256 + f] = s0;
    g_agg[bi * 256 + 128 + f] = s1;
}

// ---------------- kernel 2: GIN MLPs -> x_o (+ bf16 hi/lo split) ------------
__global__ void k_gin(const float* __restrict__ x, const float* __restrict__ flags,
                      const float* __restrict__ Wg, const float* __restrict__ bg,
                      const float* __restrict__ Wout, const float* __restrict__ bout,
                      float* __restrict__ out_xo) {
    __shared__ float aggs[8][256];
    __shared__ float xs[8][128];
    __shared__ float hs[8][256];
    __shared__ float fl[8];
    int r0 = blockIdx.x * 8;
    int t = threadIdx.x;
    for (int idx = t; idx < 8 * 256; idx += 256)
        aggs[idx >> 8][idx & 255] = g_agg[r0 * 256 + idx];
    for (int idx = t; idx < 8 * 128; idx += 256)
        xs[idx >> 7][idx & 127] = x[(size_t)r0 * 128 + idx];
    if (t < 8) fl[t] = flags[r0 + t];
    __syncthreads();
    {
        float acc[8];
        float bgv = bg[t];
        #pragma unroll
        for (int r = 0; r < 8; r++) acc[r] = bgv;
        for (int k = 0; k < 256; k++) {
            float w = Wg[k * 256 + t];
            #pragma unroll
            for (int r = 0; r < 8; r++) acc[r] += aggs[r][k] * w;
        }
        #pragma unroll
        for (int r = 0; r < 8; r++) hs[r][t] = elu_f(acc[r]) * fl[r];
    }
    __syncthreads();
    float acc[3][8];
    #pragma unroll
    for (int c = 0; c < 3; c++) {
        float bo = bout[t + c * 256];
        #pragma unroll
        for (int r = 0; r < 8; r++) acc[c][r] = bo;
    }
    for (int k = 0; k < 128; k++) {
        float o[8];
        #pragma unroll
        for (int r = 0; r < 8; r++) o[r] = xs[r][k];
        #pragma unroll
        for (int c = 0; c < 3; c++) {
            float w = Wout[k * 768 + t + c * 256];
            #pragma unroll
            for (int r = 0; r < 8; r++) acc[c][r] += o[r] * w;
        }
    }
    for (int k = 0; k < 256; k++) {
        float o[8];
        #pragma unroll
        for (int r = 0; r < 8; r++) o[r] = hs[r][k];
        #pragma unroll
        for (int c = 0; c < 3; c++) {
            float w = Wout[(128 + k) * 768 + t + c * 256];
            #pragma unroll
            for (int r = 0; r < 8; r++) acc[c][r] += o[r] * w;
        }
    }
    #pragma unroll
    for (int c = 0; c < 3; c++)
        #pragma unroll
        for (int r = 0; r < 8; r++) {
            size_t idx = (size_t)(r0 + r) * 768 + t + c * 256;
            float val = tanhf(acc[c][r]) * fl[r];
            out_xo[idx] = val;
            __nv_bfloat16 h = __float2bfloat16(val);
            g_xh[idx] = h;
            g_xl[idx] = __float2bfloat16(val - __bfloat162float(h));
        }
}

// ---------------- kernel 3: U,V via mma (xo @ W1t slices) -------------------
#define UV_AH   0
#define UV_AL   10240
#define UV_BH   20480
#define UV_BL   40960
#define UV_SMEM 61440

__global__ void __launch_bounds__(512, 1)
k_uv_mma(const float* __restrict__ W1t) {
    extern __shared__ char sm[];
    uint32_t sb = smem_addr(sm);
    int t = threadIdx.x;
    int m0 = blockIdx.y * 128;
    int ng0 = blockIdx.x * 256;
    const int isU = (ng0 < HT);
    const float* Wbase = W1t + (size_t)(isU ? 2 : 770) * HT + (isU ? ng0 : ng0 - HT);

    int wid = t >> 5, lane = t & 31;
    int mw = (wid & 1) * 64, nw = (wid >> 1) * 32;
    int row4 = lane >> 2, quad = lane & 3;

    int mrow = t >> 2, kq8 = (t & 3) * 8;
    const __nv_bfloat16* pAH = g_xh + (size_t)(m0 + mrow) * 768 + kq8;
    const __nv_bfloat16* pAL = g_xl + (size_t)(m0 + mrow) * 768 + kq8;

    uint32_t aBH = sb + UV_AH + (mw + LDSM_A_ROW(lane)) * KPAD + LDSM_A_KOFF(lane);
    uint32_t aBL = sb + UV_AL + (mw + LDSM_A_ROW(lane)) * KPAD + LDSM_A_KOFF(lane);
    uint32_t bBH = sb + UV_BH + (nw + LDSM_B_ROW(lane)) * KPAD + LDSM_B_KOFF(lane);
    uint32_t bBL = sb + UV_BL + (nw + LDSM_B_ROW(lane)) * KPAD + LDSM_B_KOFF(lane);

    float acc[4][4][4];
    #pragma unroll
    for (int tm = 0; tm < 4; tm++)
        #pragma unroll
        for (int tn = 0; tn < 4; tn++)
            #pragma unroll
            for (int q = 0; q < 4; q++) acc[tm][tn][q] = 0.f;

    for (int c = 0; c < 24; c++) {
        int k0 = c * 32;
        if (c) __syncthreads();
        *(uint4*)(sm + UV_AH + mrow * KPAD + kq8 * 2) = *(const uint4*)(pAH + k0);
        *(uint4*)(sm + UV_AL + mrow * KPAD + kq8 * 2) = *(const uint4*)(pAL + k0);
        #pragma unroll
        for (int it = 0; it < 4; it++) {
            int idx = t + it * 512;
            int n = idx & 255, kk = (idx >> 8) * 4;
            const float* pw = Wbase + (size_t)(k0 + kk) * HT + n;
            float w0v = __ldg(pw), w1v = __ldg(pw + HT),
                  w2v = __ldg(pw + 2 * HT), w3v = __ldg(pw + 3 * HT);
            float r0 = w0v - __bfloat162float(__float2bfloat16(w0v));
            float r1 = w1v - __bfloat162float(__float2bfloat16(w1v));
            float r2 = w2v - __bfloat162float(__float2bfloat16(w2v));
            float r3 = w3v - __bfloat162float(__float2bfloat16(w3v));
            int off = n * KPAD + kk * 2;
            *(uint2*)(sm + UV_BH + off) = make_uint2(pack2(w0v, w1v), pack2(w2v, w3v));
            *(uint2*)(sm + UV_BL + off) = make_uint2(pack2(r0, r1), pack2(r2, r3));
        }
        __syncthreads();
        #pragma unroll
        for (int ks = 0; ks < 2; ks++)
            SPLIT_MMA_KSTEP(aBH, aBL, bBH, bBL, ks * 32, acc);
    }

    float* Obase = (isU ? g_U : g_V);
    int c0 = isU ? ng0 : ng0 - HT;
    #pragma unroll
    for (int tm = 0; tm < 4; tm++) {
        int gr = m0 + mw + tm * 16 + row4;
        #pragma unroll
        for (int tn = 0; tn < 4; tn++) {
            int gc = c0 + nw + tn * 8 + quad * 2;
            float* p0 = Obase + (size_t)gr * HT + gc;
            float* p1 = Obase + (size_t)(gr + 8) * HT + gc;
            *(float2*)p0 = make_float2(acc[tm][tn][0], acc[tm][tn][1]);
            *(float2*)p1 = make_float2(acc[tm][tn][2], acc[tm][tn][3]);
        }
    }
}

// ---------------- kernel 4: BN stats partials -------------------------------
__global__ void k_stats(const float* __restrict__ adjs, const float* __restrict__ flags,
                        const float* __restrict__ W1t) {
    int bi = blockIdx.x;
    int b = bi >> 6, i = bi & 63;
    int t = threadIdx.x;
    __shared__ float Ur[HT];
    __shared__ float a0s[64], a1s[64];
    for (int k = t; k < HT; k += 256) Ur[k] = g_U[(size_t)bi * HT + k];
    if (t < 64) {
        int j = t;
        float m = flags[b * 64 + i] * flags[b * 64 + j];
        float a = adjs[(size_t)bi * 64 + j];
        a0s[j] = a * m;
        a1s[j] = (1.f - a) * m;
    }
    __syncthreads();
    float w0[6], w1[6], u[6], sum[6], sq[6];
    #pragma unroll
    for (int s = 0; s < 6; s++) {
        int k = t + s * 256;
        w0[s] = W1t[k];
        w1[s] = W1t[HT + k];
        u[s] = Ur[k];
        sum[s] = 0.f; sq[s] = 0.f;
    }
    const float* Vb = g_V + (size_t)(b * 64) * HT;
    for (int j = 0; j < 64; j++) {
        float a0 = a0s[j], a1 = a1s[j];
        const float* Vr = Vb + (size_t)j * HT;
        #pragma unroll
        for (int s = 0; s < 6; s++) {
            float z = u[s] + Vr[t + s * 256] + a0 * w0[s] + a1 * w1[s];
            sum[s] += z;
            sq[s] += z * z;
        }
    }
    #pragma unroll
    for (int s = 0; s < 6; s++) {
        g_part[(size_t)bi * 3072 + t + s * 256] = sum[s];
        g_part[(size_t)bi * 3072 + HT + t + s * 256] = sq[s];
    }
}

// ---------------- kernel 5: finalize BN constants ---------------------------
__global__ void k_stats2(const float* __restrict__ b1t, const float* __restrict__ gamma,
                         const float* __restrict__ beta) {
    int k = blockIdx.x * 256 + threadIdx.x;
    float s = 0.f, q = 0.f;
    for (int bi = 0; bi < NROW; bi++) {
        s += g_part[(size_t)bi * 3072 + k];
        q += g_part[(size_t)bi * 3072 + HT + k];
    }
    const float inv = 1.f / 65536.f;
    float mu_z = s * inv;
    float var = fmaxf(q * inv - mu_z * mu_z, 0.f);
    float mu = mu_z + b1t[k];
    float c1 = gamma[k] * rsqrtf(var + 1e-5f);
    g_c1[k] = c1;
    g_c2[k] = beta[k] - mu * c1;
}

// ---------------- kernel 5b: h2sum on triangle (balanced pairs) -------------
__global__ void __launch_bounds__(384)
k_agen_tri(const float* __restrict__ adjs, const float* __restrict__ flags,
           const float* __restrict__ W1t) {
    int blk = blockIdx.x;
    int b = blk >> 5, p = blk & 31;
    int c4 = threadIdx.x * 4;
    float4 w0 = __ldg((const float4*)(W1t + c4));
    float4 w1 = __ldg((const float4*)(W1t + HT + c4));
    float4 c1 = *(const float4*)(g_c1 + c4);
    float4 c2 = *(const float4*)(g_c2 + c4);
    #pragma unroll
    for (int half = 0; half < 2; half++) {
        int i = half ? (63 - p) : p;
        int bi = b * 64 + i;
        float4 ui = *(const float4*)(g_U + (size_t)bi * HT + c4);
        float4 vi = *(const float4*)(g_V + (size_t)bi * HT + c4);
        float fi = __ldg(flags + b * 64 + i);
        size_t rank0 = (size_t)b * TRI_B + i * (129 - i) / 2;
        for (int j = i; j < 64; j++) {
            float fj = __ldg(flags + b * 64 + j);
            float mk = fi * fj;
            float aij = __ldg(adjs + (size_t)b * 4096 + i * 64 + j);
            float aji = __ldg(adjs + (size_t)b * 4096 + j * 64 + i);
            float a0ij = aij * mk, a1ij = (1.f - aij) * mk;
            float a0ji = aji * mk, a1ji = (1.f - aji) * mk;
            float4 uj = *(const float4*)(g_U + (size_t)(b * 64 + j) * HT + c4);
            float4 vj = *(const float4*)(g_V + (size_t)(b * 64 + j) * HT + c4);
            float s0 = elu_f((ui.x + vj.x + a0ij * w0.x + a1ij * w1.x) * c1.x + c2.x)
                     + elu_f((uj.x + vi.x + a0ji * w0.x + a1ji * w1.x) * c1.x + c2.x);
            float s1 = elu_f((ui.y + vj.y + a0ij * w0.y + a1ij * w1.y) * c1.y + c2.y)
                     + elu_f((uj.y + vi.y + a0ji * w0.y + a1ji * w1.y) * c1.y + c2.y);
            float s2 = elu_f((ui.z + vj.z + a0ij * w0.z + a1ij * w1.z) * c1.z + c2.z)
                     + elu_f((uj.z + vi.z + a0ji * w0.z + a1ji * w1.z) * c1.z + c2.z);
            float s3 = elu_f((ui.w + vj.w + a0ij * w0.w + a1ij * w1.w) * c1.w + c2.w)
                     + elu_f((uj.w + vi.w + a0ji * w0.w + a1ji * w1.w) * c1.w + c2.w);
            float r0 = s0 - __bfloat162float(__float2bfloat16(s0));
            float r1 = s1 - __bfloat162float(__float2bfloat16(s1));
            float r2 = s2 - __bfloat162float(__float2bfloat16(s2));
            float r3 = s3 - __bfloat162float(__float2bfloat16(s3));
            size_t row = (rank0 + (j - i)) * HT + c4;
            *(uint2*)(g_hh + row) = make_uint2(pack2(s0, s1), pack2(s2, s3));
            *(uint2*)(g_hl + row) = make_uint2(pack2(r0, r1), pack2(r2, r3));
        }
    }
}

// ---------------- kernel 6: triangle translate GEMM -> S (bf16 hi/lo) -------
#define GP_AH   0
#define GP_AL   10240
#define GP_BH   20480
#define GP_BL   40960
#define GP_MKS  61440
#define GP_SMEM 61952

__global__ void __launch_bounds__(512, 1)
k_gemm2_tri(const float* __restrict__ flags,
            const float* __restrict__ W2t, const float* __restrict__ b2t) {
    extern __shared__ char sm[];
    uint32_t sb = smem_addr(sm);
    float* mks = (float*)(sm + GP_MKS);
    int t = threadIdx.x;
    int m0 = blockIdx.y * 128, n0g = blockIdx.x * 256;

    if (t < 128) {
        int e = __ldg(g_tri + m0 + t);
        int b = e >> 12, i = (e >> 6) & 63, j = e & 63;
        mks[t] = __ldg(flags + b * 64 + i) * __ldg(flags + b * 64 + j);
    }
    __syncthreads();

    int wid = t >> 5, lane = t & 31;
    int mw = (wid & 1) * 64, nw = (wid >> 1) * 32;
    int row4 = lane >> 2, quad = lane & 3;

    int mrow = t >> 2, kq8 = (t & 3) * 8;
    const __nv_bfloat16* pAH = g_hh + (size_t)(m0 + mrow) * HT + kq8;
    const __nv_bfloat16* pAL = g_hl + (size_t)(m0 + mrow) * HT + kq8;

    uint32_t aBH = sb + GP_AH + (mw + LDSM_A_ROW(lane)) * KPAD + LDSM_A_KOFF(lane);
    uint32_t aBL = sb + GP_AL + (mw + LDSM_A_ROW(lane)) * KPAD + LDSM_A_KOFF(lane);
    uint32_t bBH = sb + GP_BH + (nw + LDSM_B_ROW(lane)) * KPAD + LDSM_B_KOFF(lane);
    uint32_t bBL = sb + GP_BL + (nw + LDSM_B_ROW(lane)) * KPAD + LDSM_B_KOFF(lane);

    float acc[4][4][4];
    #pragma unroll
    for (int tm = 0; tm < 4; tm++)
        #pragma unroll
        for (int tn = 0; tn < 4; tn++)
            #pragma unroll
            for (int q = 0; q < 4; q++) acc[tm][tn][q] = 0.f;

    for (int c = 0; c < 48; c++) {
        int k0 = c * 32;
        if (c) __syncthreads();
        *(uint4*)(sm + GP_AH + mrow * KPAD + kq8 * 2) = *(const uint4*)(pAH + k0);
        *(uint4*)(sm + GP_AL + mrow * KPAD + kq8 * 2) = *(const uint4*)(pAL + k0);
        #pragma unroll
        for (int it = 0; it < 4; it++) {
            int idx = t + it * 512;
            int n = idx & 255, kk = (idx >> 8) * 4;
            const float* pw = W2t + (size_t)(k0 + kk) * 768 + n0g + n;
            float w0v = __ldg(pw), w1v = __ldg(pw + 768),
                  w2v = __ldg(pw + 1536), w3v = __ldg(pw + 2304);
            float r0 = w0v - __bfloat162float(__float2bfloat16(w0v));
            float r1 = w1v - __bfloat162float(__float2bfloat16(w1v));
            float r2 = w2v - __bfloat162float(__float2bfloat16(w2v));
            float r3 = w3v - __bfloat162float(__float2bfloat16(w3v));
            int off = n * KPAD + kk * 2;
            *(uint2*)(sm + GP_BH + off) = make_uint2(pack2(w0v, w1v), pack2(w2v, w3v));
            *(uint2*)(sm + GP_BL + off) = make_uint2(pack2(r0, r1), pack2(r2, r3));
        }
        __syncthreads();
        #pragma unroll
        for (int ks = 0; ks < 2; ks++)
            SPLIT_MMA_KSTEP(aBH, aBL, bBH, bBL, ks * 32, acc);
    }

    #pragma unroll
    for (int tm = 0; tm < 4; tm++) {
        int r0 = mw + tm * 16 + row4;
        float mk0 = mks[r0], mk1 = mks[r0 + 8];
        size_t gr0 = (size_t)(m0 + r0) * 768;
        size_t gr1 = (size_t)(m0 + r0 + 8) * 768;
        #pragma unroll
        for (int tn = 0; tn < 4; tn++) {
            int gc = n0g + nw + tn * 8 + quad * 2;
            float bx = 2.f * __ldg(b2t + gc), by = 2.f * __ldg(b2t + gc + 1);
            float s00 = (acc[tm][tn][0] + bx) * mk0, s01 = (acc[tm][tn][1] + by) * mk0;
            float s10 = (acc[tm][tn][2] + bx) * mk1, s11 = (acc[tm][tn][3] + by) * mk1;
            float r00 = s00 - __bfloat162float(__float2bfloat16(s00));
            float r01 = s01 - __bfloat162float(__float2bfloat16(s01));
            float r10 = s10 - __bfloat162float(__float2bfloat16(s10));
            float r11 = s11 - __bfloat162float(__float2bfloat16(s11));
            *(uint32_t*)(g_ssh + gr0 + gc) = pack2(s00, s01);
            *(uint32_t*)(g_ssl + gr0 + gc) = pack2(r00, r01);
            *(uint32_t*)(g_ssh + gr1 + gc) = pack2(s10, s11);
            *(uint32_t*)(g_ssl + gr1 + gc) = pack2(r10, r11);
        }
    }
}

// ---------------- kernel 7: triangle final_read_score -----------------------
#define ST_AH   0
#define ST_AL   10240
#define ST_BH   20480
#define ST_BL   40960
#define ST_A0IJ 61440
#define ST_A1IJ 61952
#define ST_A0JI 62464
#define ST_A1JI 62976
#define ST_ESM  63488
#define ST_RED  64000
#define ST_SMEM 72192

__global__ void __launch_bounds__(512, 1)
k_score_tri(const float* __restrict__ adjs, const float* __restrict__ flags,
            const float* __restrict__ W1r, const float* __restrict__ b1r,
            const float* __restrict__ W2r, const float* __restrict__ b2r,
            float* __restrict__ out_score) {
    extern __shared__ char sm[];
    uint32_t sb = smem_addr(sm);
    float* a0ijs = (float*)(sm + ST_A0IJ);
    float* a1ijs = (float*)(sm + ST_A1IJ);
    float* a0jis = (float*)(sm + ST_A0JI);
    float* a1jis = (float*)(sm + ST_A1JI);
    int*   esm   = (int*)(sm + ST_ESM);
    float* red   = (float*)(sm + ST_RED);
    int t = threadIdx.x;
    int m0 = blockIdx.x * 128;

    if (t < 128) {
        int e = __ldg(g_tri + m0 + t);
        esm[t] = e;
        int b = e >> 12, i = (e >> 6) & 63, j = e & 63;
        float mk = __ldg(flags + b * 64 + i) * __ldg(flags + b * 64 + j);
        float aij = __ldg(adjs + e);
        float aji = __ldg(adjs + (b << 12) + (j << 6) + i);
        a0ijs[t] = aij * mk; a1ijs[t] = (1.f - aij) * mk;
        a0jis[t] = aji * mk; a1jis[t] = (1.f - aji) * mk;
    }
    __syncthreads();

    int wid = t >> 5, lane = t & 31;
    int mw = (wid & 1) * 64, nw = (wid >> 1) * 32;
    int row4 = lane >> 2, quad = lane & 3;

    int mrow = t >> 2, kq8 = (t & 3) * 8;
    const __nv_bfloat16* pSH = g_ssh + (size_t)(m0 + mrow) * 768 + kq8;
    const __nv_bfloat16* pSL = g_ssl + (size_t)(m0 + mrow) * 768 + kq8;

    uint32_t aBH = sb + ST_AH + (mw + LDSM_A_ROW(lane)) * KPAD + LDSM_A_KOFF(lane);
    uint32_t aBL = sb + ST_AL + (mw + LDSM_A_ROW(lane)) * KPAD + LDSM_A_KOFF(lane);
    uint32_t bBH = sb + ST_BH + (nw + LDSM_B_ROW(lane)) * KPAD + LDSM_B_KOFF(lane);
    uint32_t bBL = sb + ST_BL + (nw + LDSM_B_ROW(lane)) * KPAD + LDSM_B_KOFF(lane);

    float sij[4][2], sji[4][2];
    #pragma unroll
    for (int tm = 0; tm < 4; tm++) {
        sij[tm][0] = 0.f; sij[tm][1] = 0.f;
        sji[tm][0] = 0.f; sji[tm][1] = 0.f;
    }

    for (int nc = 0; nc < 7; nc++) {
        int n0 = nc * 256;
        float acc[4][4][4];
        #pragma unroll
        for (int tn = 0; tn < 4; tn++)
            #pragma unroll
            for (int cq = 0; cq < 2; cq++) {
                int n = n0 + nw + tn * 8 + quad * 2 + cq;
                float br = (n < HR) ? __ldg(b1r + n) : 0.f;
                #pragma unroll
                for (int tm = 0; tm < 4; tm++) {
                    acc[tm][tn][cq] = br;
                    acc[tm][tn][2 + cq] = br;
                }
            }
        for (int c = 0; c < 24; c++) {
            int k0 = c * 32;
            __syncthreads();
            *(uint4*)(sm + ST_AH + mrow * KPAD + kq8 * 2) = *(const uint4*)(pSH + k0);
            *(uint4*)(sm + ST_AL + mrow * KPAD + kq8 * 2) = *(const uint4*)(pSL + k0);
            #pragma unroll
            for (int it = 0; it < 4; it++) {
                int idx = t + it * 512;
                int n = idx & 255, kk = (idx >> 8) * 4;
                int ncol = n0 + n;
                bool ok = ncol < HR;
                const float* pw = W1r + (size_t)(2 + k0 + kk) * HR + ncol;
                float w0v = ok ? __ldg(pw) : 0.f;
                float w1v = ok ? __ldg(pw + HR) : 0.f;
                float w2v = ok ? __ldg(pw + 2 * HR) : 0.f;
                float w3v = ok ? __ldg(pw + 3 * HR) : 0.f;
                float r0 = w0v - __bfloat162float(__float2bfloat16(w0v));
                float r1 = w1v - __bfloat162float(__float2bfloat16(w1v));
                float r2 = w2v - __bfloat162float(__float2bfloat16(w2v));
                float r3 = w3v - __bfloat162float(__float2bfloat16(w3v));
                int off = n * KPAD + kk * 2;
                *(uint2*)(sm + ST_BH + off) = make_uint2(pack2(w0v, w1v), pack2(w2v, w3v));
                *(uint2*)(sm + ST_BL + off) = make_uint2(pack2(r0, r1), pack2(r2, r3));
            }
            __syncthreads();
            #pragma unroll
            for (int ks = 0; ks < 2; ks++)
                SPLIT_MMA_KSTEP(aBH, aBL, bBH, bBL, ks * 32, acc);
        }
        #pragma unroll
        for (int tn = 0; tn < 4; tn++)
            #pragma unroll
            for (int cq = 0; cq < 2; cq++) {
                int n = n0 + nw + tn * 8 + quad * 2 + cq;
                bool ok = n < HR;
                float w0 = ok ? __ldg(W1r + n) : 0.f;
                float w1 = ok ? __ldg(W1r + HR + n) : 0.f;
                float w2 = ok ? __ldg(W2r + n) : 0.f;
                #pragma unroll
                for (int tm = 0; tm < 4; tm++) {
                    int r0 = mw + tm * 16 + row4;
                    float g0 = acc[tm][tn][cq], g1 = acc[tm][tn][2 + cq];
                    sij[tm][0] += elu_f(g0 + a0ijs[r0] * w0 + a1ijs[r0] * w1) * w2;
                    sji[tm][0] += elu_f(g0 + a0jis[r0] * w0 + a1jis[r0] * w1) * w2;
                    sij[tm][1] += elu_f(g1 + a0ijs[r0 + 8] * w0 + a1ijs[r0 + 8] * w1) * w2;
                    sji[tm][1] += elu_f(g1 + a0jis[r0 + 8] * w0 + a1jis[r0 + 8] * w1) * w2;
                }
            }
    }
    #pragma unroll
    for (int off = 1; off <= 2; off <<= 1)
        #pragma unroll
        for (int tm = 0; tm < 4; tm++) {
            sij[tm][0] += __shfl_xor_sync(0xffffffffu, sij[tm][0], off);
            sij[tm][1] += __shfl_xor_sync(0xffffffffu, sij[tm][1], off);
            sji[tm][0] += __shfl_xor_sync(0xffffffffu, sji[tm][0], off);
            sji[tm][1] += __shfl_xor_sync(0xffffffffu, sji[tm][1], off);
        }
    __syncthreads();
    if (quad == 0) {
        int wn = wid >> 1;
        #pragma unroll
        for (int tm = 0; tm < 4; tm++) {
            int r0 = mw + tm * 16 + row4;
            red[r0 * 8 + wn] = sij[tm][0];
            red[(r0 + 8) * 8 + wn] = sij[tm][1];
            red[1024 + r0 * 8 + wn] = sji[tm][0];
            red[1024 + (r0 + 8) * 8 + wn] = sji[tm][1];
        }
    }
    __syncthreads();
    if (t < 128) {
        float s1 = 0.f, s2 = 0.f;
        #pragma unroll
        for (int w8 = 0; w8 < 8; w8++) {
            s1 += red[t * 8 + w8];
            s2 += red[1024 + t * 8 + w8];
        }
        int e = esm[t];
        int b = e >> 12, i = (e >> 6) & 63, j = e & 63;
        float b2 = b2r[0];
        out_score[e] = (i == j) ? 0.f : (s1 + b2);
        if (i != j)
            out_score[(b << 12) + (j << 6) + i] = s2 + b2;
    }
}

// ---------------- launch -----------------------------------------------------
extern "C" void kernel_launch(void* const* d_in, const int* in_sizes, int n_in,
                              void* d_out, int out_size) {
    const float* x     = (const float*)d_in[0];
    const float* adjs  = (const float*)d_in[1];
    const float* flags = (const float*)d_in[2];
    const float* Wg    = (const float*)d_in[3];
    const float* bg    = (const float*)d_in[4];
    const float* Wout  = (const float*)d_in[5];
    const float* bout  = (const float*)d_in[6];
    const float* W1t   = (const float*)d_in[7];
    const float* b1t   = (const float*)d_in[8];
    const float* gamma = (const float*)d_in[9];
    const float* beta  = (const float*)d_in[10];
    const float* W2t   = (const float*)d_in[11];
    const float* b2t   = (const float*)d_in[12];
    const float* W1r   = (const float*)d_in[13];
    const float* b1r   = (const float*)d_in[14];
    const float* W2r   = (const float*)d_in[15];
    const float* b2r   = (const float*)d_in[16];

    float* out_score = (float*)d_out;             // [B,N,N] = 65536
    float* out_xo    = (float*)d_out + NEDGE;     // [B,N,768]

    cudaFuncSetAttribute(k_uv_mma, cudaFuncAttributeMaxDynamicSharedMemorySize, UV_SMEM);
    cudaFuncSetAttribute(k_gemm2_tri, cudaFuncAttributeMaxDynamicSharedMemorySize, GP_SMEM);
    cudaFuncSetAttribute(k_score_tri, cudaFuncAttributeMaxDynamicSharedMemorySize, ST_SMEM);

    k_trimap<<<64, 1024>>>();
    k_agg<<<NROW, 128>>>(x, adjs, flags);
    k_gin<<<NROW / 8, 256>>>(x, flags, Wg, bg, Wout, bout, out_xo);
    k_uv_mma<<<dim3(12, 8), 512, UV_SMEM>>>(W1t);
    k_stats<<<NROW, 256>>>(adjs, flags, W1t);
    k_stats2<<<6, 256>>>(b1t, gamma, beta);
    k_agen_tri<<<512, 384>>>(adjs, flags, W1t);
    k_gemm2_tri<<<dim3(3, 260), 512, GP_SMEM>>>(flags, W2t, b2t);
    k_score_tri<<<260, 512, ST_SMEM>>>(adjs, flags, W1r, b1r, W2r, b2r, out_score);
}

// round 13
// speedup vs baseline: 4.5485x; 1.1423x over previous
#include <cuda_runtime.h>
#include <cuda_bf16.h>
#include <stdint.h>
#include <cstdint>
#include <math.h>

// Problem constants
#define BB      16
#define NNODE   64
#define FIN     128
#define FHID    256
#define ODIM    768
#define HT      1536   // translate hidden
#define DR      770
#define HR      1540
#define NEDGE   65536  // B*N*N
#define NROW    1024   // B*N
#define TRI_B   2080   // 64*65/2 per batch
#define TRI_TOT 33280  // 16 * TRI_B (= 260 * 128)
#define HRP     1792   // W1r n-padding (7*256)

// ---------------- scratch (device globals; no runtime allocation) ----------
__device__ float g_agg[NROW * 256];
__device__ float g_U[NROW * HT];
__device__ float g_V[NROW * HT];
__device__ float g_part[NROW * 2 * HT];
__device__ __align__(16) float g_c1[HT];
__device__ __align__(16) float g_c2[HT];
__device__ int   g_tri[TRI_TOT];
__device__ __align__(16) __nv_bfloat16 g_xh[NROW * ODIM];
__device__ __align__(16) __nv_bfloat16 g_xl[NROW * ODIM];
__device__ __align__(16) __nv_bfloat16 g_hh[(size_t)TRI_TOT * HT];
__device__ __align__(16) __nv_bfloat16 g_hl[(size_t)TRI_TOT * HT];
__device__ __align__(16) __nv_bfloat16 g_ssh[(size_t)TRI_TOT * ODIM];
__device__ __align__(16) __nv_bfloat16 g_ssl[(size_t)TRI_TOT * ODIM];
// pre-packed B weights, [n][k] bf16 hi/lo
__device__ __align__(16) __nv_bfloat16 g_wuvh[3072 * 768], g_wuvl[3072 * 768];
__device__ __align__(16) __nv_bfloat16 g_w2h[768 * 1536],  g_w2l[768 * 1536];
__device__ __align__(16) __nv_bfloat16 g_w1rh[HRP * 768],  g_w1rl[HRP * 768];

__device__ __forceinline__ float elu_f(float x) {
    return x > 0.f ? x : (__expf(x) - 1.f);
}
static __device__ __forceinline__ uint32_t pack2(float a, float b) {
    __nv_bfloat162 h = __floats2bfloat162_rn(a, b);
    return *reinterpret_cast<uint32_t*>(&h);
}
static __device__ __forceinline__ uint32_t smem_addr(const void* p) {
    uint32_t a;
    asm("{ .reg .u64 t; cvta.to.shared.u64 t, %1; cvt.u32.u64 %0, t; }" : "=r"(a) : "l"(p));
    return a;
}
static __device__ __forceinline__ void mma16816(float* c, const uint32_t* a,
                                                const uint32_t* b) {
    asm volatile(
        "mma.sync.aligned.m16n8k16.row.col.f32.bf16.bf16.f32 "
        "{%0,%1,%2,%3}, {%4,%5,%6,%7}, {%8,%9}, {%0,%1,%2,%3};"
        : "+f"(c[0]), "+f"(c[1]), "+f"(c[2]), "+f"(c[3])
        : "r"(a[0]), "r"(a[1]), "r"(a[2]), "r"(a[3]), "r"(b[0]), "r"(b[1]));
}
static __device__ __forceinline__ void ldsm4(uint32_t* r, uint32_t addr) {
    asm volatile("ldmatrix.sync.aligned.m8n8.x4.shared.b16 {%0,%1,%2,%3}, [%4];"
        : "=r"(r[0]), "=r"(r[1]), "=r"(r[2]), "=r"(r[3]) : "r"(addr));
}
static __device__ __forceinline__ void ldsm2(uint32_t* r, uint32_t addr) {
    asm volatile("ldmatrix.sync.aligned.m8n8.x2.shared.b16 {%0,%1}, [%2];"
        : "=r"(r[0]), "=r"(r[1]) : "r"(addr));
}
static __device__ __forceinline__ void cpa16(uint32_t d, const void* s) {
    asm volatile("cp.async.ca.shared.global [%0], [%1], 16;" :: "r"(d), "l"(s));
}

#define KPAD    80   // bytes per k-row (40 bf16)
#define BUF_SZ  61440
#define AH_OFF  0
#define AL_OFF  10240
#define BH_OFF  20480
#define BL_OFF  40960

// ldmatrix lane-address components
#define LDSM_A_ROW(lane)  (((lane) & 7) + ((((lane) >> 3) & 1) << 3))
#define LDSM_A_KOFF(lane) ((((lane) >> 4) & 1) * 16)
#define LDSM_B_ROW(lane)  ((lane) & 7)
#define LDSM_B_KOFF(lane) ((((lane) >> 3) & 1) * 16)

// stage one chunk (A: 128x32, B: 256x32, hi+lo) into buffer bufb, commit group
#define STAGE_CHUNK(bufb, pAH, pAL, k0, BHsrc, BLsrc, nbase, SRCK)              \
    do {                                                                        \
        cpa16((bufb) + AH_OFF + mrow * KPAD + kq8 * 2, (pAH) + (k0));           \
        cpa16((bufb) + AL_OFF + mrow * KPAD + kq8 * 2, (pAL) + (k0));           \
        _Pragma("unroll")                                                       \
        for (int it_ = 0; it_ < 2; it_++) {                                     \
            int idx_ = t + it_ * 512;                                           \
            int n_ = idx_ >> 2, seg_ = idx_ & 3;                                \
            size_t so_ = (size_t)((nbase) + n_) * (SRCK) + (k0) + seg_ * 8;     \
            cpa16((bufb) + BH_OFF + n_ * KPAD + seg_ * 16, (BHsrc) + so_);      \
            cpa16((bufb) + BL_OFF + n_ * KPAD + seg_ * 16, (BLsrc) + so_);      \
        }                                                                       \
        asm volatile("cp.async.commit_group;");                                 \
    } while (0)

// One k-step of the 3-product split GEMM
#define SPLIT_MMA_KSTEP(aBH, aBL, bBH, bBL, ksb, acc)                          \
    do {                                                                       \
        uint32_t af[4][4], bh[4][2], bl[4][2];                                 \
        _Pragma("unroll")                                                      \
        for (int tm = 0; tm < 4; tm++) ldsm4(af[tm], (aBH) + tm * 16 * KPAD + (ksb)); \
        _Pragma("unroll")                                                      \
        for (int tn = 0; tn < 4; tn++) ldsm2(bh[tn], (bBH) + tn * 8 * KPAD + (ksb)); \
        _Pragma("unroll")                                                      \
        for (int tn = 0; tn < 4; tn++) ldsm2(bl[tn], (bBL) + tn * 8 * KPAD + (ksb)); \
        _Pragma("unroll")                                                      \
        for (int tm = 0; tm < 4; tm++)                                         \
            _Pragma("unroll")                                                  \
            for (int tn = 0; tn < 4; tn++)                                     \
                mma16816(acc[tm][tn], af[tm], bh[tn]);                         \
        _Pragma("unroll")                                                      \
        for (int tm = 0; tm < 4; tm++)                                         \
            _Pragma("unroll")                                                  \
            for (int tn = 0; tn < 4; tn++)                                     \
                mma16816(acc[tm][tn], af[tm], bl[tn]);                         \
        _Pragma("unroll")                                                      \
        for (int tm = 0; tm < 4; tm++) ldsm4(af[tm], (aBL) + tm * 16 * KPAD + (ksb)); \
        _Pragma("unroll")                                                      \
        for (int tm = 0; tm < 4; tm++)                                         \
            _Pragma("unroll")                                                  \
            for (int tn = 0; tn < 4; tn++)                                     \
                mma16816(acc[tm][tn], af[tm], bh[tn]);                         \
    } while (0)

// ---------------- weight pack kernels ---------------------------------------
__global__ void k_pack_uv(const float* __restrict__ W1t) {
    int idx = blockIdx.x * 256 + threadIdx.x;   // 3072*768
    int n = idx / 768, k = idx - n * 768;
    int isV = (n >= 1536);
    int col = isV ? n - 1536 : n;
    float v = W1t[(size_t)((isV ? 770 : 2) + k) * HT + col];
    __nv_bfloat16 h = __float2bfloat16(v);
    g_wuvh[idx] = h;
    g_wuvl[idx] = __float2bfloat16(v - __bfloat162float(h));
}
__global__ void k_pack_w2(const float* __restrict__ W2t) {
    int idx = blockIdx.x * 256 + threadIdx.x;   // 768*1536
    int n = idx / 1536, k = idx - n * 1536;
    float v = W2t[(size_t)k * 768 + n];
    __nv_bfloat16 h = __float2bfloat16(v);
    g_w2h[idx] = h;
    g_w2l[idx] = __float2bfloat16(v - __bfloat162float(h));
}
__global__ void k_pack_w1r(const float* __restrict__ W1r) {
    int idx = blockIdx.x * 256 + threadIdx.x;   // HRP*768
    int n = idx / 768, k = idx - n * 768;
    float v = (n < HR) ? W1r[(size_t)(2 + k) * HR + n] : 0.f;
    __nv_bfloat16 h = __float2bfloat16(v);
    g_w1rh[idx] = h;
    g_w1rl[idx] = __float2bfloat16(v - __bfloat162float(h));
}

// ---------------- kernel 0: triangle rank -> edge table ---------------------
__global__ void k_trimap() {
    int e = blockIdx.x * 1024 + threadIdx.x;
    int b = e >> 12, i = (e >> 6) & 63, j = e & 63;
    if (i <= j) {
        int rank = b * TRI_B + i * (129 - i) / 2 + (j - i);
        g_tri[rank] = e;
    }
}

// ---------------- kernel 1: agg --------------------------------------------
__global__ void k_agg(const float* __restrict__ x, const float* __restrict__ adjs,
                      const float* __restrict__ flags) {
    int bi = blockIdx.x;
    int b = bi >> 6, i = bi & 63;
    int f = threadIdx.x;
    __shared__ float a0s[64], a1s[64];
    float fi = flags[b * 64 + i];
    if (threadIdx.x < 64) {
        int j = threadIdx.x;
        float fj = flags[b * 64 + j];
        float a = adjs[(size_t)bi * 64 + j];
        float m = fi * fj;
        a0s[j] = a * m;
        a1s[j] = (1.f - a) * m;
    }
    __syncthreads();
    float s0 = 0.f, s1 = 0.f;
    const float* xb = x + (size_t)b * NNODE * FIN;
    #pragma unroll 4
    for (int j = 0; j < 64; j++) {
        float xv = xb[j * FIN + f];
        s0 += a0s[j] * xv;
        s1 += a1s[j] * xv;
    }
    g_agg[bi * 256 + f] = s0;
    g_agg[bi * 256 + 128 + f] = s1;
}

// ---------------- kernel 2: GIN MLPs -> x_o (+ bf16 hi/lo split) ------------
__global__ void k_gin(const float* __restrict__ x, const float* __restrict__ flags,
                      const float* __restrict__ Wg, const float* __restrict__ bg,
                      const float* __restrict__ Wout, const float* __restrict__ bout,
                      float* __restrict__ out_xo) {
    __shared__ float aggs[8][256];
    __shared__ float xs[8][128];
    __shared__ float hs[8][256];
    __shared__ float fl[8];
    int r0 = blockIdx.x * 8;
    int t = threadIdx.x;
    for (int idx = t; idx < 8 * 256; idx += 256)
        aggs[idx >> 8][idx & 255] = g_agg[r0 * 256 + idx];
    for (int idx = t; idx < 8 * 128; idx += 256)
        xs[idx >> 7][idx & 127] = x[(size_t)r0 * 128 + idx];
    if (t < 8) fl[t] = flags[r0 + t];
    __syncthreads();
    {
        float acc[8];
        float bgv = bg[t];
        #pragma unroll
        for (int r = 0; r < 8; r++) acc[r] = bgv;
        for (int k = 0; k < 256; k++) {
            float w = Wg[k * 256 + t];
            #pragma unroll
            for (int r = 0; r < 8; r++) acc[r] += aggs[r][k] * w;
        }
        #pragma unroll
        for (int r = 0; r < 8; r++) hs[r][t] = elu_f(acc[r]) * fl[r];
    }
    __syncthreads();
    float acc[3][8];
    #pragma unroll
    for (int c = 0; c < 3; c++) {
        float bo = bout[t + c * 256];
        #pragma unroll
        for (int r = 0; r < 8; r++) acc[c][r] = bo;
    }
    for (int k = 0; k < 128; k++) {
        float o[8];
        #pragma unroll
        for (int r = 0; r < 8; r++) o[r] = xs[r][k];
        #pragma unroll
        for (int c = 0; c < 3; c++) {
            float w = Wout[k * 768 + t + c * 256];
            #pragma unroll
            for (int r = 0; r < 8; r++) acc[c][r] += o[r] * w;
        }
    }
    for (int k = 0; k < 256; k++) {
        float o[8];
        #pragma unroll
        for (int r = 0; r < 8; r++) o[r] = hs[r][k];
        #pragma unroll
        for (int c = 0; c < 3; c++) {
            float w = Wout[(128 + k) * 768 + t + c * 256];
            #pragma unroll
            for (int r = 0; r < 8; r++) acc[c][r] += o[r] * w;
        }
    }
    #pragma unroll
    for (int c = 0; c < 3; c++)
        #pragma unroll
        for (int r = 0; r < 8; r++) {
            size_t idx = (size_t)(r0 + r) * 768 + t + c * 256;
            float val = tanhf(acc[c][r]) * fl[r];
            out_xo[idx] = val;
            __nv_bfloat16 h = __float2bfloat16(val);
            g_xh[idx] = h;
            g_xl[idx] = __float2bfloat16(val - __bfloat162float(h));
        }
}

// ---------------- kernel 3: U,V via pipelined mma ----------------------------
#define UV_SMEM (2 * BUF_SZ)

__global__ void __launch_bounds__(512, 1)
k_uv_mma() {
    extern __shared__ char sm[];
    uint32_t sb = smem_addr(sm);
    int t = threadIdx.x;
    int m0 = blockIdx.y * 128;
    int ng0 = blockIdx.x * 256;
    const int isU = (ng0 < HT);

    int wid = t >> 5, lane = t & 31;
    int mw = (wid & 1) * 64, nw = (wid >> 1) * 32;
    int row4 = lane >> 2, quad = lane & 3;
    int mrow = t >> 2, kq8 = (t & 3) * 8;
    const __nv_bfloat16* pAH = g_xh + (size_t)(m0 + mrow) * 768 + kq8;
    const __nv_bfloat16* pAL = g_xl + (size_t)(m0 + mrow) * 768 + kq8;
    int laneA = (mw + LDSM_A_ROW(lane)) * KPAD + LDSM_A_KOFF(lane);
    int laneB = (nw + LDSM_B_ROW(lane)) * KPAD + LDSM_B_KOFF(lane);

    float acc[4][4][4];
    #pragma unroll
    for (int tm = 0; tm < 4; tm++)
        #pragma unroll
        for (int tn = 0; tn < 4; tn++)
            #pragma unroll
            for (int q = 0; q < 4; q++) acc[tm][tn][q] = 0.f;

    STAGE_CHUNK(sb, pAH, pAL, 0, g_wuvh, g_wuvl, ng0, 768);
    for (int c = 0; c < 24; c++) {
        uint32_t cur = sb + (c & 1) * BUF_SZ;
        uint32_t nxt = sb + ((c + 1) & 1) * BUF_SZ;
        __syncthreads();
        if (c + 1 < 24) {
            STAGE_CHUNK(nxt, pAH, pAL, (c + 1) * 32, g_wuvh, g_wuvl, ng0, 768);
            asm volatile("cp.async.wait_group 1;" ::: "memory");
        } else {
            asm volatile("cp.async.wait_group 0;" ::: "memory");
        }
        __syncthreads();
        #pragma unroll
        for (int ks = 0; ks < 2; ks++)
            SPLIT_MMA_KSTEP(cur + AH_OFF + laneA, cur + AL_OFF + laneA,
                            cur + BH_OFF + laneB, cur + BL_OFF + laneB, ks * 32, acc);
    }

    float* Obase = (isU ? g_U : g_V);
    int c0 = isU ? ng0 : ng0 - HT;
    #pragma unroll
    for (int tm = 0; tm < 4; tm++) {
        int gr = m0 + mw + tm * 16 + row4;
        #pragma unroll
        for (int tn = 0; tn < 4; tn++) {
            int gc = c0 + nw + tn * 8 + quad * 2;
            float* p0 = Obase + (size_t)gr * HT + gc;
            float* p1 = Obase + (size_t)(gr + 8) * HT + gc;
            *(float2*)p0 = make_float2(acc[tm][tn][0], acc[tm][tn][1]);
            *(float2*)p1 = make_float2(acc[tm][tn][2], acc[tm][tn][3]);
        }
    }
}

// ---------------- kernel 4: BN stats partials -------------------------------
__global__ void k_stats(const float* __restrict__ adjs, const float* __restrict__ flags,
                        const float* __restrict__ W1t) {
    int bi = blockIdx.x;
    int b = bi >> 6, i = bi & 63;
    int t = threadIdx.x;
    __shared__ float Ur[HT];
    __shared__ float a0s[64], a1s[64];
    for (int k = t; k < HT; k += 256) Ur[k] = g_U[(size_t)bi * HT + k];
    if (t < 64) {
        int j = t;
        float m = flags[b * 64 + i] * flags[b * 64 + j];
        float a = adjs[(size_t)bi * 64 + j];
        a0s[j] = a * m;
        a1s[j] = (1.f - a) * m;
    }
    __syncthreads();
    float w0[6], w1[6], u[6], sum[6], sq[6];
    #pragma unroll
    for (int s = 0; s < 6; s++) {
        int k = t + s * 256;
        w0[s] = W1t[k];
        w1[s] = W1t[HT + k];
        u[s] = Ur[k];
        sum[s] = 0.f; sq[s] = 0.f;
    }
    const float* Vb = g_V + (size_t)(b * 64) * HT;
    for (int j = 0; j < 64; j++) {
        float a0 = a0s[j], a1 = a1s[j];
        const float* Vr = Vb + (size_t)j * HT;
        #pragma unroll
        for (int s = 0; s < 6; s++) {
            float z = u[s] + Vr[t + s * 256] + a0 * w0[s] + a1 * w1[s];
            sum[s] += z;
            sq[s] += z * z;
        }
    }
    #pragma unroll
    for (int s = 0; s < 6; s++) {
        g_part[(size_t)bi * 3072 + t + s * 256] = sum[s];
        g_part[(size_t)bi * 3072 + HT + t + s * 256] = sq[s];
    }
}

// ---------------- kernel 5: finalize BN constants ---------------------------
__global__ void k_stats2(const float* __restrict__ b1t, const float* __restrict__ gamma,
                         const float* __restrict__ beta) {
    int k = blockIdx.x * 256 + threadIdx.x;
    float s = 0.f, q = 0.f;
    for (int bi = 0; bi < NROW; bi++) {
        s += g_part[(size_t)bi * 3072 + k];
        q += g_part[(size_t)bi * 3072 + HT + k];
    }
    const float inv = 1.f / 65536.f;
    float mu_z = s * inv;
    float var = fmaxf(q * inv - mu_z * mu_z, 0.f);
    float mu = mu_z + b1t[k];
    float c1 = gamma[k] * rsqrtf(var + 1e-5f);
    g_c1[k] = c1;
    g_c2[k] = beta[k] - mu * c1;
}

// ---------------- kernel 5b: h2sum on triangle (balanced pairs) -------------
__global__ void __launch_bounds__(384)
k_agen_tri(const float* __restrict__ adjs, const float* __restrict__ flags,
           const float* __restrict__ W1t) {
    int blk = blockIdx.x;
    int b = blk >> 5, p = blk & 31;
    int c4 = threadIdx.x * 4;
    float4 w0 = __ldg((const float4*)(W1t + c4));
    float4 w1 = __ldg((const float4*)(W1t + HT + c4));
    float4 c1 = *(const float4*)(g_c1 + c4);
    float4 c2 = *(const float4*)(g_c2 + c4);
    #pragma unroll
    for (int half = 0; half < 2; half++) {
        int i = half ? (63 - p) : p;
        int bi = b * 64 + i;
        float4 ui = *(const float4*)(g_U + (size_t)bi * HT + c4);
        float4 vi = *(const float4*)(g_V + (size_t)bi * HT + c4);
        float fi = __ldg(flags + b * 64 + i);
        size_t rank0 = (size_t)b * TRI_B + i * (129 - i) / 2;
        for (int j = i; j < 64; j++) {
            float fj = __ldg(flags + b * 64 + j);
            float mk = fi * fj;
            float aij = __ldg(adjs + (size_t)b * 4096 + i * 64 + j);
            float aji = __ldg(adjs + (size_t)b * 4096 + j * 64 + i);
            float a0ij = aij * mk, a1ij = (1.f - aij) * mk;
            float a0ji = aji * mk, a1ji = (1.f - aji) * mk;
            float4 uj = *(const float4*)(g_U + (size_t)(b * 64 + j) * HT + c4);
            float4 vj = *(const float4*)(g_V + (size_t)(b * 64 + j) * HT + c4);
            float s0 = elu_f((ui.x + vj.x + a0ij * w0.x + a1ij * w1.x) * c1.x + c2.x)
                     + elu_f((uj.x + vi.x + a0ji * w0.x + a1ji * w1.x) * c1.x + c2.x);
            float s1 = elu_f((ui.y + vj.y + a0ij * w0.y + a1ij * w1.y) * c1.y + c2.y)
                     + elu_f((uj.y + vi.y + a0ji * w0.y + a1ji * w1.y) * c1.y + c2.y);
            float s2 = elu_f((ui.z + vj.z + a0ij * w0.z + a1ij * w1.z) * c1.z + c2.z)
                     + elu_f((uj.z + vi.z + a0ji * w0.z + a1ji * w1.z) * c1.z + c2.z);
            float s3 = elu_f((ui.w + vj.w + a0ij * w0.w + a1ij * w1.w) * c1.w + c2.w)
                     + elu_f((uj.w + vi.w + a0ji * w0.w + a1ji * w1.w) * c1.w + c2.w);
            float r0 = s0 - __bfloat162float(__float2bfloat16(s0));
            float r1 = s1 - __bfloat162float(__float2bfloat16(s1));
            float r2 = s2 - __bfloat162float(__float2bfloat16(s2));
            float r3 = s3 - __bfloat162float(__float2bfloat16(s3));
            size_t row = (rank0 + (j - i)) * HT + c4;
            *(uint2*)(g_hh + row) = make_uint2(pack2(s0, s1), pack2(s2, s3));
            *(uint2*)(g_hl + row) = make_uint2(pack2(r0, r1), pack2(r2, r3));
        }
    }
}

// ---------------- kernel 6: triangle translate GEMM -> S ---------------------
#define GP_MKS  (2 * BUF_SZ)
#define GP_SMEM (2 * BUF_SZ + 512)

__global__ void __launch_bounds__(512, 1)
k_gemm2_tri(const float* __restrict__ flags, const float* __restrict__ b2t) {
    extern __shared__ char sm[];
    uint32_t sb = smem_addr(sm);
    float* mks = (float*)(sm + GP_MKS);
    int t = threadIdx.x;
    int m0 = blockIdx.y * 128, n0g = blockIdx.x * 256;

    if (t < 128) {
        int e = __ldg(g_tri + m0 + t);
        int b = e >> 12, i = (e >> 6) & 63, j = e & 63;
        mks[t] = __ldg(flags + b * 64 + i) * __ldg(flags + b * 64 + j);
    }

    int wid = t >> 5, lane = t & 31;
    int mw = (wid & 1) * 64, nw = (wid >> 1) * 32;
    int row4 = lane >> 2, quad = lane & 3;
    int mrow = t >> 2, kq8 = (t & 3) * 8;
    const __nv_bfloat16* pAH = g_hh + (size_t)(m0 + mrow) * HT + kq8;
    const __nv_bfloat16* pAL = g_hl + (size_t)(m0 + mrow) * HT + kq8;
    int laneA = (mw + LDSM_A_ROW(lane)) * KPAD + LDSM_A_KOFF(lane);
    int laneB = (nw + LDSM_B_ROW(lane)) * KPAD + LDSM_B_KOFF(lane);

    float acc[4][4][4];
    #pragma unroll
    for (int tm = 0; tm < 4; tm++)
        #pragma unroll
        for (int tn = 0; tn < 4; tn++)
            #pragma unroll
            for (int q = 0; q < 4; q++) acc[tm][tn][q] = 0.f;

    STAGE_CHUNK(sb, pAH, pAL, 0, g_w2h, g_w2l, n0g, 1536);
    for (int c = 0; c < 48; c++) {
        uint32_t cur = sb + (c & 1) * BUF_SZ;
        uint32_t nxt = sb + ((c + 1) & 1) * BUF_SZ;
        __syncthreads();
        if (c + 1 < 48) {
            STAGE_CHUNK(nxt, pAH, pAL, (c + 1) * 32, g_w2h, g_w2l, n0g, 1536);
            asm volatile("cp.async.wait_group 1;" ::: "memory");
        } else {
            asm volatile("cp.async.wait_group 0;" ::: "memory");
        }
        __syncthreads();
        #pragma unroll
        for (int ks = 0; ks < 2; ks++)
            SPLIT_MMA_KSTEP(cur + AH_OFF + laneA, cur + AL_OFF + laneA,
                            cur + BH_OFF + laneB, cur + BL_OFF + laneB, ks * 32, acc);
    }

    #pragma unroll
    for (int tm = 0; tm < 4; tm++) {
        int r0 = mw + tm * 16 + row4;
        float mk0 = mks[r0], mk1 = mks[r0 + 8];
        size_t gr0 = (size_t)(m0 + r0) * 768;
        size_t gr1 = (size_t)(m0 + r0 + 8) * 768;
        #pragma unroll
        for (int tn = 0; tn < 4; tn++) {
            int gc = n0g + nw + tn * 8 + quad * 2;
            float bx = 2.f * __ldg(b2t + gc), by = 2.f * __ldg(b2t + gc + 1);
            float s00 = (acc[tm][tn][0] + bx) * mk0, s01 = (acc[tm][tn][1] + by) * mk0;
            float s10 = (acc[tm][tn][2] + bx) * mk1, s11 = (acc[tm][tn][3] + by) * mk1;
            float r00 = s00 - __bfloat162float(__float2bfloat16(s00));
            float r01 = s01 - __bfloat162float(__float2bfloat16(s01));
            float r10 = s10 - __bfloat162float(__float2bfloat16(s10));
            float r11 = s11 - __bfloat162float(__float2bfloat16(s11));
            *(uint32_t*)(g_ssh + gr0 + gc) = pack2(s00, s01);
            *(uint32_t*)(g_ssl + gr0 + gc) = pack2(r00, r01);
            *(uint32_t*)(g_ssh + gr1 + gc) = pack2(s10, s11);
            *(uint32_t*)(g_ssl + gr1 + gc) = pack2(r10, r11);
        }
    }
}

// ---------------- kernel 7: triangle final_read_score -----------------------
#define ST_A0IJ (2 * BUF_SZ)
#define ST_A1IJ (2 * BUF_SZ + 512)
#define ST_A0JI (2 * BUF_SZ + 1024)
#define ST_A1JI (2 * BUF_SZ + 1536)
#define ST_ESM  (2 * BUF_SZ + 2048)
#define ST_RED  (2 * BUF_SZ + 2560)
#define ST_SMEM (2 * BUF_SZ + 2560 + 8192)

__global__ void __launch_bounds__(512, 1)
k_score_tri(const float* __restrict__ adjs, const float* __restrict__ flags,
            const float* __restrict__ W1r, const float* __restrict__ b1r,
            const float* __restrict__ W2r, const float* __restrict__ b2r,
            float* __restrict__ out_score) {
    extern __shared__ char sm[];
    uint32_t sb = smem_addr(sm);
    float* a0ijs = (float*)(sm + ST_A0IJ);
    float* a1ijs = (float*)(sm + ST_A1IJ);
    float* a0jis = (float*)(sm + ST_A0JI);
    float* a1jis = (float*)(sm + ST_A1JI);
    int*   esm   = (int*)(sm + ST_ESM);
    float* red   = (float*)(sm + ST_RED);
    int t = threadIdx.x;
    int m0 = blockIdx.x * 128;

    if (t < 128) {
        int e = __ldg(g_tri + m0 + t);
        esm[t] = e;
        int b = e >> 12, i = (e >> 6) & 63, j = e & 63;
        float mk = __ldg(flags + b * 64 + i) * __ldg(flags + b * 64 + j);
        float aij = __ldg(adjs + e);
        float aji = __ldg(adjs + (b << 12) + (j << 6) + i);
        a0ijs[t] = aij * mk; a1ijs[t] = (1.f - aij) * mk;
        a0jis[t] = aji * mk; a1jis[t] = (1.f - aji) * mk;
    }

    int wid = t >> 5, lane = t & 31;
    int mw = (wid & 1) * 64, nw = (wid >> 1) * 32;
    int row4 = lane >> 2, quad = lane & 3;
    int mrow = t >> 2, kq8 = (t & 3) * 8;
    const __nv_bfloat16* pSH = g_ssh + (size_t)(m0 + mrow) * 768 + kq8;
    const __nv_bfloat16* pSL = g_ssl + (size_t)(m0 + mrow) * 768 + kq8;
    int laneA = (mw + LDSM_A_ROW(lane)) * KPAD + LDSM_A_KOFF(lane);
    int laneB = (nw + LDSM_B_ROW(lane)) * KPAD + LDSM_B_KOFF(lane);

    float sij[4][2], sji[4][2];
    #pragma unroll
    for (int tm = 0; tm < 4; tm++) {
        sij[tm][0] = 0.f; sij[tm][1] = 0.f;
        sji[tm][0] = 0.f; sji[tm][1] = 0.f;
    }
    __syncthreads();

    STAGE_CHUNK(sb, pSH, pSL, 0, g_w1rh, g_w1rl, 0, 768);
    for (int nc = 0; nc < 7; nc++) {
        int n0 = nc * 256;
        float acc[4][4][4];
        #pragma unroll
        for (int tn = 0; tn < 4; tn++)
            #pragma unroll
            for (int cq = 0; cq < 2; cq++) {
                int n = n0 + nw + tn * 8 + quad * 2 + cq;
                float br = (n < HR) ? __ldg(b1r + n) : 0.f;
                #pragma unroll
                for (int tm = 0; tm < 4; tm++) {
                    acc[tm][tn][cq] = br;
                    acc[tm][tn][2 + cq] = br;
                }
            }
        for (int c = 0; c < 24; c++) {
            uint32_t cur = sb + (c & 1) * BUF_SZ;
            uint32_t nxt = sb + ((c + 1) & 1) * BUF_SZ;
            __syncthreads();
            if (c + 1 < 24) {
                STAGE_CHUNK(nxt, pSH, pSL, (c + 1) * 32, g_w1rh, g_w1rl, n0, 768);
                asm volatile("cp.async.wait_group 1;" ::: "memory");
            } else {
                asm volatile("cp.async.wait_group 0;" ::: "memory");
            }
            __syncthreads();
            #pragma unroll
            for (int ks = 0; ks < 2; ks++)
                SPLIT_MMA_KSTEP(cur + AH_OFF + laneA, cur + AL_OFF + laneA,
                                cur + BH_OFF + laneB, cur + BL_OFF + laneB, ks * 32, acc);
        }
        // prefetch next nc's chunk 0 (bufA free since chunk 22) before epilogue
        if (nc + 1 < 7)
            STAGE_CHUNK(sb, pSH, pSL, 0, g_w1rh, g_w1rl, (nc + 1) * 256, 768);
        // epilogue: elu both orientations, dot with W2r
        #pragma unroll
        for (int tn = 0; tn < 4; tn++)
            #pragma unroll
            for (int cq = 0; cq < 2; cq++) {
                int n = n0 + nw + tn * 8 + quad * 2 + cq;
                bool ok = n < HR;
                float w0 = ok ? __ldg(W1r + n) : 0.f;
                float w1 = ok ? __ldg(W1r + HR + n) : 0.f;
                float w2 = ok ? __ldg(W2r + n) : 0.f;
                #pragma unroll
                for (int tm = 0; tm < 4; tm++) {
                    int r0 = mw + tm * 16 + row4;
                    float g0 = acc[tm][tn][cq], g1 = acc[tm][tn][2 + cq];
                    sij[tm][0] += elu_f(g0 + a0ijs[r0] * w0 + a1ijs[r0] * w1) * w2;
                    sji[tm][0] += elu_f(g0 + a0jis[r0] * w0 + a1jis[r0] * w1) * w2;
                    sij[tm][1] += elu_f(g1 + a0ijs[r0 + 8] * w0 + a1ijs[r0 + 8] * w1) * w2;
                    sji[tm][1] += elu_f(g1 + a0jis[r0 + 8] * w0 + a1jis[r0 + 8] * w1) * w2;
                }
            }
    }
    #pragma unroll
    for (int off = 1; off <= 2; off <<= 1)
        #pragma unroll
        for (int tm = 0; tm < 4; tm++) {
            sij[tm][0] += __shfl_xor_sync(0xffffffffu, sij[tm][0], off);
            sij[tm][1] += __shfl_xor_sync(0xffffffffu, sij[tm][1], off);
            sji[tm][0] += __shfl_xor_sync(0xffffffffu, sji[tm][0], off);
            sji[tm][1] += __shfl_xor_sync(0xffffffffu, sji[tm][1], off);
        }
    __syncthreads();
    if (quad == 0) {
        int wn = wid >> 1;
        #pragma unroll
        for (int tm = 0; tm < 4; tm++) {
            int r0 = mw + tm * 16 + row4;
            red[r0 * 8 + wn] = sij[tm][0];
            red[(r0 + 8) * 8 + wn] = sij[tm][1];
            red[1024 + r0 * 8 + wn] = sji[tm][0];
            red[1024 + (r0 + 8) * 8 + wn] = sji[tm][1];
        }
    }
    __syncthreads();
    if (t < 128) {
        float s1 = 0.f, s2 = 0.f;
        #pragma unroll
        for (int w8 = 0; w8 < 8; w8++) {
            s1 += red[t * 8 + w8];
            s2 += red[1024 + t * 8 + w8];
        }
        int e = esm[t];
        int b = e >> 12, i = (e >> 6) & 63, j = e & 63;
        float b2 = b2r[0];
        out_score[e] = (i == j) ? 0.f : (s1 + b2);
        if (i != j)
            out_score[(b << 12) + (j << 6) + i] = s2 + b2;
    }
}

// ---------------- launch -----------------------------------------------------
extern "C" void kernel_launch(void* const* d_in, const int* in_sizes, int n_in,
                              void* d_out, int out_size) {
    const float* x     = (const float*)d_in[0];
    const float* adjs  = (const float*)d_in[1];
    const float* flags = (const float*)d_in[2];
    const float* Wg    = (const float*)d_in[3];
    const float* bg    = (const float*)d_in[4];
    const float* Wout  = (const float*)d_in[5];
    const float* bout  = (const float*)d_in[6];
    const float* W1t   = (const float*)d_in[7];
    const float* b1t   = (const float*)d_in[8];
    const float* gamma = (const float*)d_in[9];
    const float* beta  = (const float*)d_in[10];
    const float* W2t   = (const float*)d_in[11];
    const float* b2t   = (const float*)d_in[12];
    const float* W1r   = (const float*)d_in[13];
    const float* b1r   = (const float*)d_in[14];
    const float* W2r   = (const float*)d_in[15];
    const float* b2r   = (const float*)d_in[16];

    float* out_score = (float*)d_out;             // [B,N,N] = 65536
    float* out_xo    = (float*)d_out + NEDGE;     // [B,N,768]

    cudaFuncSetAttribute(k_uv_mma, cudaFuncAttributeMaxDynamicSharedMemorySize, UV_SMEM);
    cudaFuncSetAttribute(k_gemm2_tri, cudaFuncAttributeMaxDynamicSharedMemorySize, GP_SMEM);
    cudaFuncSetAttribute(k_score_tri, cudaFuncAttributeMaxDynamicSharedMemorySize, ST_SMEM);

    k_pack_uv<<<3072 * 768 / 256, 256>>>(W1t);
    k_pack_w2<<<768 * 1536 / 256, 256>>>(W2t);
    k_pack_w1r<<<HRP * 768 / 256, 256>>>(W1r);
    k_trimap<<<64, 1024>>>();
    k_agg<<<NROW, 128>>>(x, adjs, flags);
    k_gin<<<NROW / 8, 256>>>(x, flags, Wg, bg, Wout, bout, out_xo);
    k_uv_mma<<<dim3(12, 8), 512, UV_SMEM>>>();
    k_stats<<<NROW, 256>>>(adjs, flags, W1t);
    k_stats2<<<6, 256>>>(b1t, gamma, beta);
    k_agen_tri<<<512, 384>>>(adjs, flags, W1t);
    k_gemm2_tri<<<dim3(3, 260), 512, GP_SMEM>>>(flags, b2t);
    k_score_tri<<<260, 512, ST_SMEM>>>(adjs, flags, W1r, b1r, W2r, b2r, out_score);
}